// round 2
// baseline (speedup 1.0000x reference)
#include <cuda_runtime.h>
#include <cuda_bf16.h>

// Problem constants
#define DMODEL   768
#define DSTATE   16
#define DCONV    4
#define DINNER   1536
#define DTRANK   48
#define NBATCH   2
#define SEQLEN   2048
#define NTOK     (NBATCH * SEQLEN)        // 4096
#define XDBL_W   (DTRANK + 2 * DSTATE)    // 80

// -------- scratch (static device globals; no runtime allocation) ----------
__device__ float g_xz  [NTOK * 2 * DINNER];  // in_proj output (x | z)
__device__ float g_q   [NTOK * DINNER];      // query proj
__device__ float g_xc  [NTOK * DINNER];      // conv+silu(x)
__device__ float g_xdbl[NTOK * XDBL_W];      // x_proj output (dt_low | B | C)
__device__ float g_dt  [NTOK * DINNER];      // softplus(dt)
__device__ float g_y   [NTOK * DINNER];      // gated scan output

// -------------------------- helpers ---------------------------------------
__device__ __forceinline__ float silu_f(float x) {
    return x / (1.0f + __expf(-x));
}
__device__ __forceinline__ float softplus_f(float x) {
    return (x > 20.0f) ? x : log1pf(__expf(x));
}

// ---------------------- tiled fp32 GEMM: C = A * W^T ----------------------
// A: [M, K] row-major (lda), W: [N, K] row-major (ldw), C: [M, N] (ldc)
// EPI: 0 = none, 1 = +bias[n], 2 = +bias[n] then softplus
template<int BM, int BN, int BK, int TM, int TN, int EPI>
__global__ void __launch_bounds__((BM / TM) * (BN / TN))
gemm_tn(const float* __restrict__ A, const float* __restrict__ W,
        const float* __restrict__ bias, float* __restrict__ C,
        int M, int N, int K, int lda, int ldw, int ldc)
{
    constexpr int TX = BN / TN;
    constexpr int TY = BM / TM;
    constexpr int NT = TX * TY;

    __shared__ float As[BK][BM + 1];
    __shared__ float Ws[BK][BN + 1];

    const int tid = threadIdx.x;
    const int tx  = tid % TX;
    const int ty  = tid / TX;
    const int m0  = blockIdx.y * BM;
    const int n0  = blockIdx.x * BN;

    float acc[TM][TN];
#pragma unroll
    for (int i = 0; i < TM; i++)
#pragma unroll
        for (int j = 0; j < TN; j++) acc[i][j] = 0.0f;

    for (int k0 = 0; k0 < K; k0 += BK) {
        // load A tile (BM x BK) and W tile (BN x BK), K-major in smem
        for (int i = tid; i < BM * BK; i += NT) {
            int m = i / BK, k = i % BK;
            As[k][m] = A[(size_t)(m0 + m) * lda + (k0 + k)];
        }
        for (int i = tid; i < BN * BK; i += NT) {
            int n = i / BK, k = i % BK;
            Ws[k][n] = W[(size_t)(n0 + n) * ldw + (k0 + k)];
        }
        __syncthreads();

#pragma unroll
        for (int k = 0; k < BK; k++) {
            float a[TM], w[TN];
#pragma unroll
            for (int i = 0; i < TM; i++) a[i] = As[k][ty * TM + i];
#pragma unroll
            for (int j = 0; j < TN; j++) w[j] = Ws[k][tx * TN + j];
#pragma unroll
            for (int i = 0; i < TM; i++)
#pragma unroll
                for (int j = 0; j < TN; j++)
                    acc[i][j] = fmaf(a[i], w[j], acc[i][j]);
        }
        __syncthreads();
    }

#pragma unroll
    for (int i = 0; i < TM; i++) {
        int m = m0 + ty * TM + i;
#pragma unroll
        for (int j = 0; j < TN; j++) {
            int n = n0 + tx * TN + j;
            float v = acc[i][j];
            if (EPI >= 1) v += bias[n];
            if (EPI == 2) v = softplus_f(v);
            C[(size_t)m * ldc + n] = v;
        }
    }
}

// ------------------- causal depthwise conv (4 taps) + silu -----------------
__global__ void conv_silu_kernel(const float* __restrict__ xz,
                                 const float* __restrict__ conv_w,
                                 const float* __restrict__ conv_b,
                                 float* __restrict__ xc)
{
    int idx = blockIdx.x * blockDim.x + threadIdx.x;
    if (idx >= NTOK * DINNER) return;
    int d   = idx % DINNER;
    int row = idx / DINNER;
    int l   = row & (SEQLEN - 1);
    int b   = row >> 11;            // SEQLEN = 2048

    float w0 = conv_w[d * DCONV + 0];
    float w1 = conv_w[d * DCONV + 1];
    float w2 = conv_w[d * DCONV + 2];
    float w3 = conv_w[d * DCONV + 3];

    float acc = conv_b[d];
    // x[b, l+k-3, d], x stored as first DINNER cols of xz (row stride 2*DINNER)
    const size_t base = ((size_t)b * SEQLEN) * (2 * DINNER) + d;
    if (l >= 3) acc += w0 * xz[base + (size_t)(l - 3) * (2 * DINNER)];
    if (l >= 2) acc += w1 * xz[base + (size_t)(l - 2) * (2 * DINNER)];
    if (l >= 1) acc += w2 * xz[base + (size_t)(l - 1) * (2 * DINNER)];
    acc += w3 * xz[base + (size_t)l * (2 * DINNER)];

    xc[idx] = silu_f(acc);
}

// ------------------------- selective scan + gating -------------------------
// Thread layout: 16 lanes per channel (one per state). 8 channels per block.
__global__ void __launch_bounds__(128)
scan_kernel(const float* __restrict__ xdbl, const float* __restrict__ dt,
            const float* __restrict__ xc,   const float* __restrict__ xz,
            const float* __restrict__ q,    const float* __restrict__ A_log,
            const float* __restrict__ Dvec, float* __restrict__ yout)
{
    const int grp = threadIdx.x >> 4;          // 0..7
    const int n   = threadIdx.x & 15;          // state index
    const int ch  = blockIdx.x * 8 + grp;      // 0..3071
    const int b   = ch / DINNER;
    const int d   = ch % DINNER;

    const float An = -__expf(A_log[d * DSTATE + n]);
    const float Dd = Dvec[d];

    float h = 0.0f;
    const int row0 = b * SEQLEN;

    for (int l = 0; l < SEQLEN; l++) {
        const int row = row0 + l;
        const float dtv = dt[(size_t)row * DINNER + d];
        const float xv  = xc[(size_t)row * DINNER + d];
        const float Bv  = xdbl[(size_t)row * XDBL_W + DTRANK + n];
        const float Cv  = xdbl[(size_t)row * XDBL_W + DTRANK + DSTATE + n];

        const float dA = __expf(dtv * An);
        h = fmaf(dA, h, dtv * xv * Bv);

        float p = h * Cv;
        p += __shfl_xor_sync(0xffffffffu, p, 8);
        p += __shfl_xor_sync(0xffffffffu, p, 4);
        p += __shfl_xor_sync(0xffffffffu, p, 2);
        p += __shfl_xor_sync(0xffffffffu, p, 1);

        if (n == 0) {
            float y  = p + xv * Dd;
            float zv = xz[(size_t)row * (2 * DINNER) + DINNER + d];
            float qv = q[(size_t)row * DINNER + d];
            y = y * silu_f(zv) * silu_f(qv);
            yout[(size_t)row * DINNER + d] = y;
        }
    }
}

// --------------------------------- host ------------------------------------
extern "C" void kernel_launch(void* const* d_in, const int* in_sizes, int n_in,
                              void* d_out, int out_size)
{
    const float* hs         = (const float*)d_in[0];
    const float* query      = (const float*)d_in[1];
    const float* in_proj_w  = (const float*)d_in[2];
    const float* conv_w     = (const float*)d_in[3];
    const float* conv_b     = (const float*)d_in[4];
    const float* x_proj_w   = (const float*)d_in[5];
    const float* dt_proj_w  = (const float*)d_in[6];
    const float* dt_proj_b  = (const float*)d_in[7];
    const float* A_log      = (const float*)d_in[8];
    const float* Dvec       = (const float*)d_in[9];
    const float* query_w    = (const float*)d_in[10];
    const float* query_b    = (const float*)d_in[11];
    const float* out_proj_w = (const float*)d_in[12];
    float* out = (float*)d_out;

    float *p_xz, *p_q, *p_xc, *p_xdbl, *p_dt, *p_y;
    cudaGetSymbolAddress((void**)&p_xz,   g_xz);
    cudaGetSymbolAddress((void**)&p_q,    g_q);
    cudaGetSymbolAddress((void**)&p_xc,   g_xc);
    cudaGetSymbolAddress((void**)&p_xdbl, g_xdbl);
    cudaGetSymbolAddress((void**)&p_dt,   g_dt);
    cudaGetSymbolAddress((void**)&p_y,    g_y);

    // 1) xz = hs @ in_proj_w^T            (4096 x 3072, K=768)
    gemm_tn<128, 128, 16, 8, 8, 0><<<dim3(2 * DINNER / 128, NTOK / 128), 256>>>(
        hs, in_proj_w, nullptr, p_xz, NTOK, 2 * DINNER, DMODEL,
        DMODEL, DMODEL, 2 * DINNER);

    // 2) q = query @ query_w^T + query_b  (4096 x 1536, K=768)
    gemm_tn<128, 128, 16, 8, 8, 1><<<dim3(DINNER / 128, NTOK / 128), 256>>>(
        query, query_w, query_b, p_q, NTOK, DINNER, DMODEL,
        DMODEL, DMODEL, DINNER);

    // 3) causal depthwise conv + silu
    {
        int total = NTOK * DINNER;
        conv_silu_kernel<<<(total + 255) / 256, 256>>>(p_xz, conv_w, conv_b, p_xc);
    }

    // 4) x_dbl = xc @ x_proj_w^T          (4096 x 80, K=1536)
    gemm_tn<128, 80, 16, 8, 5, 0><<<dim3(1, NTOK / 128), 256>>>(
        p_xc, x_proj_w, nullptr, p_xdbl, NTOK, XDBL_W, DINNER,
        DINNER, DINNER, XDBL_W);

    // 5) dt = softplus(x_dbl[:, :48] @ dt_proj_w^T + dt_proj_b)  (K=48)
    gemm_tn<128, 128, 16, 8, 8, 2><<<dim3(DINNER / 128, NTOK / 128), 256>>>(
        p_xdbl, dt_proj_w, dt_proj_b, p_dt, NTOK, DINNER, DTRANK,
        XDBL_W, DTRANK, DINNER);

    // 6) selective scan + D skip + silu(z) + silu(q) gating
    scan_kernel<<<NBATCH * DINNER / 8, 128>>>(
        p_xdbl, p_dt, p_xc, p_xz, p_q, A_log, Dvec, p_y);

    // 7) out = y @ out_proj_w^T           (4096 x 768, K=1536)
    gemm_tn<128, 128, 16, 8, 8, 0><<<dim3(DMODEL / 128, NTOK / 128), 256>>>(
        p_y, out_proj_w, nullptr, out, NTOK, DMODEL, DINNER,
        DINNER, DINNER, DMODEL);
}

// round 3
// speedup vs baseline: 1.6953x; 1.6953x over previous
#include <cuda_runtime.h>
#include <cuda_bf16.h>
#include <cstdint>

// Problem constants
#define DMODEL   768
#define DSTATE   16
#define DCONV    4
#define DINNER   1536
#define DTRANK   48
#define NBATCH   2
#define SEQLEN   2048
#define NTOK     (NBATCH * SEQLEN)        // 4096
#define XDBL_W   (DTRANK + 2 * DSTATE)    // 80
#define KSPLIT   8

// -------- scratch (static device globals; no runtime allocation) ----------
__device__ float g_xz  [NTOK * 2 * DINNER];        // in_proj output (x | z)
__device__ float g_q   [NTOK * DINNER];            // query proj
__device__ float g_xc  [NTOK * DINNER];            // conv+silu(x)
__device__ float g_xdbl[NTOK * XDBL_W];            // x_proj output (dt_low | B | C)
__device__ float g_xdp [KSPLIT * NTOK * XDBL_W];   // x_proj split-K partials
__device__ float g_dt  [NTOK * DINNER];            // softplus(dt)
__device__ float g_y   [NTOK * DINNER];            // gated scan output

// -------------------------- helpers ---------------------------------------
__device__ __forceinline__ float silu_f(float x) {
    return x / (1.0f + __expf(-x));
}
__device__ __forceinline__ float softplus_f(float x) {
    return (x > 20.0f) ? x : log1pf(__expf(x));
}
__device__ __forceinline__ uint32_t f2tf32(float x) {
    uint32_t r;
    asm("cvt.rna.tf32.f32 %0, %1;" : "=r"(r) : "f"(x));
    return r;
}
__device__ __forceinline__ void cp16(void* s, const void* g) {
    uint32_t sa = (uint32_t)__cvta_generic_to_shared(s);
    asm volatile("cp.async.ca.shared.global [%0], [%1], 16;" :: "r"(sa), "l"(g));
}
__device__ __forceinline__ void cp_commit() {
    asm volatile("cp.async.commit_group;" ::: "memory");
}
__device__ __forceinline__ void mma_tf32(float* d, const uint32_t* a, const uint32_t* b) {
    asm volatile(
        "mma.sync.aligned.m16n8k8.row.col.f32.tf32.tf32.f32 "
        "{%0,%1,%2,%3}, {%4,%5,%6,%7}, {%8,%9}, {%0,%1,%2,%3};\n"
        : "+f"(d[0]), "+f"(d[1]), "+f"(d[2]), "+f"(d[3])
        : "r"(a[0]), "r"(a[1]), "r"(a[2]), "r"(a[3]), "r"(b[0]), "r"(b[1]));
}

// ================= tf32 tensor-core GEMM: C = A * W^T + (bias) =============
// A: [M, K] row-major (lda), W: [N, K] row-major (ldw), C: [M, N] (ldc)
// Block tile 128x128, BK=16, 8 warps (2 M x 4 N), warp tile 64x32.
// EPI: 0 = none, 1 = +bias[n], 2 = +bias[n] then softplus
#define TBM 128
#define TBN 128
#define TBK 16
#define TPAD 20   // smem row stride (floats); conflict-free for fragment loads

template<int EPI>
__global__ void __launch_bounds__(256, 2)
gemm_tf32(const float* __restrict__ A, const float* __restrict__ W,
          const float* __restrict__ bias, float* __restrict__ C,
          int M, int N, int K, int lda, int ldw, int ldc)
{
    __shared__ float As[2][TBM][TPAD];
    __shared__ float Ws[2][TBN][TPAD];

    const int tid  = threadIdx.x;
    const int m0   = blockIdx.y * TBM;
    const int n0   = blockIdx.x * TBN;
    const int warp = tid >> 5;
    const int lane = tid & 31;
    const int g    = lane >> 2;   // group id (0..7)
    const int t    = lane & 3;    // thread-in-group (0..3)
    const int wm   = (warp & 1) * 64;  // warp M offset within block
    const int wn   = (warp >> 1) * 32; // warp N offset within block

    // loader coordinates: 64 rows/pass x 4 float4 per 16-col row
    const int lr = tid >> 2;         // 0..63
    const int lc = (tid & 3) * 4;    // 0,4,8,12

    const int niter = K / TBK;

    const float* Abase = A + (size_t)(m0 + lr) * lda + lc;
    const float* Wbase = W + (size_t)(n0 + lr) * ldw + lc;

    float acc[4][4][4];
#pragma unroll
    for (int mt = 0; mt < 4; mt++)
#pragma unroll
        for (int nt = 0; nt < 4; nt++)
#pragma unroll
            for (int i = 0; i < 4; i++) acc[mt][nt][i] = 0.0f;

    // prologue: stage 0
    {
        cp16(&As[0][lr][lc],      Abase);
        cp16(&As[0][lr + 64][lc], Abase + (size_t)64 * lda);
        cp16(&Ws[0][lr][lc],      Wbase);
        cp16(&Ws[0][lr + 64][lc], Wbase + (size_t)64 * ldw);
        cp_commit();
    }

    for (int it = 0; it < niter; it++) {
        if (it + 1 < niter) {
            const int s = (it + 1) & 1;
            const int k0 = (it + 1) * TBK;
            cp16(&As[s][lr][lc],      Abase + k0);
            cp16(&As[s][lr + 64][lc], Abase + k0 + (size_t)64 * lda);
            cp16(&Ws[s][lr][lc],      Wbase + k0);
            cp16(&Ws[s][lr + 64][lc], Wbase + k0 + (size_t)64 * ldw);
            cp_commit();
            asm volatile("cp.async.wait_group 1;" ::: "memory");
        } else {
            asm volatile("cp.async.wait_group 0;" ::: "memory");
        }
        __syncthreads();

        const int s = it & 1;
#pragma unroll
        for (int kk = 0; kk < TBK; kk += 8) {
            uint32_t afr[4][4];
            uint32_t bfr[4][2];
#pragma unroll
            for (int mt = 0; mt < 4; mt++) {
                const int r = wm + mt * 16 + g;
                afr[mt][0] = f2tf32(As[s][r][kk + t]);
                afr[mt][1] = f2tf32(As[s][r + 8][kk + t]);
                afr[mt][2] = f2tf32(As[s][r][kk + t + 4]);
                afr[mt][3] = f2tf32(As[s][r + 8][kk + t + 4]);
            }
#pragma unroll
            for (int nt = 0; nt < 4; nt++) {
                const int cn = wn + nt * 8 + g;
                bfr[nt][0] = f2tf32(Ws[s][cn][kk + t]);
                bfr[nt][1] = f2tf32(Ws[s][cn][kk + t + 4]);
            }
#pragma unroll
            for (int mt = 0; mt < 4; mt++)
#pragma unroll
                for (int nt = 0; nt < 4; nt++)
                    mma_tf32(acc[mt][nt], afr[mt], bfr[nt]);
        }
        __syncthreads();
    }

    // epilogue: c0:(g,2t) c1:(g,2t+1) c2:(g+8,2t) c3:(g+8,2t+1)
#pragma unroll
    for (int mt = 0; mt < 4; mt++) {
#pragma unroll
        for (int nt = 0; nt < 4; nt++) {
            const int row = m0 + wm + mt * 16 + g;
            const int col = n0 + wn + nt * 8 + 2 * t;
            float v0 = acc[mt][nt][0];
            float v1 = acc[mt][nt][1];
            float v2 = acc[mt][nt][2];
            float v3 = acc[mt][nt][3];
            if (EPI >= 1) {
                const float b0 = bias[col];
                const float b1 = bias[col + 1];
                v0 += b0; v1 += b1; v2 += b0; v3 += b1;
            }
            if (EPI == 2) {
                v0 = softplus_f(v0); v1 = softplus_f(v1);
                v2 = softplus_f(v2); v3 = softplus_f(v3);
            }
            float2* p0 = (float2*)&C[(size_t)row * ldc + col];
            float2* p1 = (float2*)&C[(size_t)(row + 8) * ldc + col];
            *p0 = make_float2(v0, v1);
            *p1 = make_float2(v2, v3);
        }
    }
}

// ---------------- SIMT split-K GEMM for x_proj (N=80) ----------------------
// A: [M,K] lda, W: [N,K] ldw; writes partial C per K-slice (deterministic).
template<int BM, int BN, int BK, int TM, int TN>
__global__ void __launch_bounds__((BM / TM) * (BN / TN))
gemm_tn_splitk(const float* __restrict__ A, const float* __restrict__ W,
               float* __restrict__ Cpart,
               int M, int N, int K, int lda, int ldw, int ldc)
{
    constexpr int TX = BN / TN;
    constexpr int TY = BM / TM;
    constexpr int NT = TX * TY;

    __shared__ float As[BK][BM + 1];
    __shared__ float Ws[BK][BN + 1];

    const int tid = threadIdx.x;
    const int tx  = tid % TX;
    const int ty  = tid / TX;
    const int m0  = blockIdx.y * BM;
    const int n0  = blockIdx.x * BN;

    const int kper = K / KSPLIT;
    const int kbeg = blockIdx.z * kper;

    float acc[TM][TN];
#pragma unroll
    for (int i = 0; i < TM; i++)
#pragma unroll
        for (int j = 0; j < TN; j++) acc[i][j] = 0.0f;

    for (int k0 = kbeg; k0 < kbeg + kper; k0 += BK) {
        for (int i = tid; i < BM * BK; i += NT) {
            int m = i / BK, k = i % BK;
            As[k][m] = A[(size_t)(m0 + m) * lda + (k0 + k)];
        }
        for (int i = tid; i < BN * BK; i += NT) {
            int n = i / BK, k = i % BK;
            Ws[k][n] = W[(size_t)(n0 + n) * ldw + (k0 + k)];
        }
        __syncthreads();

#pragma unroll
        for (int k = 0; k < BK; k++) {
            float a[TM], w[TN];
#pragma unroll
            for (int i = 0; i < TM; i++) a[i] = As[k][ty * TM + i];
#pragma unroll
            for (int j = 0; j < TN; j++) w[j] = Ws[k][tx * TN + j];
#pragma unroll
            for (int i = 0; i < TM; i++)
#pragma unroll
                for (int j = 0; j < TN; j++)
                    acc[i][j] = fmaf(a[i], w[j], acc[i][j]);
        }
        __syncthreads();
    }

    float* Cz = Cpart + (size_t)blockIdx.z * M * N;
#pragma unroll
    for (int i = 0; i < TM; i++) {
        int m = m0 + ty * TM + i;
#pragma unroll
        for (int j = 0; j < TN; j++) {
            int n = n0 + tx * TN + j;
            Cz[(size_t)m * ldc + n] = acc[i][j];
        }
    }
}

__global__ void reduce_xdbl_kernel(const float* __restrict__ part,
                                   float* __restrict__ out)
{
    int i = blockIdx.x * 256 + threadIdx.x;
    if (i < NTOK * XDBL_W) {
        float s = 0.0f;
#pragma unroll
        for (int z = 0; z < KSPLIT; z++)
            s += part[(size_t)z * NTOK * XDBL_W + i];
        out[i] = s;
    }
}

// ------------------- causal depthwise conv (4 taps) + silu -----------------
__global__ void conv_silu_kernel(const float* __restrict__ xz,
                                 const float* __restrict__ conv_w,
                                 const float* __restrict__ conv_b,
                                 float* __restrict__ xc)
{
    int idx = blockIdx.x * blockDim.x + threadIdx.x;
    if (idx >= NTOK * DINNER) return;
    int d   = idx % DINNER;
    int row = idx / DINNER;
    int l   = row & (SEQLEN - 1);
    int b   = row >> 11;            // SEQLEN = 2048

    float w0 = conv_w[d * DCONV + 0];
    float w1 = conv_w[d * DCONV + 1];
    float w2 = conv_w[d * DCONV + 2];
    float w3 = conv_w[d * DCONV + 3];

    float acc = conv_b[d];
    const size_t base = ((size_t)b * SEQLEN) * (2 * DINNER) + d;
    if (l >= 3) acc += w0 * xz[base + (size_t)(l - 3) * (2 * DINNER)];
    if (l >= 2) acc += w1 * xz[base + (size_t)(l - 2) * (2 * DINNER)];
    if (l >= 1) acc += w2 * xz[base + (size_t)(l - 1) * (2 * DINNER)];
    acc += w3 * xz[base + (size_t)l * (2 * DINNER)];

    xc[idx] = silu_f(acc);
}

// ------------------------- selective scan + gating -------------------------
__global__ void __launch_bounds__(128)
scan_kernel(const float* __restrict__ xdbl, const float* __restrict__ dt,
            const float* __restrict__ xc,   const float* __restrict__ xz,
            const float* __restrict__ q,    const float* __restrict__ A_log,
            const float* __restrict__ Dvec, float* __restrict__ yout)
{
    const int grp = threadIdx.x >> 4;          // 0..7
    const int n   = threadIdx.x & 15;          // state index
    const int ch  = blockIdx.x * 8 + grp;      // 0..3071
    const int b   = ch / DINNER;
    const int d   = ch % DINNER;

    const float An = -__expf(A_log[d * DSTATE + n]);
    const float Dd = Dvec[d];

    float h = 0.0f;
    const int row0 = b * SEQLEN;

    for (int l = 0; l < SEQLEN; l++) {
        const int row = row0 + l;
        const float dtv = dt[(size_t)row * DINNER + d];
        const float xv  = xc[(size_t)row * DINNER + d];
        const float Bv  = xdbl[(size_t)row * XDBL_W + DTRANK + n];
        const float Cv  = xdbl[(size_t)row * XDBL_W + DTRANK + DSTATE + n];

        const float dA = __expf(dtv * An);
        h = fmaf(dA, h, dtv * xv * Bv);

        float p = h * Cv;
        p += __shfl_xor_sync(0xffffffffu, p, 8);
        p += __shfl_xor_sync(0xffffffffu, p, 4);
        p += __shfl_xor_sync(0xffffffffu, p, 2);
        p += __shfl_xor_sync(0xffffffffu, p, 1);

        if (n == 0) {
            float y  = p + xv * Dd;
            float zv = xz[(size_t)row * (2 * DINNER) + DINNER + d];
            float qv = q[(size_t)row * DINNER + d];
            y = y * silu_f(zv) * silu_f(qv);
            yout[(size_t)row * DINNER + d] = y;
        }
    }
}

// --------------------------------- host ------------------------------------
extern "C" void kernel_launch(void* const* d_in, const int* in_sizes, int n_in,
                              void* d_out, int out_size)
{
    const float* hs         = (const float*)d_in[0];
    const float* query      = (const float*)d_in[1];
    const float* in_proj_w  = (const float*)d_in[2];
    const float* conv_w     = (const float*)d_in[3];
    const float* conv_b     = (const float*)d_in[4];
    const float* x_proj_w   = (const float*)d_in[5];
    const float* dt_proj_w  = (const float*)d_in[6];
    const float* dt_proj_b  = (const float*)d_in[7];
    const float* A_log      = (const float*)d_in[8];
    const float* Dvec       = (const float*)d_in[9];
    const float* query_w    = (const float*)d_in[10];
    const float* query_b    = (const float*)d_in[11];
    const float* out_proj_w = (const float*)d_in[12];
    float* out = (float*)d_out;

    float *p_xz, *p_q, *p_xc, *p_xdbl, *p_xdp, *p_dt, *p_y;
    cudaGetSymbolAddress((void**)&p_xz,   g_xz);
    cudaGetSymbolAddress((void**)&p_q,    g_q);
    cudaGetSymbolAddress((void**)&p_xc,   g_xc);
    cudaGetSymbolAddress((void**)&p_xdbl, g_xdbl);
    cudaGetSymbolAddress((void**)&p_xdp,  g_xdp);
    cudaGetSymbolAddress((void**)&p_dt,   g_dt);
    cudaGetSymbolAddress((void**)&p_y,    g_y);

    // 1) xz = hs @ in_proj_w^T            (4096 x 3072, K=768)  [tf32 TC]
    gemm_tf32<0><<<dim3(2 * DINNER / TBN, NTOK / TBM), 256>>>(
        hs, in_proj_w, nullptr, p_xz, NTOK, 2 * DINNER, DMODEL,
        DMODEL, DMODEL, 2 * DINNER);

    // 2) q = query @ query_w^T + query_b  (4096 x 1536, K=768)  [tf32 TC]
    gemm_tf32<1><<<dim3(DINNER / TBN, NTOK / TBM), 256>>>(
        query, query_w, query_b, p_q, NTOK, DINNER, DMODEL,
        DMODEL, DMODEL, DINNER);

    // 3) causal depthwise conv + silu
    {
        int total = NTOK * DINNER;
        conv_silu_kernel<<<(total + 255) / 256, 256>>>(p_xz, conv_w, conv_b, p_xc);
    }

    // 4) x_dbl = xc @ x_proj_w^T          (4096 x 80, K=1536)  [split-K SIMT]
    gemm_tn_splitk<128, 80, 16, 8, 5><<<dim3(1, NTOK / 128, KSPLIT), 256>>>(
        p_xc, x_proj_w, p_xdp, NTOK, XDBL_W, DINNER,
        DINNER, DINNER, XDBL_W);
    reduce_xdbl_kernel<<<(NTOK * XDBL_W + 255) / 256, 256>>>(p_xdp, p_xdbl);

    // 5) dt = softplus(x_dbl[:, :48] @ dt_proj_w^T + dt_proj_b)  (K=48) [tf32 TC]
    gemm_tf32<2><<<dim3(DINNER / TBN, NTOK / TBM), 256>>>(
        p_xdbl, dt_proj_w, dt_proj_b, p_dt, NTOK, DINNER, DTRANK,
        XDBL_W, DTRANK, DINNER);

    // 6) selective scan + D skip + silu(z) + silu(q) gating
    scan_kernel<<<NBATCH * DINNER / 8, 128>>>(
        p_xdbl, p_dt, p_xc, p_xz, p_q, A_log, Dvec, p_y);

    // 7) out = y @ out_proj_w^T           (4096 x 768, K=1536)  [tf32 TC]
    gemm_tf32<0><<<dim3(DMODEL / TBN, NTOK / TBM), 256>>>(
        p_y, out_proj_w, nullptr, out, NTOK, DMODEL, DINNER,
        DINNER, DINNER, DMODEL);
}

// round 4
// speedup vs baseline: 4.3428x; 2.5617x over previous
#include <cuda_runtime.h>
#include <cuda_bf16.h>
#include <cstdint>

// Problem constants
#define DMODEL   768
#define DSTATE   16
#define DCONV    4
#define DINNER   1536
#define DTRANK   48
#define NBATCH   2
#define SEQLEN   2048
#define NTOK     (NBATCH * SEQLEN)        // 4096
#define XDBL_W   (DTRANK + 2 * DSTATE)    // 80
#define KSPLIT   8

// -------- scratch (static device globals; no runtime allocation) ----------
__device__ float g_xz   [NTOK * 2 * DINNER];        // in_proj output (x | z)
__device__ float g_q    [NTOK * DINNER];            // query proj
__device__ float g_xc   [NTOK * DINNER];            // conv+silu(x)
__device__ float g_xdbl [NTOK * XDBL_W];            // x_proj output (raw)
__device__ float g_xdblr[NTOK * XDBL_W];            // x_proj output (tf32-rounded)
__device__ float g_xdp  [KSPLIT * NTOK * XDBL_W];   // x_proj split-K partials
__device__ float g_dt   [NTOK * DINNER];            // softplus(dt)
__device__ float g_y    [NTOK * DINNER];            // gated scan output (tf32-rounded)
// pre-rounded tf32 copies of GEMM inputs
__device__ float g_hsr  [NTOK * DMODEL];
__device__ float g_qur  [NTOK * DMODEL];
__device__ float g_w1   [2 * DINNER * DMODEL];
__device__ float g_w2   [DINNER * DMODEL];
__device__ float g_w3   [DMODEL * DINNER];
__device__ float g_w4   [DINNER * DTRANK];

// -------------------------- helpers ---------------------------------------
__device__ __forceinline__ float silu_f(float x) {
    return x / (1.0f + __expf(-x));
}
__device__ __forceinline__ float softplus_f(float x) {
    return (x > 20.0f) ? x : log1pf(__expf(x));
}
__device__ __forceinline__ float tf32r(float x) {
    float r;
    asm("cvt.rna.tf32.f32 %0, %1;" : "=f"(r) : "f"(x));
    return r;
}
__device__ __forceinline__ void cp16(void* s, const void* g) {
    uint32_t sa = (uint32_t)__cvta_generic_to_shared(s);
    asm volatile("cp.async.ca.shared.global [%0], [%1], 16;" :: "r"(sa), "l"(g));
}
__device__ __forceinline__ void cp_commit() {
    asm volatile("cp.async.commit_group;" ::: "memory");
}
__device__ __forceinline__ void ldsm_x4(uint32_t* r, uint32_t addr) {
    asm volatile("ldmatrix.sync.aligned.m8n8.x4.shared.b16 {%0,%1,%2,%3}, [%4];"
                 : "=r"(r[0]), "=r"(r[1]), "=r"(r[2]), "=r"(r[3]) : "r"(addr));
}
__device__ __forceinline__ void mma_tf32(float* d, const uint32_t* a, const uint32_t* b) {
    asm volatile(
        "mma.sync.aligned.m16n8k8.row.col.f32.tf32.tf32.f32 "
        "{%0,%1,%2,%3}, {%4,%5,%6,%7}, {%8,%9}, {%0,%1,%2,%3};\n"
        : "+f"(d[0]), "+f"(d[1]), "+f"(d[2]), "+f"(d[3])
        : "r"(a[0]), "r"(a[1]), "r"(a[2]), "r"(a[3]), "r"(b[0]), "r"(b[1]));
}

// ---------------- elementwise tf32 rounding pass (float4) ------------------
__global__ void round_tf32_kernel(const float* __restrict__ in,
                                  float* __restrict__ out, int n4)
{
    int i = blockIdx.x * blockDim.x + threadIdx.x;
    if (i < n4) {
        float4 v = ((const float4*)in)[i];
        v.x = tf32r(v.x); v.y = tf32r(v.y);
        v.z = tf32r(v.z); v.w = tf32r(v.w);
        ((float4*)out)[i] = v;
    }
}

// ========== tf32 tensor-core GEMM (pre-rounded inputs, ldmatrix) ===========
// A: [M, K] row-major (lda), W: [N, K] row-major (ldw), C: [M, N] (ldc)
// Block tile 128x128, BK=16, 8 warps (2 M x 4 N), warp tile 64x32.
// EPI: 0 = none, 1 = +bias[n], 2 = +bias[n] then softplus
#define TBM 128
#define TBN 128
#define TBK 16
#define TPAD 20   // smem row stride (floats); conflict-free incl. ldmatrix

template<int EPI>
__global__ void __launch_bounds__(256, 2)
gemm_tf32f(const float* __restrict__ A, const float* __restrict__ W,
           const float* __restrict__ bias, float* __restrict__ C,
           int M, int N, int K, int lda, int ldw, int ldc)
{
    __shared__ float As[2][TBM][TPAD];
    __shared__ float Ws[2][TBN][TPAD];

    const int tid  = threadIdx.x;
    const int m0   = blockIdx.y * TBM;
    const int n0   = blockIdx.x * TBN;
    const int warp = tid >> 5;
    const int lane = tid & 31;
    const int g    = lane >> 2;        // 0..7
    const int t    = lane & 3;         // 0..3
    const int wm   = (warp & 1) * 64;  // warp M offset
    const int wn   = (warp >> 1) * 32; // warp N offset

    // ldmatrix per-lane address components
    const int u   = lane & 7;          // row within 8-row tile
    const int grp = lane >> 3;         // address group 0..3

    const uint32_t aBase = (uint32_t)__cvta_generic_to_shared(&As[0][0][0]);
    const uint32_t wBase = (uint32_t)__cvta_generic_to_shared(&Ws[0][0][0]);
    const uint32_t stg   = TBM * TPAD * 4;   // bytes per stage

    // A tile addresses: tile order {(rows0-7,k0-3),(rows8-15,k0-3),(rows0-7,k4-7),(rows8-15,k4-7)}
    uint32_t aA[4];
#pragma unroll
    for (int mt = 0; mt < 4; mt++) {
        int row = wm + mt * 16 + (grp & 1) * 8 + u;
        int col = (grp >> 1) * 4;
        aA[mt] = aBase + (uint32_t)(row * TPAD + col) * 4u;
    }
    // B tile addresses (pair p covers nt=2p,2p+1):
    // groups {(nt=2p,k0-3),(2p,k4-7),(2p+1,k0-3),(2p+1,k4-7)}
    uint32_t aB[2];
#pragma unroll
    for (int p = 0; p < 2; p++) {
        int row = wn + (2 * p + (grp >> 1)) * 8 + u;
        int col = (grp & 1) * 4;
        aB[p] = wBase + (uint32_t)(row * TPAD + col) * 4u;
    }

    // loader coordinates: 64 rows/pass x 4 float4 per 16-col row
    const int lr = tid >> 2;         // 0..63
    const int lc = (tid & 3) * 4;    // 0,4,8,12
    const int niter = K / TBK;

    const float* Abase = A + (size_t)(m0 + lr) * lda + lc;
    const float* Wbase = W + (size_t)(n0 + lr) * ldw + lc;

    float acc[4][4][4];
#pragma unroll
    for (int mt = 0; mt < 4; mt++)
#pragma unroll
        for (int nt = 0; nt < 4; nt++)
#pragma unroll
            for (int i = 0; i < 4; i++) acc[mt][nt][i] = 0.0f;

    // prologue: stage 0
    cp16(&As[0][lr][lc],      Abase);
    cp16(&As[0][lr + 64][lc], Abase + (size_t)64 * lda);
    cp16(&Ws[0][lr][lc],      Wbase);
    cp16(&Ws[0][lr + 64][lc], Wbase + (size_t)64 * ldw);
    cp_commit();

    for (int it = 0; it < niter; it++) {
        if (it + 1 < niter) {
            const int s = (it + 1) & 1;
            const int k0 = (it + 1) * TBK;
            cp16(&As[s][lr][lc],      Abase + k0);
            cp16(&As[s][lr + 64][lc], Abase + k0 + (size_t)64 * lda);
            cp16(&Ws[s][lr][lc],      Wbase + k0);
            cp16(&Ws[s][lr + 64][lc], Wbase + k0 + (size_t)64 * ldw);
            cp_commit();
            asm volatile("cp.async.wait_group 1;" ::: "memory");
        } else {
            asm volatile("cp.async.wait_group 0;" ::: "memory");
        }
        __syncthreads();

        const uint32_t sOff = (uint32_t)(it & 1) * stg;
#pragma unroll
        for (int kk = 0; kk < TBK; kk += 8) {
            const uint32_t kOff = sOff + (uint32_t)kk * 4u;
            uint32_t afr[4][4];
            uint32_t bfr[4][2];
#pragma unroll
            for (int mt = 0; mt < 4; mt++)
                ldsm_x4(afr[mt], aA[mt] + kOff);
            {
                uint32_t r[4];
                ldsm_x4(r, aB[0] + kOff);
                bfr[0][0] = r[0]; bfr[0][1] = r[1];
                bfr[1][0] = r[2]; bfr[1][1] = r[3];
                ldsm_x4(r, aB[1] + kOff);
                bfr[2][0] = r[0]; bfr[2][1] = r[1];
                bfr[3][0] = r[2]; bfr[3][1] = r[3];
            }
#pragma unroll
            for (int mt = 0; mt < 4; mt++)
#pragma unroll
                for (int nt = 0; nt < 4; nt++)
                    mma_tf32(acc[mt][nt], afr[mt], bfr[nt]);
        }
        __syncthreads();
    }

    // epilogue: c0:(g,2t) c1:(g,2t+1) c2:(g+8,2t) c3:(g+8,2t+1)
#pragma unroll
    for (int mt = 0; mt < 4; mt++) {
#pragma unroll
        for (int nt = 0; nt < 4; nt++) {
            const int row = m0 + wm + mt * 16 + g;
            const int col = n0 + wn + nt * 8 + 2 * t;
            float v0 = acc[mt][nt][0];
            float v1 = acc[mt][nt][1];
            float v2 = acc[mt][nt][2];
            float v3 = acc[mt][nt][3];
            if (EPI >= 1) {
                const float b0 = bias[col];
                const float b1 = bias[col + 1];
                v0 += b0; v1 += b1; v2 += b0; v3 += b1;
            }
            if (EPI == 2) {
                v0 = softplus_f(v0); v1 = softplus_f(v1);
                v2 = softplus_f(v2); v3 = softplus_f(v3);
            }
            float2* p0 = (float2*)&C[(size_t)row * ldc + col];
            float2* p1 = (float2*)&C[(size_t)(row + 8) * ldc + col];
            *p0 = make_float2(v0, v1);
            *p1 = make_float2(v2, v3);
        }
    }
}

// ---------------- SIMT split-K GEMM for x_proj (N=80) ----------------------
template<int BM, int BN, int BK, int TM, int TN>
__global__ void __launch_bounds__((BM / TM) * (BN / TN))
gemm_tn_splitk(const float* __restrict__ A, const float* __restrict__ W,
               float* __restrict__ Cpart,
               int M, int N, int K, int lda, int ldw, int ldc)
{
    constexpr int TX = BN / TN;
    constexpr int TY = BM / TM;
    constexpr int NT = TX * TY;

    __shared__ float As[BK][BM + 1];
    __shared__ float Ws[BK][BN + 1];

    const int tid = threadIdx.x;
    const int tx  = tid % TX;
    const int ty  = tid / TX;
    const int m0  = blockIdx.y * BM;
    const int n0  = blockIdx.x * BN;

    const int kper = K / KSPLIT;
    const int kbeg = blockIdx.z * kper;

    float acc[TM][TN];
#pragma unroll
    for (int i = 0; i < TM; i++)
#pragma unroll
        for (int j = 0; j < TN; j++) acc[i][j] = 0.0f;

    for (int k0 = kbeg; k0 < kbeg + kper; k0 += BK) {
        for (int i = tid; i < BM * BK; i += NT) {
            int m = i / BK, k = i % BK;
            As[k][m] = A[(size_t)(m0 + m) * lda + (k0 + k)];
        }
        for (int i = tid; i < BN * BK; i += NT) {
            int n = i / BK, k = i % BK;
            Ws[k][n] = W[(size_t)(n0 + n) * ldw + (k0 + k)];
        }
        __syncthreads();

#pragma unroll
        for (int k = 0; k < BK; k++) {
            float a[TM], w[TN];
#pragma unroll
            for (int i = 0; i < TM; i++) a[i] = As[k][ty * TM + i];
#pragma unroll
            for (int j = 0; j < TN; j++) w[j] = Ws[k][tx * TN + j];
#pragma unroll
            for (int i = 0; i < TM; i++)
#pragma unroll
                for (int j = 0; j < TN; j++)
                    acc[i][j] = fmaf(a[i], w[j], acc[i][j]);
        }
        __syncthreads();
    }

    float* Cz = Cpart + (size_t)blockIdx.z * M * N;
#pragma unroll
    for (int i = 0; i < TM; i++) {
        int m = m0 + ty * TM + i;
#pragma unroll
        for (int j = 0; j < TN; j++) {
            int n = n0 + tx * TN + j;
            Cz[(size_t)m * ldc + n] = acc[i][j];
        }
    }
}

__global__ void reduce_xdbl_kernel(const float* __restrict__ part,
                                   float* __restrict__ out,
                                   float* __restrict__ outr)
{
    int i = blockIdx.x * 256 + threadIdx.x;
    if (i < NTOK * XDBL_W) {
        float s = 0.0f;
#pragma unroll
        for (int z = 0; z < KSPLIT; z++)
            s += part[(size_t)z * NTOK * XDBL_W + i];
        out[i]  = s;
        outr[i] = tf32r(s);
    }
}

// ------------------- causal depthwise conv (4 taps) + silu -----------------
__global__ void conv_silu_kernel(const float* __restrict__ xz,
                                 const float* __restrict__ conv_w,
                                 const float* __restrict__ conv_b,
                                 float* __restrict__ xc)
{
    int idx = blockIdx.x * blockDim.x + threadIdx.x;
    if (idx >= NTOK * DINNER) return;
    int d   = idx % DINNER;
    int row = idx / DINNER;
    int l   = row & (SEQLEN - 1);
    int b   = row >> 11;            // SEQLEN = 2048

    float w0 = conv_w[d * DCONV + 0];
    float w1 = conv_w[d * DCONV + 1];
    float w2 = conv_w[d * DCONV + 2];
    float w3 = conv_w[d * DCONV + 3];

    float acc = conv_b[d];
    const size_t base = ((size_t)b * SEQLEN) * (2 * DINNER) + d;
    if (l >= 3) acc += w0 * xz[base + (size_t)(l - 3) * (2 * DINNER)];
    if (l >= 2) acc += w1 * xz[base + (size_t)(l - 2) * (2 * DINNER)];
    if (l >= 1) acc += w2 * xz[base + (size_t)(l - 1) * (2 * DINNER)];
    acc += w3 * xz[base + (size_t)l * (2 * DINNER)];

    xc[idx] = silu_f(acc);
}

// ---------------- selective scan: cp.async chunked, smem-fed ---------------
// Block: 128 threads = 8 channels x 16 states. Chunks of 64 timesteps,
// double-buffered via cp.async.
#define LCH 64
#define NCHUNK (SEQLEN / LCH)   // 32

struct __align__(16) ScanSmem {
    float dt[2][LCH][8];
    float xc[2][LCH][8];
    float zz[2][LCH][8];
    float qq[2][LCH][8];
    float Bm[2][LCH][16];
    float Cm[2][LCH][16];
};

__global__ void __launch_bounds__(128)
scan_kernel(const float* __restrict__ xdbl, const float* __restrict__ dt,
            const float* __restrict__ xc,   const float* __restrict__ xz,
            const float* __restrict__ q,    const float* __restrict__ A_log,
            const float* __restrict__ Dvec, float* __restrict__ yout)
{
    __shared__ ScanSmem sm;

    const int tid = threadIdx.x;
    const int grp = tid >> 4;          // 0..7   (channel within block)
    const int n   = tid & 15;          // state index
    const int ch0 = blockIdx.x * 8;
    const int b   = ch0 / DINNER;
    const int d0  = ch0 % DINNER;
    const int d   = d0 + grp;

    const float An = -__expf(A_log[d * DSTATE + n]);
    const float Dd = Dvec[d];

    const int row0 = b * SEQLEN;

    // per-thread cp.async assignments
    const int lA  = tid >> 1;          // 0..63 (row for 8-wide arrays)
    const int hA  = (tid & 1) * 4;     // 0 or 4
    const int lB0 = tid >> 2;          // 0..31 base for 16-wide arrays
    const int qB  = (tid & 3) * 4;     // 0,4,8,12

    auto stage = [&](int c, int s) {
        const int lbase = c * LCH;
        {
            const size_t r = (size_t)(row0 + lbase + lA);
            cp16(&sm.dt[s][lA][hA], &dt[r * DINNER + d0 + hA]);
            cp16(&sm.xc[s][lA][hA], &xc[r * DINNER + d0 + hA]);
            cp16(&sm.zz[s][lA][hA], &xz[r * (2 * DINNER) + DINNER + d0 + hA]);
            cp16(&sm.qq[s][lA][hA], &q [r * DINNER + d0 + hA]);
        }
#pragma unroll
        for (int k = 0; k < 2; k++) {
            const int l = lB0 + k * 32;
            const size_t r = (size_t)(row0 + lbase + l);
            cp16(&sm.Bm[s][l][qB], &xdbl[r * XDBL_W + DTRANK + qB]);
            cp16(&sm.Cm[s][l][qB], &xdbl[r * XDBL_W + DTRANK + DSTATE + qB]);
        }
        cp_commit();
    };

    float h = 0.0f;

    stage(0, 0);
    for (int c = 0; c < NCHUNK; c++) {
        const int s = c & 1;
        if (c + 1 < NCHUNK) {
            stage(c + 1, s ^ 1);
            asm volatile("cp.async.wait_group 1;" ::: "memory");
        } else {
            asm volatile("cp.async.wait_group 0;" ::: "memory");
        }
        __syncthreads();

#pragma unroll 4
        for (int l = 0; l < LCH; l++) {
            const float dtv = sm.dt[s][l][grp];
            const float xv  = sm.xc[s][l][grp];
            const float Bv  = sm.Bm[s][l][n];
            const float Cv  = sm.Cm[s][l][n];

            const float dA = __expf(dtv * An);
            h = fmaf(dA, h, dtv * xv * Bv);

            float p = h * Cv;
            p += __shfl_xor_sync(0xffffffffu, p, 8);
            p += __shfl_xor_sync(0xffffffffu, p, 4);
            p += __shfl_xor_sync(0xffffffffu, p, 2);
            p += __shfl_xor_sync(0xffffffffu, p, 1);

            if (n == 0) {
                float y  = p + xv * Dd;
                const float zv = sm.zz[s][l][grp];
                const float qv = sm.qq[s][l][grp];
                y = y * silu_f(zv) * silu_f(qv);
                yout[(size_t)(row0 + c * LCH + l) * DINNER + d] = tf32r(y);
            }
        }
        __syncthreads();
    }
}

// --------------------------------- host ------------------------------------
extern "C" void kernel_launch(void* const* d_in, const int* in_sizes, int n_in,
                              void* d_out, int out_size)
{
    const float* hs         = (const float*)d_in[0];
    const float* query      = (const float*)d_in[1];
    const float* in_proj_w  = (const float*)d_in[2];
    const float* conv_w     = (const float*)d_in[3];
    const float* conv_b     = (const float*)d_in[4];
    const float* x_proj_w   = (const float*)d_in[5];
    const float* dt_proj_w  = (const float*)d_in[6];
    const float* dt_proj_b  = (const float*)d_in[7];
    const float* A_log      = (const float*)d_in[8];
    const float* Dvec       = (const float*)d_in[9];
    const float* query_w    = (const float*)d_in[10];
    const float* query_b    = (const float*)d_in[11];
    const float* out_proj_w = (const float*)d_in[12];
    float* out = (float*)d_out;

    float *p_xz, *p_q, *p_xc, *p_xdbl, *p_xdblr, *p_xdp, *p_dt, *p_y;
    float *p_hsr, *p_qur, *p_w1, *p_w2, *p_w3, *p_w4;
    cudaGetSymbolAddress((void**)&p_xz,    g_xz);
    cudaGetSymbolAddress((void**)&p_q,     g_q);
    cudaGetSymbolAddress((void**)&p_xc,    g_xc);
    cudaGetSymbolAddress((void**)&p_xdbl,  g_xdbl);
    cudaGetSymbolAddress((void**)&p_xdblr, g_xdblr);
    cudaGetSymbolAddress((void**)&p_xdp,   g_xdp);
    cudaGetSymbolAddress((void**)&p_dt,    g_dt);
    cudaGetSymbolAddress((void**)&p_y,     g_y);
    cudaGetSymbolAddress((void**)&p_hsr,   g_hsr);
    cudaGetSymbolAddress((void**)&p_qur,   g_qur);
    cudaGetSymbolAddress((void**)&p_w1,    g_w1);
    cudaGetSymbolAddress((void**)&p_w2,    g_w2);
    cudaGetSymbolAddress((void**)&p_w3,    g_w3);
    cudaGetSymbolAddress((void**)&p_w4,    g_w4);

    // 0) pre-round all tf32-GEMM inputs (rna) once
    auto roundN = [](const float* in, float* out, int n) {
        int n4 = n / 4;
        round_tf32_kernel<<<(n4 + 255) / 256, 256>>>(in, out, n4);
    };
    roundN(hs,         p_hsr, NTOK * DMODEL);
    roundN(query,      p_qur, NTOK * DMODEL);
    roundN(in_proj_w,  p_w1,  2 * DINNER * DMODEL);
    roundN(query_w,    p_w2,  DINNER * DMODEL);
    roundN(out_proj_w, p_w3,  DMODEL * DINNER);
    roundN(dt_proj_w,  p_w4,  DINNER * DTRANK);

    // 1) xz = hs @ in_proj_w^T            (4096 x 3072, K=768)
    gemm_tf32f<0><<<dim3(2 * DINNER / TBN, NTOK / TBM), 256>>>(
        p_hsr, p_w1, nullptr, p_xz, NTOK, 2 * DINNER, DMODEL,
        DMODEL, DMODEL, 2 * DINNER);

    // 2) q = query @ query_w^T + query_b  (4096 x 1536, K=768)
    gemm_tf32f<1><<<dim3(DINNER / TBN, NTOK / TBM), 256>>>(
        p_qur, p_w2, query_b, p_q, NTOK, DINNER, DMODEL,
        DMODEL, DMODEL, DINNER);

    // 3) causal depthwise conv + silu
    {
        int total = NTOK * DINNER;
        conv_silu_kernel<<<(total + 255) / 256, 256>>>(p_xz, conv_w, conv_b, p_xc);
    }

    // 4) x_dbl = xc @ x_proj_w^T          (4096 x 80, K=1536)  [split-K SIMT]
    gemm_tn_splitk<128, 80, 16, 8, 5><<<dim3(1, NTOK / 128, KSPLIT), 256>>>(
        p_xc, x_proj_w, p_xdp, NTOK, XDBL_W, DINNER,
        DINNER, DINNER, XDBL_W);
    reduce_xdbl_kernel<<<(NTOK * XDBL_W + 255) / 256, 256>>>(p_xdp, p_xdbl, p_xdblr);

    // 5) dt = softplus(x_dbl[:, :48] @ dt_proj_w^T + dt_proj_b)  (K=48)
    gemm_tf32f<2><<<dim3(DINNER / TBN, NTOK / TBM), 256>>>(
        p_xdblr, p_w4, dt_proj_b, p_dt, NTOK, DINNER, DTRANK,
        XDBL_W, DTRANK, DINNER);

    // 6) selective scan + D skip + silu(z) + silu(q) gating
    scan_kernel<<<NBATCH * DINNER / 8, 128>>>(
        p_xdbl, p_dt, p_xc, p_xz, p_q, A_log, Dvec, p_y);

    // 7) out = y @ out_proj_w^T           (4096 x 768, K=1536)
    gemm_tf32f<0><<<dim3(DMODEL / TBN, NTOK / TBM), 256>>>(
        p_y, p_w3, nullptr, out, NTOK, DMODEL, DINNER,
        DINNER, DINNER, DMODEL);
}

// round 9
// speedup vs baseline: 5.1657x; 1.1895x over previous
#include <cuda_runtime.h>
#include <cuda_fp16.h>
#include <cstdint>

// Problem constants
#define DMODEL   768
#define DSTATE   16
#define DCONV    4
#define DINNER   1536
#define DTRANK   48
#define NBATCH   2
#define SEQLEN   2048
#define NTOK     (NBATCH * SEQLEN)        // 4096
#define XDBL_W   (DTRANK + 2 * DSTATE)    // 80
#define KSPLIT   8
#define DTK      64                        // padded K for dt gemm

// -------- scratch (static device globals; no runtime allocation) ----------
__device__ float  g_xz   [NTOK * 2 * DINNER];
__device__ float  g_q    [NTOK * DINNER];
__device__ float  g_xc   [NTOK * DINNER];
__device__ float  g_xdbl [NTOK * XDBL_W];
__device__ float  g_xdp  [KSPLIT * NTOK * XDBL_W];
__device__ float  g_dt   [NTOK * DINNER];
// fp16 GEMM operands
__device__ __half g_hsh  [NTOK * DMODEL];
__device__ __half g_quh  [NTOK * DMODEL];
__device__ __half g_w1h  [2 * DINNER * DMODEL];
__device__ __half g_w2h  [DINNER * DMODEL];
__device__ __half g_w3h  [DMODEL * DINNER];
__device__ __half g_w4h  [DINNER * DTK];
__device__ __half g_xdinh[NTOK * DTK];
__device__ __half g_yh   [NTOK * DINNER];

// -------------------------- helpers ---------------------------------------
__device__ __forceinline__ float silu_f(float x) {
    return x / (1.0f + __expf(-x));
}
__device__ __forceinline__ float softplus_f(float x) {
    return (x > 20.0f) ? x : log1pf(__expf(x));
}
__device__ __forceinline__ void cp16(void* s, const void* g) {
    uint32_t sa = (uint32_t)__cvta_generic_to_shared(s);
    asm volatile("cp.async.ca.shared.global [%0], [%1], 16;" :: "r"(sa), "l"(g));
}
__device__ __forceinline__ void cp_commit() {
    asm volatile("cp.async.commit_group;" ::: "memory");
}
__device__ __forceinline__ void ldsm_x4(uint32_t* r, uint32_t addr) {
    asm volatile("ldmatrix.sync.aligned.m8n8.x4.shared.b16 {%0,%1,%2,%3}, [%4];"
                 : "=r"(r[0]), "=r"(r[1]), "=r"(r[2]), "=r"(r[3]) : "r"(addr));
}
__device__ __forceinline__ void mma_f16(float* d, const uint32_t* a, const uint32_t* b) {
    asm volatile(
        "mma.sync.aligned.m16n8k16.row.col.f32.f16.f16.f32 "
        "{%0,%1,%2,%3}, {%4,%5,%6,%7}, {%8,%9}, {%0,%1,%2,%3};\n"
        : "+f"(d[0]), "+f"(d[1]), "+f"(d[2]), "+f"(d[3])
        : "r"(a[0]), "r"(a[1]), "r"(a[2]), "r"(a[3]), "r"(b[0]), "r"(b[1]));
}

// ---------------- fp32 -> fp16 conversion pass (vectorized) ----------------
__global__ void f2h_kernel(const float* __restrict__ in,
                           __half* __restrict__ out, int n8)
{
    int i = blockIdx.x * blockDim.x + threadIdx.x;
    if (i < n8) {
        float4 v0 = ((const float4*)in)[2 * i];
        float4 v1 = ((const float4*)in)[2 * i + 1];
        __half2 hp[4];
        hp[0] = __floats2half2_rn(v0.x, v0.y);
        hp[1] = __floats2half2_rn(v0.z, v0.w);
        hp[2] = __floats2half2_rn(v1.x, v1.y);
        hp[3] = __floats2half2_rn(v1.z, v1.w);
        ((uint4*)out)[i] = *(const uint4*)hp;
    }
}

// pad dt weights [1536,48] -> fp16 [1536,64], zero tail
__global__ void pad_w4_kernel(const float* __restrict__ w,
                              __half* __restrict__ out)
{
    int i = blockIdx.x * blockDim.x + threadIdx.x;
    if (i < DINNER * DTK) {
        int row = i >> 6, col = i & 63;
        out[i] = (col < DTRANK) ? __float2half(w[row * DTRANK + col])
                                : __float2half(0.0f);
    }
}

// ================= fp16 tensor-core GEMM: C = A * W^T + (bias) =============
// A: [M,K] half (lda), W: [N,K] half (ldw), C: [M,N] fp32 (ldc)
// Block tile 128x128, BK=32, 8 warps (2 M x 4 N), warp tile 64x32.
// EPI: 0 = none, 1 = +bias[n], 2 = +bias[n] then softplus
#define HBM 128
#define HBN 128
#define HBK 32
#define HSTR 40   // halfs per smem row (32 data + 8 pad); conflict-free ldsm

template<int EPI>
__global__ void __launch_bounds__(256, 2)
gemm_hf(const __half* __restrict__ A, const __half* __restrict__ W,
        const float* __restrict__ bias, float* __restrict__ C,
        int K, int lda, int ldw, int ldc)
{
    __shared__ __half As[2][HBM][HSTR];
    __shared__ __half Ws[2][HBN][HSTR];

    const int tid  = threadIdx.x;
    const int m0   = blockIdx.y * HBM;
    const int n0   = blockIdx.x * HBN;
    const int warp = tid >> 5;
    const int lane = tid & 31;
    const int g    = lane >> 2;        // 0..7
    const int t    = lane & 3;         // 0..3
    const int wm   = (warp & 1) * 64;  // warp M offset
    const int wn   = (warp >> 1) * 32; // warp N offset

    // ldmatrix per-lane address components
    const int u   = lane & 7;          // row within 8-row tile
    const int grp = lane >> 3;         // address group 0..3

    const uint32_t aBase = (uint32_t)__cvta_generic_to_shared(&As[0][0][0]);
    const uint32_t wBase = (uint32_t)__cvta_generic_to_shared(&Ws[0][0][0]);
    const uint32_t stg   = HBM * HSTR * 2;   // bytes per stage

    // A tiles (order matches a0..a3): {(r0-7,k0-7),(r8-15,k0-7),(r0-7,k8-15),(r8-15,k8-15)}
    uint32_t aA[4];
#pragma unroll
    for (int mt = 0; mt < 4; mt++) {
        int row  = wm + mt * 16 + (grp & 1) * 8 + u;
        int kofh = (grp >> 1) * 8;      // halfs
        aA[mt] = aBase + (uint32_t)(row * HSTR + kofh) * 2u;
    }
    // B tiles (pair p covers nt=2p,2p+1): {(n=2p,k0-7),(2p,k8-15),(2p+1,k0-7),(2p+1,k8-15)}
    uint32_t aB[2];
#pragma unroll
    for (int p = 0; p < 2; p++) {
        int row  = wn + (2 * p + (grp >> 1)) * 8 + u;
        int kofh = (grp & 1) * 8;
        aB[p] = wBase + (uint32_t)(row * HSTR + kofh) * 2u;
    }

    // loader: 64 rows/pass x 4 chunks of 8 halfs (16B) per 32-col row
    const int lr = tid >> 2;         // 0..63
    const int lc = (tid & 3) * 8;    // halfs: 0,8,16,24
    const int niter = K / HBK;

    const __half* Abase = A + (size_t)(m0 + lr) * lda + lc;
    const __half* Wbase = W + (size_t)(n0 + lr) * ldw + lc;

    float acc[4][4][4];
#pragma unroll
    for (int mt = 0; mt < 4; mt++)
#pragma unroll
        for (int nt = 0; nt < 4; nt++)
#pragma unroll
            for (int i = 0; i < 4; i++) acc[mt][nt][i] = 0.0f;

    // prologue: stage 0
    cp16(&As[0][lr][lc],      Abase);
    cp16(&As[0][lr + 64][lc], Abase + (size_t)64 * lda);
    cp16(&Ws[0][lr][lc],      Wbase);
    cp16(&Ws[0][lr + 64][lc], Wbase + (size_t)64 * ldw);
    cp_commit();

    for (int it = 0; it < niter; it++) {
        if (it + 1 < niter) {
            const int s = (it + 1) & 1;
            const int k0 = (it + 1) * HBK;
            cp16(&As[s][lr][lc],      Abase + k0);
            cp16(&As[s][lr + 64][lc], Abase + k0 + (size_t)64 * lda);
            cp16(&Ws[s][lr][lc],      Wbase + k0);
            cp16(&Ws[s][lr + 64][lc], Wbase + k0 + (size_t)64 * ldw);
            cp_commit();
            asm volatile("cp.async.wait_group 1;" ::: "memory");
        } else {
            asm volatile("cp.async.wait_group 0;" ::: "memory");
        }
        __syncthreads();

        const uint32_t sOff = (uint32_t)(it & 1) * stg;
#pragma unroll
        for (int kk = 0; kk < 2; kk++) {                 // two k16 steps
            const uint32_t kOff = sOff + (uint32_t)kk * 32u;  // 16 halfs = 32B
            uint32_t afr[4][4];
            uint32_t bfr[4][2];
#pragma unroll
            for (int mt = 0; mt < 4; mt++)
                ldsm_x4(afr[mt], aA[mt] + kOff);
            {
                uint32_t r[4];
                ldsm_x4(r, aB[0] + kOff);
                bfr[0][0] = r[0]; bfr[0][1] = r[1];
                bfr[1][0] = r[2]; bfr[1][1] = r[3];
                ldsm_x4(r, aB[1] + kOff);
                bfr[2][0] = r[0]; bfr[2][1] = r[1];
                bfr[3][0] = r[2]; bfr[3][1] = r[3];
            }
#pragma unroll
            for (int mt = 0; mt < 4; mt++)
#pragma unroll
                for (int nt = 0; nt < 4; nt++)
                    mma_f16(acc[mt][nt], afr[mt], bfr[nt]);
        }
        __syncthreads();
    }

    // epilogue: c0:(g,2t) c1:(g,2t+1) c2:(g+8,2t) c3:(g+8,2t+1)
#pragma unroll
    for (int mt = 0; mt < 4; mt++) {
#pragma unroll
        for (int nt = 0; nt < 4; nt++) {
            const int row = m0 + wm + mt * 16 + g;
            const int col = n0 + wn + nt * 8 + 2 * t;
            float v0 = acc[mt][nt][0];
            float v1 = acc[mt][nt][1];
            float v2 = acc[mt][nt][2];
            float v3 = acc[mt][nt][3];
            if (EPI >= 1) {
                const float b0 = bias[col];
                const float b1 = bias[col + 1];
                v0 += b0; v1 += b1; v2 += b0; v3 += b1;
            }
            if (EPI == 2) {
                v0 = softplus_f(v0); v1 = softplus_f(v1);
                v2 = softplus_f(v2); v3 = softplus_f(v3);
            }
            float2* p0 = (float2*)&C[(size_t)row * ldc + col];
            float2* p1 = (float2*)&C[(size_t)(row + 8) * ldc + col];
            *p0 = make_float2(v0, v1);
            *p1 = make_float2(v2, v3);
        }
    }
}

// ---------------- SIMT split-K GEMM for x_proj (N=80) ----------------------
template<int BM, int BN, int BK, int TM, int TN>
__global__ void __launch_bounds__((BM / TM) * (BN / TN))
gemm_tn_splitk(const float* __restrict__ A, const float* __restrict__ W,
               float* __restrict__ Cpart,
               int M, int N, int K, int lda, int ldw, int ldc)
{
    constexpr int TX = BN / TN;
    constexpr int TY = BM / TM;
    constexpr int NT = TX * TY;

    __shared__ float As[BK][BM + 1];
    __shared__ float Ws[BK][BN + 1];

    const int tid = threadIdx.x;
    const int tx  = tid % TX;
    const int ty  = tid / TX;
    const int m0  = blockIdx.y * BM;
    const int n0  = blockIdx.x * BN;

    const int kper = K / KSPLIT;
    const int kbeg = blockIdx.z * kper;

    float acc[TM][TN];
#pragma unroll
    for (int i = 0; i < TM; i++)
#pragma unroll
        for (int j = 0; j < TN; j++) acc[i][j] = 0.0f;

    for (int k0 = kbeg; k0 < kbeg + kper; k0 += BK) {
        for (int i = tid; i < BM * BK; i += NT) {
            int m = i / BK, k = i % BK;
            As[k][m] = A[(size_t)(m0 + m) * lda + (k0 + k)];
        }
        for (int i = tid; i < BN * BK; i += NT) {
            int n = i / BK, k = i % BK;
            Ws[k][n] = W[(size_t)(n0 + n) * ldw + (k0 + k)];
        }
        __syncthreads();

#pragma unroll
        for (int k = 0; k < BK; k++) {
            float a[TM], w[TN];
#pragma unroll
            for (int i = 0; i < TM; i++) a[i] = As[k][ty * TM + i];
#pragma unroll
            for (int j = 0; j < TN; j++) w[j] = Ws[k][tx * TN + j];
#pragma unroll
            for (int i = 0; i < TM; i++)
#pragma unroll
                for (int j = 0; j < TN; j++)
                    acc[i][j] = fmaf(a[i], w[j], acc[i][j]);
        }
        __syncthreads();
    }

    float* Cz = Cpart + (size_t)blockIdx.z * M * N;
#pragma unroll
    for (int i = 0; i < TM; i++) {
        int m = m0 + ty * TM + i;
#pragma unroll
        for (int j = 0; j < TN; j++) {
            int n = n0 + tx * TN + j;
            Cz[(size_t)m * ldc + n] = acc[i][j];
        }
    }
}

// reduce split-K partials; also emit padded fp16 dt-gemm input
__global__ void reduce_xdbl_kernel(const float* __restrict__ part,
                                   float* __restrict__ out,
                                   __half* __restrict__ outp)
{
    int i = blockIdx.x * 256 + threadIdx.x;
    if (i < NTOK * XDBL_W) {
        float s = 0.0f;
#pragma unroll
        for (int z = 0; z < KSPLIT; z++)
            s += part[(size_t)z * NTOK * XDBL_W + i];
        out[i] = s;
        int row = i / XDBL_W, col = i % XDBL_W;
        if (col < DTRANK)   outp[row * DTK + col] = __float2half(s);
        else if (col < DTK) outp[row * DTK + col] = __float2half(0.0f);
    }
}

// ------------------- causal depthwise conv (4 taps) + silu -----------------
__global__ void conv_silu_kernel(const float* __restrict__ xz,
                                 const float* __restrict__ conv_w,
                                 const float* __restrict__ conv_b,
                                 float* __restrict__ xc)
{
    int idx = blockIdx.x * blockDim.x + threadIdx.x;
    if (idx >= NTOK * DINNER) return;
    int d   = idx % DINNER;
    int row = idx / DINNER;
    int l   = row & (SEQLEN - 1);
    int b   = row >> 11;            // SEQLEN = 2048

    float w0 = conv_w[d * DCONV + 0];
    float w1 = conv_w[d * DCONV + 1];
    float w2 = conv_w[d * DCONV + 2];
    float w3 = conv_w[d * DCONV + 3];

    float acc = conv_b[d];
    const size_t base = ((size_t)b * SEQLEN) * (2 * DINNER) + d;
    if (l >= 3) acc += w0 * xz[base + (size_t)(l - 3) * (2 * DINNER)];
    if (l >= 2) acc += w1 * xz[base + (size_t)(l - 2) * (2 * DINNER)];
    if (l >= 1) acc += w2 * xz[base + (size_t)(l - 1) * (2 * DINNER)];
    acc += w3 * xz[base + (size_t)l * (2 * DINNER)];

    xc[idx] = silu_f(acc);
}

// ---------------- selective scan: cp.async chunked, smem-fed ---------------
#define LCH 64
#define NCHUNK (SEQLEN / LCH)   // 32

struct __align__(16) ScanSmem {
    float dt[2][LCH][8];
    float xc[2][LCH][8];
    float zz[2][LCH][8];
    float qq[2][LCH][8];
    float Bm[2][LCH][16];
    float Cm[2][LCH][16];
};

__global__ void __launch_bounds__(128)
scan_kernel(const float* __restrict__ xdbl, const float* __restrict__ dt,
            const float* __restrict__ xc,   const float* __restrict__ xz,
            const float* __restrict__ q,    const float* __restrict__ A_log,
            const float* __restrict__ Dvec, __half* __restrict__ yout)
{
    __shared__ ScanSmem sm;

    const int tid = threadIdx.x;
    const int grp = tid >> 4;          // 0..7   (channel within block)
    const int n   = tid & 15;          // state index
    const int ch0 = blockIdx.x * 8;
    const int b   = ch0 / DINNER;
    const int d0  = ch0 % DINNER;
    const int d   = d0 + grp;

    const float An = -__expf(A_log[d * DSTATE + n]);
    const float Dd = Dvec[d];

    const int row0 = b * SEQLEN;

    const int lA  = tid >> 1;          // 0..63
    const int hA  = (tid & 1) * 4;     // 0 or 4
    const int lB0 = tid >> 2;          // 0..31
    const int qB  = (tid & 3) * 4;     // 0,4,8,12

    auto stage = [&](int c, int s) {
        const int lbase = c * LCH;
        {
            const size_t r = (size_t)(row0 + lbase + lA);
            cp16(&sm.dt[s][lA][hA], &dt[r * DINNER + d0 + hA]);
            cp16(&sm.xc[s][lA][hA], &xc[r * DINNER + d0 + hA]);
            cp16(&sm.zz[s][lA][hA], &xz[r * (2 * DINNER) + DINNER + d0 + hA]);
            cp16(&sm.qq[s][lA][hA], &q [r * DINNER + d0 + hA]);
        }
#pragma unroll
        for (int k = 0; k < 2; k++) {
            const int l = lB0 + k * 32;
            const size_t r = (size_t)(row0 + lbase + l);
            cp16(&sm.Bm[s][l][qB], &xdbl[r * XDBL_W + DTRANK + qB]);
            cp16(&sm.Cm[s][l][qB], &xdbl[r * XDBL_W + DTRANK + DSTATE + qB]);
        }
        cp_commit();
    };

    float h = 0.0f;

    stage(0, 0);
    for (int c = 0; c < NCHUNK; c++) {
        const int s = c & 1;
        if (c + 1 < NCHUNK) {
            stage(c + 1, s ^ 1);
            asm volatile("cp.async.wait_group 1;" ::: "memory");
        } else {
            asm volatile("cp.async.wait_group 0;" ::: "memory");
        }
        __syncthreads();

#pragma unroll 4
        for (int l = 0; l < LCH; l++) {
            const float dtv = sm.dt[s][l][grp];
            const float xv  = sm.xc[s][l][grp];
            const float Bv  = sm.Bm[s][l][n];
            const float Cv  = sm.Cm[s][l][n];

            const float dA = __expf(dtv * An);
            h = fmaf(dA, h, dtv * xv * Bv);

            float p = h * Cv;
            p += __shfl_xor_sync(0xffffffffu, p, 8);
            p += __shfl_xor_sync(0xffffffffu, p, 4);
            p += __shfl_xor_sync(0xffffffffu, p, 2);
            p += __shfl_xor_sync(0xffffffffu, p, 1);

            if (n == 0) {
                float y  = p + xv * Dd;
                const float zv = sm.zz[s][l][grp];
                const float qv = sm.qq[s][l][grp];
                y = y * silu_f(zv) * silu_f(qv);
                yout[(size_t)(row0 + c * LCH + l) * DINNER + d] = __float2half(y);
            }
        }
        __syncthreads();
    }
}

// --------------------------------- host ------------------------------------
extern "C" void kernel_launch(void* const* d_in, const int* in_sizes, int n_in,
                              void* d_out, int out_size)
{
    const float* hs         = (const float*)d_in[0];
    const float* query      = (const float*)d_in[1];
    const float* in_proj_w  = (const float*)d_in[2];
    const float* conv_w     = (const float*)d_in[3];
    const float* conv_b     = (const float*)d_in[4];
    const float* x_proj_w   = (const float*)d_in[5];
    const float* dt_proj_w  = (const float*)d_in[6];
    const float* dt_proj_b  = (const float*)d_in[7];
    const float* A_log      = (const float*)d_in[8];
    const float* Dvec       = (const float*)d_in[9];
    const float* query_w    = (const float*)d_in[10];
    const float* query_b    = (const float*)d_in[11];
    const float* out_proj_w = (const float*)d_in[12];
    float* out = (float*)d_out;

    float  *p_xz, *p_q, *p_xc, *p_xdbl, *p_xdp, *p_dt;
    __half *p_hsh, *p_quh, *p_w1h, *p_w2h, *p_w3h, *p_w4h, *p_xdinh, *p_yh;
    cudaGetSymbolAddress((void**)&p_xz,    g_xz);
    cudaGetSymbolAddress((void**)&p_q,     g_q);
    cudaGetSymbolAddress((void**)&p_xc,    g_xc);
    cudaGetSymbolAddress((void**)&p_xdbl,  g_xdbl);
    cudaGetSymbolAddress((void**)&p_xdp,   g_xdp);
    cudaGetSymbolAddress((void**)&p_dt,    g_dt);
    cudaGetSymbolAddress((void**)&p_hsh,   g_hsh);
    cudaGetSymbolAddress((void**)&p_quh,   g_quh);
    cudaGetSymbolAddress((void**)&p_w1h,   g_w1h);
    cudaGetSymbolAddress((void**)&p_w2h,   g_w2h);
    cudaGetSymbolAddress((void**)&p_w3h,   g_w3h);
    cudaGetSymbolAddress((void**)&p_w4h,   g_w4h);
    cudaGetSymbolAddress((void**)&p_xdinh, g_xdinh);
    cudaGetSymbolAddress((void**)&p_yh,    g_yh);

    auto toHalf = [](const float* in, __half* out, int n) {
        int n8 = n / 8;
        f2h_kernel<<<(n8 + 255) / 256, 256>>>(in, out, n8);
    };

    // 1) xz = hs @ in_proj_w^T  (4096 x 3072, K=768)  [fp16 HMMA]
    toHalf(hs,        p_hsh, NTOK * DMODEL);
    toHalf(in_proj_w, p_w1h, 2 * DINNER * DMODEL);
    gemm_hf<0><<<dim3(2 * DINNER / HBN, NTOK / HBM), 256>>>(
        p_hsh, p_w1h, nullptr, p_xz, DMODEL, DMODEL, DMODEL, 2 * DINNER);

    // 2) q = query @ query_w^T + query_b  (4096 x 1536, K=768)
    toHalf(query,   p_quh, NTOK * DMODEL);
    toHalf(query_w, p_w2h, DINNER * DMODEL);
    gemm_hf<1><<<dim3(DINNER / HBN, NTOK / HBM), 256>>>(
        p_quh, p_w2h, query_b, p_q, DMODEL, DMODEL, DMODEL, DINNER);

    // 3) causal depthwise conv + silu
    {
        int total = NTOK * DINNER;
        conv_silu_kernel<<<(total + 255) / 256, 256>>>(p_xz, conv_w, conv_b, p_xc);
    }

    // 4) x_dbl = xc @ x_proj_w^T  (4096 x 80, K=1536)  [split-K SIMT fp32]
    gemm_tn_splitk<128, 80, 16, 8, 5><<<dim3(1, NTOK / 128, KSPLIT), 256>>>(
        p_xc, x_proj_w, p_xdp, NTOK, XDBL_W, DINNER,
        DINNER, DINNER, XDBL_W);
    reduce_xdbl_kernel<<<(NTOK * XDBL_W + 255) / 256, 256>>>(p_xdp, p_xdbl, p_xdinh);

    // 5) dt = softplus(xdin @ w4^T + dt_proj_b)  (K=64 padded, fp16)
    pad_w4_kernel<<<(DINNER * DTK + 255) / 256, 256>>>(dt_proj_w, p_w4h);
    gemm_hf<2><<<dim3(DINNER / HBN, NTOK / HBM), 256>>>(
        p_xdinh, p_w4h, dt_proj_b, p_dt, DTK, DTK, DTK, DINNER);

    // 6) selective scan + D skip + silu(z) + silu(q) gating -> fp16 y
    scan_kernel<<<NBATCH * DINNER / 8, 128>>>(
        p_xdbl, p_dt, p_xc, p_xz, p_q, A_log, Dvec, p_yh);

    // 7) out = y @ out_proj_w^T  (4096 x 768, K=1536)  [fp16]
    toHalf(out_proj_w, p_w3h, DMODEL * DINNER);
    gemm_hf<0><<<dim3(DMODEL / HBN, NTOK / HBM), 256>>>(
        p_yh, p_w3h, nullptr, out, DINNER, DINNER, DINNER, DMODEL);
}

// round 10
// speedup vs baseline: 5.5550x; 1.0754x over previous
#include <cuda_runtime.h>
#include <cuda_fp16.h>
#include <cstdint>

// Problem constants
#define DMODEL   768
#define DSTATE   16
#define DCONV    4
#define DINNER   1536
#define DTRANK   48
#define NBATCH   2
#define SEQLEN   2048
#define NTOK     (NBATCH * SEQLEN)        // 4096
#define XDBL_W   (DTRANK + 2 * DSTATE)    // 80
#define XPN      128                       // padded N for x_proj gemm
#define XPSPLIT  4                         // split-K for x_proj gemm
#define DTK      64                        // padded K for dt gemm

// -------- scratch (static device globals; no runtime allocation) ----------
__device__ float  g_xz   [NTOK * 2 * DINNER];
__device__ float  g_q    [NTOK * DINNER];
__device__ float  g_xc   [NTOK * DINNER];
__device__ float  g_xdbl [NTOK * XDBL_W];
__device__ float  g_xdp  [XPSPLIT * NTOK * XPN];   // x_proj split-K partials
__device__ float  g_dt   [NTOK * DINNER];
// fp16 GEMM operands
__device__ __half g_hsh  [NTOK * DMODEL];
__device__ __half g_quh  [NTOK * DMODEL];
__device__ __half g_w1h  [2 * DINNER * DMODEL];
__device__ __half g_w2h  [DINNER * DMODEL];
__device__ __half g_w3h  [DMODEL * DINNER];
__device__ __half g_w4h  [DINNER * DTK];
__device__ __half g_xpwh [XPN * DINNER];           // padded x_proj weights
__device__ __half g_xch  [NTOK * DINNER];          // fp16 conv output
__device__ __half g_xdinh[NTOK * DTK];
__device__ __half g_yh   [NTOK * DINNER];

// -------------------------- helpers ---------------------------------------
__device__ __forceinline__ float silu_f(float x) {
    return x / (1.0f + __expf(-x));
}
__device__ __forceinline__ float softplus_f(float x) {
    return (x > 20.0f) ? x : log1pf(__expf(x));
}
__device__ __forceinline__ void cp16(void* s, const void* g) {
    uint32_t sa = (uint32_t)__cvta_generic_to_shared(s);
    asm volatile("cp.async.ca.shared.global [%0], [%1], 16;" :: "r"(sa), "l"(g));
}
__device__ __forceinline__ void cp16s(uint32_t saddr, const void* g) {
    asm volatile("cp.async.ca.shared.global [%0], [%1], 16;" :: "r"(saddr), "l"(g));
}
__device__ __forceinline__ void cp_commit() {
    asm volatile("cp.async.commit_group;" ::: "memory");
}
__device__ __forceinline__ void ldsm_x4(uint32_t* r, uint32_t addr) {
    asm volatile("ldmatrix.sync.aligned.m8n8.x4.shared.b16 {%0,%1,%2,%3}, [%4];"
                 : "=r"(r[0]), "=r"(r[1]), "=r"(r[2]), "=r"(r[3]) : "r"(addr));
}
__device__ __forceinline__ void mma_f16(float* d, const uint32_t* a, const uint32_t* b) {
    asm volatile(
        "mma.sync.aligned.m16n8k16.row.col.f32.f16.f16.f32 "
        "{%0,%1,%2,%3}, {%4,%5,%6,%7}, {%8,%9}, {%0,%1,%2,%3};\n"
        : "+f"(d[0]), "+f"(d[1]), "+f"(d[2]), "+f"(d[3])
        : "r"(a[0]), "r"(a[1]), "r"(a[2]), "r"(a[3]), "r"(b[0]), "r"(b[1]));
}

// ---------------- fp32 -> fp16 conversion pass (vectorized) ----------------
__global__ void f2h_kernel(const float* __restrict__ in,
                           __half* __restrict__ out, int n8)
{
    int i = blockIdx.x * blockDim.x + threadIdx.x;
    if (i < n8) {
        float4 v0 = ((const float4*)in)[2 * i];
        float4 v1 = ((const float4*)in)[2 * i + 1];
        __half2 hp[4];
        hp[0] = __floats2half2_rn(v0.x, v0.y);
        hp[1] = __floats2half2_rn(v0.z, v0.w);
        hp[2] = __floats2half2_rn(v1.x, v1.y);
        hp[3] = __floats2half2_rn(v1.z, v1.w);
        ((uint4*)out)[i] = *(const uint4*)hp;
    }
}

// pad dt weights [1536,48] -> fp16 [1536,64], zero tail
__global__ void pad_w4_kernel(const float* __restrict__ w,
                              __half* __restrict__ out)
{
    int i = blockIdx.x * blockDim.x + threadIdx.x;
    if (i < DINNER * DTK) {
        int row = i >> 6, col = i & 63;
        out[i] = (col < DTRANK) ? __float2half(w[row * DTRANK + col])
                                : __float2half(0.0f);
    }
}

// pad x_proj weights [80,1536] -> fp16 [128,1536], zero rows 80..127
__global__ void pad_xw_kernel(const float* __restrict__ w,
                              __half* __restrict__ out)
{
    int i = blockIdx.x * blockDim.x + threadIdx.x;
    if (i < XPN * DINNER) {
        int row = i / DINNER;
        out[i] = (row < XDBL_W) ? __float2half(w[i]) : __float2half(0.0f);
    }
}

// ================= fp16 tensor-core GEMM: C = A * W^T + (bias) =============
// A: [M,K_total] half (lda), W: [N,K_total] half (ldw), C: fp32 (ldc)
// CTA tile 128x128, BK=32, 8 warps (2 M x 4 N), warp tile 64x32.
// 4-stage cp.async pipeline, ONE __syncthreads per K-iter.
// Split-K via gridDim.z: slice k-offset = z*K, C += z*4096*ldc.
// EPI: 0 = none, 1 = +bias[n], 2 = +bias[n] then softplus
#define HBK   32
#define HSTR  40                         // halfs per smem row (32 + 8 pad)
#define HAST  (128 * HSTR * 2)           // bytes of A block per stage (10240)
#define HSTG  (2 * HAST)                 // bytes per stage (A+B) = 20480
#define HNST  4                          // pipeline stages
#define HSMEM (HNST * HSTG)              // 81920 bytes dynamic smem

template<int EPI>
__global__ void __launch_bounds__(256, 2)
gemm_hf(const __half* __restrict__ A, const __half* __restrict__ W,
        const float* __restrict__ bias, float* __restrict__ C,
        int K, int lda, int ldw, int ldc)
{
    extern __shared__ char dynsmem[];
    const uint32_t sb = (uint32_t)__cvta_generic_to_shared(dynsmem);

    const int tid  = threadIdx.x;
    const int m0   = blockIdx.y * 128;
    const int n0   = blockIdx.x * 128;
    const int koff = blockIdx.z * K;
    const int warp = tid >> 5;
    const int lane = tid & 31;
    const int g    = lane >> 2;        // 0..7
    const int t    = lane & 3;         // 0..3
    const int wm   = (warp & 1) * 64;  // warp M offset
    const int wn   = (warp >> 1) * 32; // warp N offset

    // ldmatrix per-lane address components
    const int u   = lane & 7;
    const int grp = lane >> 3;

    // stage-relative fragment addresses
    uint32_t aA[4];
#pragma unroll
    for (int mt = 0; mt < 4; mt++) {
        int row  = wm + mt * 16 + (grp & 1) * 8 + u;
        int kofh = (grp >> 1) * 8;
        aA[mt] = (uint32_t)(row * HSTR + kofh) * 2u;
    }
    uint32_t aB[2];
#pragma unroll
    for (int p = 0; p < 2; p++) {
        int row  = wn + (2 * p + (grp >> 1)) * 8 + u;
        int kofh = (grp & 1) * 8;
        aB[p] = (uint32_t)HAST + (uint32_t)(row * HSTR + kofh) * 2u;
    }

    // loader: 64 rows/pass x 4 chunks of 8 halfs (16B) per 32-col row
    const int lr = tid >> 2;         // 0..63
    const int lc = (tid & 3) * 8;    // halfs: 0,8,16,24
    const int niter = K / HBK;

    const __half* Abase = A + (size_t)(m0 + lr) * lda + koff + lc;
    const __half* Wbase = W + (size_t)(n0 + lr) * ldw + koff + lc;
    const uint32_t dA0 = sb + (uint32_t)(lr * HSTR + lc) * 2u;
    const uint32_t dA1 = sb + (uint32_t)((lr + 64) * HSTR + lc) * 2u;
    const uint32_t dW0 = dA0 + HAST;
    const uint32_t dW1 = dA1 + HAST;

    auto stage_load = [&](int s, int kb) {
        const uint32_t so = (uint32_t)s * HSTG;
        const int k0 = kb * HBK;
        cp16s(dA0 + so, Abase + k0);
        cp16s(dA1 + so, Abase + k0 + (size_t)64 * lda);
        cp16s(dW0 + so, Wbase + k0);
        cp16s(dW1 + so, Wbase + k0 + (size_t)64 * ldw);
    };

    float acc[4][4][4];
#pragma unroll
    for (int mt = 0; mt < 4; mt++)
#pragma unroll
        for (int nt = 0; nt < 4; nt++)
#pragma unroll
            for (int i = 0; i < 4; i++) acc[mt][nt][i] = 0.0f;

    // prologue: stages 0..HNST-2
#pragma unroll
    for (int s = 0; s < HNST - 1; s++) {
        if (s < niter) stage_load(s, s);
        cp_commit();
    }

    for (int it = 0; it < niter; it++) {
        asm volatile("cp.async.wait_group %0;" :: "n"(HNST - 2) : "memory");
        __syncthreads();

        // prefetch stage it+HNST-1 (writes buffer consumed at iter it-1)
        const int pf = it + HNST - 1;
        if (pf < niter) stage_load(pf % HNST, pf);
        cp_commit();

        const uint32_t sOff = sb + (uint32_t)(it % HNST) * HSTG;
#pragma unroll
        for (int kk = 0; kk < 2; kk++) {                 // two k16 steps
            const uint32_t kOff = sOff + (uint32_t)kk * 32u;  // 16 halfs = 32B
            uint32_t afr[4][4];
            uint32_t bfr[4][2];
#pragma unroll
            for (int mt = 0; mt < 4; mt++)
                ldsm_x4(afr[mt], aA[mt] + kOff);
            {
                uint32_t r[4];
                ldsm_x4(r, aB[0] + kOff);
                bfr[0][0] = r[0]; bfr[0][1] = r[1];
                bfr[1][0] = r[2]; bfr[1][1] = r[3];
                ldsm_x4(r, aB[1] + kOff);
                bfr[2][0] = r[0]; bfr[2][1] = r[1];
                bfr[3][0] = r[2]; bfr[3][1] = r[3];
            }
#pragma unroll
            for (int mt = 0; mt < 4; mt++)
#pragma unroll
                for (int nt = 0; nt < 4; nt++)
                    mma_f16(acc[mt][nt], afr[mt], bfr[nt]);
        }
    }

    // epilogue: c0:(g,2t) c1:(g,2t+1) c2:(g+8,2t) c3:(g+8,2t+1)
    float* Cz = C + (size_t)blockIdx.z * NTOK * ldc;
#pragma unroll
    for (int mt = 0; mt < 4; mt++) {
#pragma unroll
        for (int nt = 0; nt < 4; nt++) {
            const int row = m0 + wm + mt * 16 + g;
            const int col = n0 + wn + nt * 8 + 2 * t;
            float v0 = acc[mt][nt][0];
            float v1 = acc[mt][nt][1];
            float v2 = acc[mt][nt][2];
            float v3 = acc[mt][nt][3];
            if (EPI >= 1) {
                const float b0 = bias[col];
                const float b1 = bias[col + 1];
                v0 += b0; v1 += b1; v2 += b0; v3 += b1;
            }
            if (EPI == 2) {
                v0 = softplus_f(v0); v1 = softplus_f(v1);
                v2 = softplus_f(v2); v3 = softplus_f(v3);
            }
            float2* p0 = (float2*)&Cz[(size_t)row * ldc + col];
            float2* p1 = (float2*)&Cz[(size_t)(row + 8) * ldc + col];
            *p0 = make_float2(v0, v1);
            *p1 = make_float2(v2, v3);
        }
    }
}

// reduce x_proj split-K partials; emit xdbl fp32 + padded fp16 dt-gemm input
__global__ void reduce_xdbl_kernel(const float* __restrict__ part,
                                   float* __restrict__ out,
                                   __half* __restrict__ outp)
{
    int i = blockIdx.x * 256 + threadIdx.x;
    if (i < NTOK * XDBL_W) {
        int row = i / XDBL_W, col = i % XDBL_W;
        float s = 0.0f;
#pragma unroll
        for (int z = 0; z < XPSPLIT; z++)
            s += part[(size_t)z * NTOK * XPN + (size_t)row * XPN + col];
        out[i] = s;
        if (col < DTRANK)   outp[row * DTK + col] = __float2half(s);
        else if (col < DTK) outp[row * DTK + col] = __float2half(0.0f);
    }
}

// ------------- causal depthwise conv (4 taps) + silu (fp32 + fp16) ---------
__global__ void conv_silu_kernel(const float* __restrict__ xz,
                                 const float* __restrict__ conv_w,
                                 const float* __restrict__ conv_b,
                                 float* __restrict__ xc,
                                 __half* __restrict__ xch)
{
    int idx = blockIdx.x * blockDim.x + threadIdx.x;
    if (idx >= NTOK * DINNER) return;
    int d   = idx % DINNER;
    int row = idx / DINNER;
    int l   = row & (SEQLEN - 1);
    int b   = row >> 11;            // SEQLEN = 2048

    float w0 = conv_w[d * DCONV + 0];
    float w1 = conv_w[d * DCONV + 1];
    float w2 = conv_w[d * DCONV + 2];
    float w3 = conv_w[d * DCONV + 3];

    float acc = conv_b[d];
    const size_t base = ((size_t)b * SEQLEN) * (2 * DINNER) + d;
    if (l >= 3) acc += w0 * xz[base + (size_t)(l - 3) * (2 * DINNER)];
    if (l >= 2) acc += w1 * xz[base + (size_t)(l - 2) * (2 * DINNER)];
    if (l >= 1) acc += w2 * xz[base + (size_t)(l - 1) * (2 * DINNER)];
    acc += w3 * xz[base + (size_t)l * (2 * DINNER)];

    float v = silu_f(acc);
    xc[idx]  = v;
    xch[idx] = __float2half(v);
}

// ---------------- selective scan: cp.async chunked, smem-fed ---------------
#define LCH 64
#define NCHUNK (SEQLEN / LCH)   // 32

struct __align__(16) ScanSmem {
    float dt[2][LCH][8];
    float xc[2][LCH][8];
    float zz[2][LCH][8];
    float qq[2][LCH][8];
    float Bm[2][LCH][16];
    float Cm[2][LCH][16];
};

__global__ void __launch_bounds__(128)
scan_kernel(const float* __restrict__ xdbl, const float* __restrict__ dt,
            const float* __restrict__ xc,   const float* __restrict__ xz,
            const float* __restrict__ q,    const float* __restrict__ A_log,
            const float* __restrict__ Dvec, __half* __restrict__ yout)
{
    __shared__ ScanSmem sm;

    const int tid = threadIdx.x;
    const int grp = tid >> 4;          // 0..7   (channel within block)
    const int n   = tid & 15;          // state index
    const int ch0 = blockIdx.x * 8;
    const int b   = ch0 / DINNER;
    const int d0  = ch0 % DINNER;
    const int d   = d0 + grp;

    const float An = -__expf(A_log[d * DSTATE + n]);
    const float Dd = Dvec[d];

    const int row0 = b * SEQLEN;

    const int lA  = tid >> 1;          // 0..63
    const int hA  = (tid & 1) * 4;     // 0 or 4
    const int lB0 = tid >> 2;          // 0..31
    const int qB  = (tid & 3) * 4;     // 0,4,8,12

    auto stage = [&](int c, int s) {
        const int lbase = c * LCH;
        {
            const size_t r = (size_t)(row0 + lbase + lA);
            cp16(&sm.dt[s][lA][hA], &dt[r * DINNER + d0 + hA]);
            cp16(&sm.xc[s][lA][hA], &xc[r * DINNER + d0 + hA]);
            cp16(&sm.zz[s][lA][hA], &xz[r * (2 * DINNER) + DINNER + d0 + hA]);
            cp16(&sm.qq[s][lA][hA], &q [r * DINNER + d0 + hA]);
        }
#pragma unroll
        for (int k = 0; k < 2; k++) {
            const int l = lB0 + k * 32;
            const size_t r = (size_t)(row0 + lbase + l);
            cp16(&sm.Bm[s][l][qB], &xdbl[r * XDBL_W + DTRANK + qB]);
            cp16(&sm.Cm[s][l][qB], &xdbl[r * XDBL_W + DTRANK + DSTATE + qB]);
        }
        cp_commit();
    };

    float h = 0.0f;

    stage(0, 0);
    for (int c = 0; c < NCHUNK; c++) {
        const int s = c & 1;
        if (c + 1 < NCHUNK) {
            stage(c + 1, s ^ 1);
            asm volatile("cp.async.wait_group 1;" ::: "memory");
        } else {
            asm volatile("cp.async.wait_group 0;" ::: "memory");
        }
        __syncthreads();

#pragma unroll 4
        for (int l = 0; l < LCH; l++) {
            const float dtv = sm.dt[s][l][grp];
            const float xv  = sm.xc[s][l][grp];
            const float Bv  = sm.Bm[s][l][n];
            const float Cv  = sm.Cm[s][l][n];

            const float dA = __expf(dtv * An);
            h = fmaf(dA, h, dtv * xv * Bv);

            float p = h * Cv;
            p += __shfl_xor_sync(0xffffffffu, p, 8);
            p += __shfl_xor_sync(0xffffffffu, p, 4);
            p += __shfl_xor_sync(0xffffffffu, p, 2);
            p += __shfl_xor_sync(0xffffffffu, p, 1);

            if (n == 0) {
                float y  = p + xv * Dd;
                const float zv = sm.zz[s][l][grp];
                const float qv = sm.qq[s][l][grp];
                y = y * silu_f(zv) * silu_f(qv);
                yout[(size_t)(row0 + c * LCH + l) * DINNER + d] = __float2half(y);
            }
        }
        __syncthreads();
    }
}

// --------------------------------- host ------------------------------------
extern "C" void kernel_launch(void* const* d_in, const int* in_sizes, int n_in,
                              void* d_out, int out_size)
{
    const float* hs         = (const float*)d_in[0];
    const float* query      = (const float*)d_in[1];
    const float* in_proj_w  = (const float*)d_in[2];
    const float* conv_w     = (const float*)d_in[3];
    const float* conv_b     = (const float*)d_in[4];
    const float* x_proj_w   = (const float*)d_in[5];
    const float* dt_proj_w  = (const float*)d_in[6];
    const float* dt_proj_b  = (const float*)d_in[7];
    const float* A_log      = (const float*)d_in[8];
    const float* Dvec       = (const float*)d_in[9];
    const float* query_w    = (const float*)d_in[10];
    const float* query_b    = (const float*)d_in[11];
    const float* out_proj_w = (const float*)d_in[12];
    float* out = (float*)d_out;

    float  *p_xz, *p_q, *p_xc, *p_xdbl, *p_xdp, *p_dt;
    __half *p_hsh, *p_quh, *p_w1h, *p_w2h, *p_w3h, *p_w4h;
    __half *p_xpwh, *p_xch, *p_xdinh, *p_yh;
    cudaGetSymbolAddress((void**)&p_xz,    g_xz);
    cudaGetSymbolAddress((void**)&p_q,     g_q);
    cudaGetSymbolAddress((void**)&p_xc,    g_xc);
    cudaGetSymbolAddress((void**)&p_xdbl,  g_xdbl);
    cudaGetSymbolAddress((void**)&p_xdp,   g_xdp);
    cudaGetSymbolAddress((void**)&p_dt,    g_dt);
    cudaGetSymbolAddress((void**)&p_hsh,   g_hsh);
    cudaGetSymbolAddress((void**)&p_quh,   g_quh);
    cudaGetSymbolAddress((void**)&p_w1h,   g_w1h);
    cudaGetSymbolAddress((void**)&p_w2h,   g_w2h);
    cudaGetSymbolAddress((void**)&p_w3h,   g_w3h);
    cudaGetSymbolAddress((void**)&p_w4h,   g_w4h);
    cudaGetSymbolAddress((void**)&p_xpwh,  g_xpwh);
    cudaGetSymbolAddress((void**)&p_xch,   g_xch);
    cudaGetSymbolAddress((void**)&p_xdinh, g_xdinh);
    cudaGetSymbolAddress((void**)&p_yh,    g_yh);

    cudaFuncSetAttribute(gemm_hf<0>, cudaFuncAttributeMaxDynamicSharedMemorySize, HSMEM);
    cudaFuncSetAttribute(gemm_hf<1>, cudaFuncAttributeMaxDynamicSharedMemorySize, HSMEM);
    cudaFuncSetAttribute(gemm_hf<2>, cudaFuncAttributeMaxDynamicSharedMemorySize, HSMEM);

    auto toHalf = [](const float* in, __half* out, int n) {
        int n8 = n / 8;
        f2h_kernel<<<(n8 + 255) / 256, 256>>>(in, out, n8);
    };

    // launches 1-3: conversions; launch 4 = in_proj GEMM (ncu captures #4)
    toHalf(hs,        p_hsh, NTOK * DMODEL);          // 1
    toHalf(query,     p_quh, NTOK * DMODEL);          // 2
    toHalf(in_proj_w, p_w1h, 2 * DINNER * DMODEL);    // 3

    // 4) xz = hs @ in_proj_w^T  (4096 x 3072, K=768)
    gemm_hf<0><<<dim3(2 * DINNER / 128, NTOK / 128), 256, HSMEM>>>(
        p_hsh, p_w1h, nullptr, p_xz, DMODEL, DMODEL, DMODEL, 2 * DINNER);

    // 5-6) q = query @ query_w^T + query_b  (4096 x 1536, K=768)
    toHalf(query_w, p_w2h, DINNER * DMODEL);
    gemm_hf<1><<<dim3(DINNER / 128, NTOK / 128), 256, HSMEM>>>(
        p_quh, p_w2h, query_b, p_q, DMODEL, DMODEL, DMODEL, DINNER);

    // 7) causal depthwise conv + silu (fp32 + fp16 outputs)
    {
        int total = NTOK * DINNER;
        conv_silu_kernel<<<(total + 255) / 256, 256>>>(
            p_xz, conv_w, conv_b, p_xc, p_xch);
    }

    // 8-10) x_dbl = xc @ x_proj_w^T  (4096 x 80->128, K=1536, split-K=4 HMMA)
    pad_xw_kernel<<<(XPN * DINNER + 255) / 256, 256>>>(x_proj_w, p_xpwh);
    gemm_hf<0><<<dim3(1, NTOK / 128, XPSPLIT), 256, HSMEM>>>(
        p_xch, p_xpwh, nullptr, p_xdp, DINNER / XPSPLIT, DINNER, DINNER, XPN);
    reduce_xdbl_kernel<<<(NTOK * XDBL_W + 255) / 256, 256>>>(p_xdp, p_xdbl, p_xdinh);

    // 11-12) dt = softplus(xdin @ w4^T + dt_proj_b)  (K=64 padded, fp16)
    pad_w4_kernel<<<(DINNER * DTK + 255) / 256, 256>>>(dt_proj_w, p_w4h);
    gemm_hf<2><<<dim3(DINNER / 128, NTOK / 128), 256, HSMEM>>>(
        p_xdinh, p_w4h, dt_proj_b, p_dt, DTK, DTK, DTK, DINNER);

    // 13) selective scan + D skip + silu(z) + silu(q) gating -> fp16 y
    scan_kernel<<<NBATCH * DINNER / 8, 128>>>(
        p_xdbl, p_dt, p_xc, p_xz, p_q, A_log, Dvec, p_yh);

    // 14-15) out = y @ out_proj_w^T  (4096 x 768, K=1536)
    toHalf(out_proj_w, p_w3h, DMODEL * DINNER);
    gemm_hf<0><<<dim3(DMODEL / 128, NTOK / 128), 256, HSMEM>>>(
        p_yh, p_w3h, nullptr, out, DINNER, DINNER, DINNER, DMODEL);
}

// round 13
// speedup vs baseline: 10.3370x; 1.8608x over previous
#include <cuda_runtime.h>
#include <cuda_fp16.h>
#include <cstdint>

// Problem constants
#define DMODEL   768
#define DSTATE   16
#define DCONV    4
#define DINNER   1536
#define DTRANK   48
#define NBATCH   2
#define SEQLEN   2048
#define NTOK     (NBATCH * SEQLEN)        // 4096
#define XDBL_W   (DTRANK + 2 * DSTATE)    // 80
#define XPN      128                       // padded N for x_proj gemm
#define XPSPLIT  4                         // split-K for x_proj gemm
#define DTK      64                        // padded K for dt gemm
#define NCHAN    (NBATCH * DINNER)         // 3072 scan channels
#define CH_T     128                       // timesteps per scan chunk
#define NCH      (SEQLEN / CH_T)           // 16 chunks
#define SUB      64                        // staging sub-chunk

// -------- scratch (static device globals; no runtime allocation) ----------
__device__ float  g_xz   [NTOK * 2 * DINNER];
__device__ float  g_gate [NTOK * DINNER];          // silu(q)*silu(z)
__device__ float  g_xc   [NTOK * DINNER];
__device__ float  g_xdbl [NTOK * XDBL_W];
__device__ float  g_xdp  [XPSPLIT * NTOK * XPN];   // x_proj split-K partials
__device__ float  g_dt   [NTOK * DINNER];
__device__ float  g_scA  [NCH * NCHAN * DSTATE];   // per-chunk prod(a)
__device__ float  g_scB  [NCH * NCHAN * DSTATE];   // per-chunk local state
__device__ float  g_hst  [NCH * NCHAN * DSTATE];   // chunk-start states
// fp16 GEMM operands
__device__ __half g_hsh  [NTOK * DMODEL];
__device__ __half g_quh  [NTOK * DMODEL];
__device__ __half g_w1h  [2 * DINNER * DMODEL];
__device__ __half g_w2h  [DINNER * DMODEL];
__device__ __half g_w3h  [DMODEL * DINNER];
__device__ __half g_w4h  [DINNER * DTK];
__device__ __half g_xpwh [XPN * DINNER];           // padded x_proj weights
__device__ __half g_xch  [NTOK * DINNER];          // fp16 conv output
__device__ __half g_xdinh[NTOK * DTK];
__device__ __half g_yh   [NTOK * DINNER];

// -------------------------- helpers ---------------------------------------
__device__ __forceinline__ float silu_f(float x) {
    return x / (1.0f + __expf(-x));
}
__device__ __forceinline__ float softplus_f(float x) {
    return (x > 20.0f) ? x : log1pf(__expf(x));
}
__device__ __forceinline__ void cp16(void* s, const void* g) {
    uint32_t sa = (uint32_t)__cvta_generic_to_shared(s);
    asm volatile("cp.async.ca.shared.global [%0], [%1], 16;" :: "r"(sa), "l"(g));
}
__device__ __forceinline__ void cp16s(uint32_t saddr, const void* g) {
    asm volatile("cp.async.ca.shared.global [%0], [%1], 16;" :: "r"(saddr), "l"(g));
}
__device__ __forceinline__ void cp_commit() {
    asm volatile("cp.async.commit_group;" ::: "memory");
}
__device__ __forceinline__ void ldsm_x4(uint32_t* r, uint32_t addr) {
    asm volatile("ldmatrix.sync.aligned.m8n8.x4.shared.b16 {%0,%1,%2,%3}, [%4];"
                 : "=r"(r[0]), "=r"(r[1]), "=r"(r[2]), "=r"(r[3]) : "r"(addr));
}
__device__ __forceinline__ void mma_f16(float* d, const uint32_t* a, const uint32_t* b) {
    asm volatile(
        "mma.sync.aligned.m16n8k16.row.col.f32.f16.f16.f32 "
        "{%0,%1,%2,%3}, {%4,%5,%6,%7}, {%8,%9}, {%0,%1,%2,%3};\n"
        : "+f"(d[0]), "+f"(d[1]), "+f"(d[2]), "+f"(d[3])
        : "r"(a[0]), "r"(a[1]), "r"(a[2]), "r"(a[3]), "r"(b[0]), "r"(b[1]));
}

// ---------------- fused fp32 -> fp16 conversion (up to 3 arrays) -----------
__device__ __forceinline__ void f2h8(const float* in, __half* out, int j) {
    float4 v0 = ((const float4*)in)[2 * j];
    float4 v1 = ((const float4*)in)[2 * j + 1];
    __half2 hp[4];
    hp[0] = __floats2half2_rn(v0.x, v0.y);
    hp[1] = __floats2half2_rn(v0.z, v0.w);
    hp[2] = __floats2half2_rn(v1.x, v1.y);
    hp[3] = __floats2half2_rn(v1.z, v1.w);
    ((uint4*)out)[j] = *(const uint4*)hp;
}

__global__ void f2h3_kernel(const float* i0, __half* o0, int n0,
                            const float* i1, __half* o1, int n1,
                            const float* i2, __half* o2, int n2)
{
    int i = blockIdx.x * blockDim.x + threadIdx.x;
    if (i < n0)                 f2h8(i0, o0, i);
    else if (i < n0 + n1)       f2h8(i1, o1, i - n0);
    else if (i < n0 + n1 + n2)  f2h8(i2, o2, i - n0 - n1);
}

// fused pads: dt weights [1536,48]->[1536,64], x_proj weights [80,1536]->[128,1536]
__global__ void padcomb_kernel(const float* w4, __half* ow4,
                               const float* xw, __half* oxw)
{
    int i = blockIdx.x * blockDim.x + threadIdx.x;
    if (i < DINNER * DTK) {
        int row = i >> 6, col = i & 63;
        ow4[i] = (col < DTRANK) ? __float2half(w4[row * DTRANK + col])
                                : __float2half(0.0f);
    } else {
        int k = i - DINNER * DTK;
        if (k < XPN * DINNER) {
            int row = k / DINNER;
            oxw[k] = (row < XDBL_W) ? __float2half(xw[k]) : __float2half(0.0f);
        }
    }
}

// ================= fp16 tensor-core GEMM: C = A * W^T + epi ================
// A: [M,K_total] half (lda), W: [N,K_total] half (ldw), C fp32 (ldc)
// CTA 128x128, BK=32, 8 warps, 4-stage cp.async, 1 sync/iter.
// EPI: 0 none; 1 +bias; 2 +bias,softplus; 3 silu(v+bias)*silu(Z[row][col])
#define HBK   32
#define HSTR  40
#define HAST  (128 * HSTR * 2)
#define HSTG  (2 * HAST)
#define HNST  4
#define HSMEM (HNST * HSTG)

template<int EPI>
__global__ void __launch_bounds__(256, 2)
gemm_hf(const __half* __restrict__ A, const __half* __restrict__ W,
        const float* __restrict__ bias, const float* __restrict__ Z,
        float* __restrict__ C,
        int K, int lda, int ldw, int ldz, int ldc)
{
    extern __shared__ char dynsmem[];
    const uint32_t sb = (uint32_t)__cvta_generic_to_shared(dynsmem);

    const int tid  = threadIdx.x;
    const int m0   = blockIdx.y * 128;
    const int n0   = blockIdx.x * 128;
    const int koff = blockIdx.z * K;
    const int warp = tid >> 5;
    const int lane = tid & 31;
    const int g    = lane >> 2;
    const int t    = lane & 3;
    const int wm   = (warp & 1) * 64;
    const int wn   = (warp >> 1) * 32;

    const int u   = lane & 7;
    const int grp = lane >> 3;

    uint32_t aA[4];
#pragma unroll
    for (int mt = 0; mt < 4; mt++) {
        int row  = wm + mt * 16 + (grp & 1) * 8 + u;
        int kofh = (grp >> 1) * 8;
        aA[mt] = (uint32_t)(row * HSTR + kofh) * 2u;
    }
    uint32_t aB[2];
#pragma unroll
    for (int p = 0; p < 2; p++) {
        int row  = wn + (2 * p + (grp >> 1)) * 8 + u;
        int kofh = (grp & 1) * 8;
        aB[p] = (uint32_t)HAST + (uint32_t)(row * HSTR + kofh) * 2u;
    }

    const int lr = tid >> 2;
    const int lc = (tid & 3) * 8;
    const int niter = K / HBK;

    const __half* Abase = A + (size_t)(m0 + lr) * lda + koff + lc;
    const __half* Wbase = W + (size_t)(n0 + lr) * ldw + koff + lc;
    const uint32_t dA0 = sb + (uint32_t)(lr * HSTR + lc) * 2u;
    const uint32_t dA1 = sb + (uint32_t)((lr + 64) * HSTR + lc) * 2u;
    const uint32_t dW0 = dA0 + HAST;
    const uint32_t dW1 = dA1 + HAST;

    auto stage_load = [&](int s, int kb) {
        const uint32_t so = (uint32_t)s * HSTG;
        const int k0 = kb * HBK;
        cp16s(dA0 + so, Abase + k0);
        cp16s(dA1 + so, Abase + k0 + (size_t)64 * lda);
        cp16s(dW0 + so, Wbase + k0);
        cp16s(dW1 + so, Wbase + k0 + (size_t)64 * ldw);
    };

    float acc[4][4][4];
#pragma unroll
    for (int mt = 0; mt < 4; mt++)
#pragma unroll
        for (int nt = 0; nt < 4; nt++)
#pragma unroll
            for (int i = 0; i < 4; i++) acc[mt][nt][i] = 0.0f;

#pragma unroll
    for (int s = 0; s < HNST - 1; s++) {
        if (s < niter) stage_load(s, s);
        cp_commit();
    }

    for (int it = 0; it < niter; it++) {
        asm volatile("cp.async.wait_group %0;" :: "n"(HNST - 2) : "memory");
        __syncthreads();

        const int pf = it + HNST - 1;
        if (pf < niter) stage_load(pf % HNST, pf);
        cp_commit();

        const uint32_t sOff = sb + (uint32_t)(it % HNST) * HSTG;
#pragma unroll
        for (int kk = 0; kk < 2; kk++) {
            const uint32_t kOff = sOff + (uint32_t)kk * 32u;
            uint32_t afr[4][4];
            uint32_t bfr[4][2];
#pragma unroll
            for (int mt = 0; mt < 4; mt++)
                ldsm_x4(afr[mt], aA[mt] + kOff);
            {
                uint32_t r[4];
                ldsm_x4(r, aB[0] + kOff);
                bfr[0][0] = r[0]; bfr[0][1] = r[1];
                bfr[1][0] = r[2]; bfr[1][1] = r[3];
                ldsm_x4(r, aB[1] + kOff);
                bfr[2][0] = r[0]; bfr[2][1] = r[1];
                bfr[3][0] = r[2]; bfr[3][1] = r[3];
            }
#pragma unroll
            for (int mt = 0; mt < 4; mt++)
#pragma unroll
                for (int nt = 0; nt < 4; nt++)
                    mma_f16(acc[mt][nt], afr[mt], bfr[nt]);
        }
    }

    float* Cz = C + (size_t)blockIdx.z * NTOK * ldc;
#pragma unroll
    for (int mt = 0; mt < 4; mt++) {
#pragma unroll
        for (int nt = 0; nt < 4; nt++) {
            const int row = m0 + wm + mt * 16 + g;
            const int col = n0 + wn + nt * 8 + 2 * t;
            float v0 = acc[mt][nt][0];
            float v1 = acc[mt][nt][1];
            float v2 = acc[mt][nt][2];
            float v3 = acc[mt][nt][3];
            if (EPI >= 1) {
                const float b0 = bias[col];
                const float b1 = bias[col + 1];
                v0 += b0; v1 += b1; v2 += b0; v3 += b1;
            }
            if (EPI == 2) {
                v0 = softplus_f(v0); v1 = softplus_f(v1);
                v2 = softplus_f(v2); v3 = softplus_f(v3);
            }
            if (EPI == 3) {
                const float z0 = Z[(size_t)row * ldz + col];
                const float z1 = Z[(size_t)row * ldz + col + 1];
                const float z2 = Z[(size_t)(row + 8) * ldz + col];
                const float z3 = Z[(size_t)(row + 8) * ldz + col + 1];
                v0 = silu_f(v0) * silu_f(z0);
                v1 = silu_f(v1) * silu_f(z1);
                v2 = silu_f(v2) * silu_f(z2);
                v3 = silu_f(v3) * silu_f(z3);
            }
            float2* p0 = (float2*)&Cz[(size_t)row * ldc + col];
            float2* p1 = (float2*)&Cz[(size_t)(row + 8) * ldc + col];
            *p0 = make_float2(v0, v1);
            *p1 = make_float2(v2, v3);
        }
    }
}

// reduce x_proj split-K partials; emit xdbl fp32 + padded fp16 dt-gemm input
__global__ void reduce_xdbl_kernel(const float* __restrict__ part,
                                   float* __restrict__ out,
                                   __half* __restrict__ outp)
{
    int i = blockIdx.x * 256 + threadIdx.x;
    if (i < NTOK * XDBL_W) {
        int row = i / XDBL_W, col = i % XDBL_W;
        float s = 0.0f;
#pragma unroll
        for (int z = 0; z < XPSPLIT; z++)
            s += part[(size_t)z * NTOK * XPN + (size_t)row * XPN + col];
        out[i] = s;
        if (col < DTRANK)   outp[row * DTK + col] = __float2half(s);
        else if (col < DTK) outp[row * DTK + col] = __float2half(0.0f);
    }
}

// ------------- causal depthwise conv (4 taps) + silu (fp32 + fp16) ---------
__global__ void conv_silu_kernel(const float* __restrict__ xz,
                                 const float* __restrict__ conv_w,
                                 const float* __restrict__ conv_b,
                                 float* __restrict__ xc,
                                 __half* __restrict__ xch)
{
    int idx = blockIdx.x * blockDim.x + threadIdx.x;
    if (idx >= NTOK * DINNER) return;
    int d   = idx % DINNER;
    int row = idx / DINNER;
    int l   = row & (SEQLEN - 1);
    int b   = row >> 11;

    float w0 = conv_w[d * DCONV + 0];
    float w1 = conv_w[d * DCONV + 1];
    float w2 = conv_w[d * DCONV + 2];
    float w3 = conv_w[d * DCONV + 3];

    float acc = conv_b[d];
    const size_t base = ((size_t)b * SEQLEN) * (2 * DINNER) + d;
    if (l >= 3) acc += w0 * xz[base + (size_t)(l - 3) * (2 * DINNER)];
    if (l >= 2) acc += w1 * xz[base + (size_t)(l - 2) * (2 * DINNER)];
    if (l >= 1) acc += w2 * xz[base + (size_t)(l - 1) * (2 * DINNER)];
    acc += w3 * xz[base + (size_t)l * (2 * DINNER)];

    float v = silu_f(acc);
    xc[idx]  = v;
    xch[idx] = __float2half(v);
}

// ============== chunked selective scan: 3 phases ===========================
// Phase A: per (chunk, channel, state): prod(a) and local scan end-state.
// Phase B: sequential composition over chunks -> chunk-start states.
// Phase C: per-chunk real scan with y output (gated).

struct ScanASmem {
    float dt[2][SUB][8];
    float xc[2][SUB][8];
    float Bm[2][SUB][16];
};

__global__ void __launch_bounds__(128)
scanA_kernel(const float* __restrict__ dt, const float* __restrict__ xc,
             const float* __restrict__ xdbl, const float* __restrict__ A_log,
             float* __restrict__ gA, float* __restrict__ gB)
{
    __shared__ ScanASmem sm;
    const int tid = threadIdx.x;
    const int grp = tid >> 4;
    const int n   = tid & 15;
    const int ch0 = blockIdx.x * 8;
    const int c   = blockIdx.y;
    const int ch  = ch0 + grp;
    const int b   = ch0 / DINNER;
    const int d0  = ch0 % DINNER;
    const int d   = d0 + grp;

    const float An = -__expf(A_log[d * DSTATE + n]);
    const int row0 = b * SEQLEN + c * CH_T;

    const int lA  = tid >> 1;
    const int hA  = (tid & 1) * 4;
    const int lB0 = tid >> 2;
    const int qB  = (tid & 3) * 4;

    auto stage = [&](int sc, int s) {
        const int lbase = sc * SUB;
        {
            const size_t r = (size_t)(row0 + lbase + lA);
            cp16(&sm.dt[s][lA][hA], &dt[r * DINNER + d0 + hA]);
            cp16(&sm.xc[s][lA][hA], &xc[r * DINNER + d0 + hA]);
        }
#pragma unroll
        for (int k = 0; k < 2; k++) {
            const int l = lB0 + k * 32;
            const size_t r = (size_t)(row0 + lbase + l);
            cp16(&sm.Bm[s][l][qB], &xdbl[r * XDBL_W + DTRANK + qB]);
        }
        cp_commit();
    };

    float Ap = 1.0f, hB = 0.0f;

    stage(0, 0);
    for (int sc = 0; sc < CH_T / SUB; sc++) {
        const int s = sc & 1;
        if (sc + 1 < CH_T / SUB) {
            stage(sc + 1, s ^ 1);
            asm volatile("cp.async.wait_group 1;" ::: "memory");
        } else {
            asm volatile("cp.async.wait_group 0;" ::: "memory");
        }
        __syncthreads();

#pragma unroll 4
        for (int l = 0; l < SUB; l++) {
            const float dtv = sm.dt[s][l][grp];
            const float xv  = sm.xc[s][l][grp];
            const float Bv  = sm.Bm[s][l][n];
            const float a   = __expf(dtv * An);
            hB = fmaf(a, hB, dtv * xv * Bv);
            Ap *= a;
        }
        __syncthreads();
    }

    const size_t o = ((size_t)c * NCHAN + ch) * DSTATE + n;
    gA[o] = Ap;
    gB[o] = hB;
}

__global__ void scanB_kernel(const float* __restrict__ gA,
                             const float* __restrict__ gB,
                             float* __restrict__ hst)
{
    int idx = blockIdx.x * 256 + threadIdx.x;
    if (idx >= NCHAN * DSTATE) return;
    float h = 0.0f;
#pragma unroll
    for (int c = 0; c < NCH; c++) {
        const size_t o = (size_t)c * (NCHAN * DSTATE) + idx;
        hst[o] = h;
        h = fmaf(gA[o], h, gB[o]);
    }
}

struct ScanCSmem {
    float dt[2][SUB][8];
    float xc[2][SUB][8];
    float gt[2][SUB][8];
    float Bm[2][SUB][16];
    float Cm[2][SUB][16];
};

__global__ void __launch_bounds__(128)
scanC_kernel(const float* __restrict__ xdbl, const float* __restrict__ dt,
             const float* __restrict__ xc,   const float* __restrict__ gate,
             const float* __restrict__ A_log, const float* __restrict__ Dvec,
             const float* __restrict__ hst,  __half* __restrict__ yout)
{
    __shared__ ScanCSmem sm;
    const int tid = threadIdx.x;
    const int grp = tid >> 4;
    const int n   = tid & 15;
    const int ch0 = blockIdx.x * 8;
    const int c   = blockIdx.y;
    const int ch  = ch0 + grp;
    const int b   = ch0 / DINNER;
    const int d0  = ch0 % DINNER;
    const int d   = d0 + grp;

    const float An = -__expf(A_log[d * DSTATE + n]);
    const float Dd = Dvec[d];
    const int row0 = b * SEQLEN + c * CH_T;

    const int lA  = tid >> 1;
    const int hA  = (tid & 1) * 4;
    const int lB0 = tid >> 2;
    const int qB  = (tid & 3) * 4;

    auto stage = [&](int sc, int s) {
        const int lbase = sc * SUB;
        {
            const size_t r = (size_t)(row0 + lbase + lA);
            cp16(&sm.dt[s][lA][hA], &dt  [r * DINNER + d0 + hA]);
            cp16(&sm.xc[s][lA][hA], &xc  [r * DINNER + d0 + hA]);
            cp16(&sm.gt[s][lA][hA], &gate[r * DINNER + d0 + hA]);
        }
#pragma unroll
        for (int k = 0; k < 2; k++) {
            const int l = lB0 + k * 32;
            const size_t r = (size_t)(row0 + lbase + l);
            cp16(&sm.Bm[s][l][qB], &xdbl[r * XDBL_W + DTRANK + qB]);
            cp16(&sm.Cm[s][l][qB], &xdbl[r * XDBL_W + DTRANK + DSTATE + qB]);
        }
        cp_commit();
    };

    float h = hst[((size_t)c * NCHAN + ch) * DSTATE + n];

    stage(0, 0);
    for (int sc = 0; sc < CH_T / SUB; sc++) {
        const int s = sc & 1;
        if (sc + 1 < CH_T / SUB) {
            stage(sc + 1, s ^ 1);
            asm volatile("cp.async.wait_group 1;" ::: "memory");
        } else {
            asm volatile("cp.async.wait_group 0;" ::: "memory");
        }
        __syncthreads();

#pragma unroll 4
        for (int l = 0; l < SUB; l++) {
            const float dtv = sm.dt[s][l][grp];
            const float xv  = sm.xc[s][l][grp];
            const float Bv  = sm.Bm[s][l][n];
            const float Cv  = sm.Cm[s][l][n];

            const float dA = __expf(dtv * An);
            h = fmaf(dA, h, dtv * xv * Bv);

            float p = h * Cv;
            p += __shfl_xor_sync(0xffffffffu, p, 8);
            p += __shfl_xor_sync(0xffffffffu, p, 4);
            p += __shfl_xor_sync(0xffffffffu, p, 2);
            p += __shfl_xor_sync(0xffffffffu, p, 1);

            if (n == 0) {
                const float y = (p + xv * Dd) * sm.gt[s][l][grp];
                yout[(size_t)(row0 + sc * SUB + l) * DINNER + d] = __float2half(y);
            }
        }
        __syncthreads();
    }
}

// --------------------------------- host ------------------------------------
extern "C" void kernel_launch(void* const* d_in, const int* in_sizes, int n_in,
                              void* d_out, int out_size)
{
    const float* hs         = (const float*)d_in[0];
    const float* query      = (const float*)d_in[1];
    const float* in_proj_w  = (const float*)d_in[2];
    const float* conv_w     = (const float*)d_in[3];
    const float* conv_b     = (const float*)d_in[4];
    const float* x_proj_w   = (const float*)d_in[5];
    const float* dt_proj_w  = (const float*)d_in[6];
    const float* dt_proj_b  = (const float*)d_in[7];
    const float* A_log      = (const float*)d_in[8];
    const float* Dvec       = (const float*)d_in[9];
    const float* query_w    = (const float*)d_in[10];
    const float* query_b    = (const float*)d_in[11];
    const float* out_proj_w = (const float*)d_in[12];
    float* out = (float*)d_out;

    float  *p_xz, *p_gate, *p_xc, *p_xdbl, *p_xdp, *p_dt, *p_scA, *p_scB, *p_hst;
    __half *p_hsh, *p_quh, *p_w1h, *p_w2h, *p_w3h, *p_w4h;
    __half *p_xpwh, *p_xch, *p_xdinh, *p_yh;
    cudaGetSymbolAddress((void**)&p_xz,    g_xz);
    cudaGetSymbolAddress((void**)&p_gate,  g_gate);
    cudaGetSymbolAddress((void**)&p_xc,    g_xc);
    cudaGetSymbolAddress((void**)&p_xdbl,  g_xdbl);
    cudaGetSymbolAddress((void**)&p_xdp,   g_xdp);
    cudaGetSymbolAddress((void**)&p_dt,    g_dt);
    cudaGetSymbolAddress((void**)&p_scA,   g_scA);
    cudaGetSymbolAddress((void**)&p_scB,   g_scB);
    cudaGetSymbolAddress((void**)&p_hst,   g_hst);
    cudaGetSymbolAddress((void**)&p_hsh,   g_hsh);
    cudaGetSymbolAddress((void**)&p_quh,   g_quh);
    cudaGetSymbolAddress((void**)&p_w1h,   g_w1h);
    cudaGetSymbolAddress((void**)&p_w2h,   g_w2h);
    cudaGetSymbolAddress((void**)&p_w3h,   g_w3h);
    cudaGetSymbolAddress((void**)&p_w4h,   g_w4h);
    cudaGetSymbolAddress((void**)&p_xpwh,  g_xpwh);
    cudaGetSymbolAddress((void**)&p_xch,   g_xch);
    cudaGetSymbolAddress((void**)&p_xdinh, g_xdinh);
    cudaGetSymbolAddress((void**)&p_yh,    g_yh);

    cudaFuncSetAttribute(gemm_hf<0>, cudaFuncAttributeMaxDynamicSharedMemorySize, HSMEM);
    cudaFuncSetAttribute(gemm_hf<2>, cudaFuncAttributeMaxDynamicSharedMemorySize, HSMEM);
    cudaFuncSetAttribute(gemm_hf<3>, cudaFuncAttributeMaxDynamicSharedMemorySize, HSMEM);

    // 1) fused conversions: hs, query, in_proj_w
    {
        int n0 = NTOK * DMODEL / 8;          // hs
        int n1 = NTOK * DMODEL / 8;          // query
        int n2 = 2 * DINNER * DMODEL / 8;    // in_proj_w
        int tot = n0 + n1 + n2;
        f2h3_kernel<<<(tot + 255) / 256, 256>>>(hs, p_hsh, n0,
                                                query, p_quh, n1,
                                                in_proj_w, p_w1h, n2);
    }
    // 2) fused conversions: query_w, out_proj_w
    {
        int n0 = DINNER * DMODEL / 8;
        int n1 = DMODEL * DINNER / 8;
        int tot = n0 + n1;
        f2h3_kernel<<<(tot + 255) / 256, 256>>>(query_w, p_w2h, n0,
                                                out_proj_w, p_w3h, n1,
                                                nullptr, nullptr, 0);
    }
    // 3) fused pads: dt weights + x_proj weights
    {
        int tot = DINNER * DTK + XPN * DINNER;
        padcomb_kernel<<<(tot + 255) / 256, 256>>>(dt_proj_w, p_w4h,
                                                   x_proj_w, p_xpwh);
    }

    // 4) xz = hs @ in_proj_w^T  (4096 x 3072, K=768)   [ncu captures this]
    gemm_hf<0><<<dim3(2 * DINNER / 128, NTOK / 128), 256, HSMEM>>>(
        p_hsh, p_w1h, nullptr, nullptr, p_xz, DMODEL, DMODEL, DMODEL, 0, 2 * DINNER);

    // 5) gate = silu(query @ query_w^T + b) * silu(z)  (4096 x 1536)
    gemm_hf<3><<<dim3(DINNER / 128, NTOK / 128), 256, HSMEM>>>(
        p_quh, p_w2h, query_b, p_xz + DINNER, p_gate,
        DMODEL, DMODEL, DMODEL, 2 * DINNER, DINNER);

    // 6) causal depthwise conv + silu (fp32 + fp16 outputs)
    {
        int total = NTOK * DINNER;
        conv_silu_kernel<<<(total + 255) / 256, 256>>>(
            p_xz, conv_w, conv_b, p_xc, p_xch);
    }

    // 7) x_dbl partials = xc @ x_proj_w^T (padded N=128, split-K=4)
    gemm_hf<0><<<dim3(1, NTOK / 128, XPSPLIT), 256, HSMEM>>>(
        p_xch, p_xpwh, nullptr, nullptr, p_xdp,
        DINNER / XPSPLIT, DINNER, DINNER, 0, XPN);

    // 8) reduce partials -> xdbl fp32 + padded fp16 dt input
    reduce_xdbl_kernel<<<(NTOK * XDBL_W + 255) / 256, 256>>>(p_xdp, p_xdbl, p_xdinh);

    // 9) dt = softplus(xdin @ w4^T + dt_proj_b)  (K=64 padded)
    gemm_hf<2><<<dim3(DINNER / 128, NTOK / 128), 256, HSMEM>>>(
        p_xdinh, p_w4h, dt_proj_b, nullptr, p_dt, DTK, DTK, DTK, 0, DINNER);

    // 10-12) chunked selective scan
    scanA_kernel<<<dim3(NCHAN / 8, NCH), 128>>>(
        p_dt, p_xc, p_xdbl, A_log, p_scA, p_scB);
    scanB_kernel<<<(NCHAN * DSTATE + 255) / 256, 256>>>(p_scA, p_scB, p_hst);
    scanC_kernel<<<dim3(NCHAN / 8, NCH), 128>>>(
        p_xdbl, p_dt, p_xc, p_gate, A_log, Dvec, p_hst, p_yh);

    // 13) out = y @ out_proj_w^T  (4096 x 768, K=1536)
    gemm_hf<0><<<dim3(DMODEL / 128, NTOK / 128), 256, HSMEM>>>(
        p_yh, p_w3h, nullptr, nullptr, out, DINNER, DINNER, DINNER, 0, DMODEL);
}

// round 14
// speedup vs baseline: 10.8907x; 1.0536x over previous
#include <cuda_runtime.h>
#include <cuda_fp16.h>
#include <cstdint>

// Problem constants
#define DMODEL   768
#define DSTATE   16
#define DCONV    4
#define DINNER   1536
#define DTRANK   48
#define NBATCH   2
#define SEQLEN   2048
#define NTOK     (NBATCH * SEQLEN)        // 4096
#define XDBL_W   (DTRANK + 2 * DSTATE)    // 80
#define XPN      128                       // padded N for x_proj gemm
#define XPSPLIT  4                         // split-K for x_proj gemm
#define DTK      64                        // padded K for dt gemm
#define NCHAN    (NBATCH * DINNER)         // 3072 scan channels
#define CH_T     128                       // timesteps per scan chunk
#define NCH      (SEQLEN / CH_T)           // 16 chunks
#define SUB      32                        // staging sub-chunk

// -------- scratch (static device globals; no runtime allocation) ----------
__device__ float  g_xz   [NTOK * 2 * DINNER];
__device__ float  g_gate [NTOK * DINNER];          // silu(q)*silu(z)
__device__ float  g_xc   [NTOK * DINNER];
__device__ float  g_xdbl [NTOK * XDBL_W];
__device__ float  g_xdp  [XPSPLIT * NTOK * XPN];   // x_proj split-K partials
__device__ float  g_dt   [NTOK * DINNER];
__device__ float  g_scA  [NCH * NCHAN * DSTATE];   // per-chunk prod(a)
__device__ float  g_scB  [NCH * NCHAN * DSTATE];   // per-chunk local state
__device__ float  g_hst  [NCH * NCHAN * DSTATE];   // chunk-start states
// fp16 GEMM operands
__device__ __half g_hsh  [NTOK * DMODEL];
__device__ __half g_quh  [NTOK * DMODEL];
__device__ __half g_w1h  [2 * DINNER * DMODEL];
__device__ __half g_w2h  [DINNER * DMODEL];
__device__ __half g_w3h  [DMODEL * DINNER];
__device__ __half g_w4h  [DINNER * DTK];
__device__ __half g_xpwh [XPN * DINNER];           // padded x_proj weights
__device__ __half g_xch  [NTOK * DINNER];          // fp16 conv output
__device__ __half g_xdinh[NTOK * DTK];
__device__ __half g_yh   [NTOK * DINNER];

// -------------------------- helpers ---------------------------------------
__device__ __forceinline__ float silu_f(float x) {
    return x / (1.0f + __expf(-x));
}
__device__ __forceinline__ float softplus_f(float x) {
    return (x > 20.0f) ? x : log1pf(__expf(x));
}
__device__ __forceinline__ void cp16(void* s, const void* g) {
    uint32_t sa = (uint32_t)__cvta_generic_to_shared(s);
    asm volatile("cp.async.ca.shared.global [%0], [%1], 16;" :: "r"(sa), "l"(g));
}
__device__ __forceinline__ void cp16s(uint32_t saddr, const void* g) {
    asm volatile("cp.async.ca.shared.global [%0], [%1], 16;" :: "r"(saddr), "l"(g));
}
__device__ __forceinline__ void cp_commit() {
    asm volatile("cp.async.commit_group;" ::: "memory");
}
__device__ __forceinline__ void ldsm_x4(uint32_t* r, uint32_t addr) {
    asm volatile("ldmatrix.sync.aligned.m8n8.x4.shared.b16 {%0,%1,%2,%3}, [%4];"
                 : "=r"(r[0]), "=r"(r[1]), "=r"(r[2]), "=r"(r[3]) : "r"(addr));
}
__device__ __forceinline__ void mma_f16(float* d, const uint32_t* a, const uint32_t* b) {
    asm volatile(
        "mma.sync.aligned.m16n8k16.row.col.f32.f16.f16.f32 "
        "{%0,%1,%2,%3}, {%4,%5,%6,%7}, {%8,%9}, {%0,%1,%2,%3};\n"
        : "+f"(d[0]), "+f"(d[1]), "+f"(d[2]), "+f"(d[3])
        : "r"(a[0]), "r"(a[1]), "r"(a[2]), "r"(a[3]), "r"(b[0]), "r"(b[1]));
}

// ---------------- fused fp32 -> fp16 conversion (up to 3 arrays) -----------
__device__ __forceinline__ void f2h8(const float* in, __half* out, int j) {
    float4 v0 = ((const float4*)in)[2 * j];
    float4 v1 = ((const float4*)in)[2 * j + 1];
    __half2 hp[4];
    hp[0] = __floats2half2_rn(v0.x, v0.y);
    hp[1] = __floats2half2_rn(v0.z, v0.w);
    hp[2] = __floats2half2_rn(v1.x, v1.y);
    hp[3] = __floats2half2_rn(v1.z, v1.w);
    ((uint4*)out)[j] = *(const uint4*)hp;
}

__global__ void f2h3_kernel(const float* i0, __half* o0, int n0,
                            const float* i1, __half* o1, int n1,
                            const float* i2, __half* o2, int n2)
{
    int i = blockIdx.x * blockDim.x + threadIdx.x;
    if (i < n0)                 f2h8(i0, o0, i);
    else if (i < n0 + n1)       f2h8(i1, o1, i - n0);
    else if (i < n0 + n1 + n2)  f2h8(i2, o2, i - n0 - n1);
}

// fused pads: dt weights [1536,48]->[1536,64], x_proj weights [80,1536]->[128,1536]
__global__ void padcomb_kernel(const float* w4, __half* ow4,
                               const float* xw, __half* oxw)
{
    int i = blockIdx.x * blockDim.x + threadIdx.x;
    if (i < DINNER * DTK) {
        int row = i >> 6, col = i & 63;
        ow4[i] = (col < DTRANK) ? __float2half(w4[row * DTRANK + col])
                                : __float2half(0.0f);
    } else {
        int k = i - DINNER * DTK;
        if (k < XPN * DINNER) {
            int row = k / DINNER;
            oxw[k] = (row < XDBL_W) ? __float2half(xw[k]) : __float2half(0.0f);
        }
    }
}

// ================= fp16 tensor-core GEMM: C = A * W^T + epi ================
// A: [M,K_total] half (lda), W: [N,K_total] half (ldw), C fp32 (ldc)
// CTA 128x128, BK=32, 4 warps (2x2 of 64x64), 4-stage cp.async, 1 sync/iter.
// EPI: 0 none; 1 +bias; 2 +bias,softplus; 3 silu(v+bias)*silu(Z[row][col])
#define HBK   32
#define HSTR  40
#define HAST  (128 * HSTR * 2)
#define HSTG  (2 * HAST)
#define HNST  4
#define HSMEM (HNST * HSTG)

template<int EPI>
__global__ void __launch_bounds__(128, 2)
gemm_hf(const __half* __restrict__ A, const __half* __restrict__ W,
        const float* __restrict__ bias, const float* __restrict__ Z,
        float* __restrict__ C,
        int K, int lda, int ldw, int ldz, int ldc)
{
    extern __shared__ char dynsmem[];
    const uint32_t sb = (uint32_t)__cvta_generic_to_shared(dynsmem);

    const int tid  = threadIdx.x;
    const int m0   = blockIdx.y * 128;
    const int n0   = blockIdx.x * 128;
    const int koff = blockIdx.z * K;
    const int warp = tid >> 5;
    const int lane = tid & 31;
    const int g    = lane >> 2;
    const int t    = lane & 3;
    const int wm   = (warp & 1) * 64;
    const int wn   = (warp >> 1) * 64;

    const int u   = lane & 7;
    const int grp = lane >> 3;

    uint32_t aA[4];
#pragma unroll
    for (int mt = 0; mt < 4; mt++) {
        int row  = wm + mt * 16 + (grp & 1) * 8 + u;
        int kofh = (grp >> 1) * 8;
        aA[mt] = (uint32_t)(row * HSTR + kofh) * 2u;
    }
    uint32_t aB[4];
#pragma unroll
    for (int p = 0; p < 4; p++) {
        int row  = wn + (2 * p + (grp >> 1)) * 8 + u;
        int kofh = (grp & 1) * 8;
        aB[p] = (uint32_t)HAST + (uint32_t)(row * HSTR + kofh) * 2u;
    }

    // loader: 128 threads; row pair (lr, lr+64), two 8-half chunks per row
    const int lr = tid >> 1;           // 0..63
    const int lc = (tid & 1) * 16;     // halfs: 0 or 16
    const int niter = K / HBK;

    const __half* Abase = A + (size_t)(m0 + lr) * lda + koff + lc;
    const __half* Wbase = W + (size_t)(n0 + lr) * ldw + koff + lc;
    const uint32_t dA0 = sb + (uint32_t)(lr * HSTR + lc) * 2u;
    const uint32_t dA1 = sb + (uint32_t)((lr + 64) * HSTR + lc) * 2u;
    const uint32_t dW0 = dA0 + HAST;
    const uint32_t dW1 = dA1 + HAST;

    auto stage_load = [&](int s, int kb) {
        const uint32_t so = (uint32_t)s * HSTG;
        const int k0 = kb * HBK;
        cp16s(dA0 + so,       Abase + k0);
        cp16s(dA0 + so + 16u, Abase + k0 + 8);
        cp16s(dA1 + so,       Abase + k0 + (size_t)64 * lda);
        cp16s(dA1 + so + 16u, Abase + k0 + (size_t)64 * lda + 8);
        cp16s(dW0 + so,       Wbase + k0);
        cp16s(dW0 + so + 16u, Wbase + k0 + 8);
        cp16s(dW1 + so,       Wbase + k0 + (size_t)64 * ldw);
        cp16s(dW1 + so + 16u, Wbase + k0 + (size_t)64 * ldw + 8);
    };

    float acc[4][8][4];
#pragma unroll
    for (int mt = 0; mt < 4; mt++)
#pragma unroll
        for (int nt = 0; nt < 8; nt++)
#pragma unroll
            for (int i = 0; i < 4; i++) acc[mt][nt][i] = 0.0f;

#pragma unroll
    for (int s = 0; s < HNST - 1; s++) {
        if (s < niter) stage_load(s, s);
        cp_commit();
    }

    for (int it = 0; it < niter; it++) {
        asm volatile("cp.async.wait_group %0;" :: "n"(HNST - 2) : "memory");
        __syncthreads();

        const int pf = it + HNST - 1;
        if (pf < niter) stage_load(pf % HNST, pf);
        cp_commit();

        const uint32_t sOff = sb + (uint32_t)(it % HNST) * HSTG;
#pragma unroll
        for (int kk = 0; kk < 2; kk++) {
            const uint32_t kOff = sOff + (uint32_t)kk * 32u;
            uint32_t afr[4][4];
            uint32_t bfr[8][2];
#pragma unroll
            for (int mt = 0; mt < 4; mt++)
                ldsm_x4(afr[mt], aA[mt] + kOff);
#pragma unroll
            for (int p = 0; p < 4; p++) {
                uint32_t r[4];
                ldsm_x4(r, aB[p] + kOff);
                bfr[2 * p][0]     = r[0]; bfr[2 * p][1]     = r[1];
                bfr[2 * p + 1][0] = r[2]; bfr[2 * p + 1][1] = r[3];
            }
#pragma unroll
            for (int mt = 0; mt < 4; mt++)
#pragma unroll
                for (int nt = 0; nt < 8; nt++)
                    mma_f16(acc[mt][nt], afr[mt], bfr[nt]);
        }
    }

    float* Cz = C + (size_t)blockIdx.z * NTOK * ldc;
#pragma unroll
    for (int mt = 0; mt < 4; mt++) {
#pragma unroll
        for (int nt = 0; nt < 8; nt++) {
            const int row = m0 + wm + mt * 16 + g;
            const int col = n0 + wn + nt * 8 + 2 * t;
            float v0 = acc[mt][nt][0];
            float v1 = acc[mt][nt][1];
            float v2 = acc[mt][nt][2];
            float v3 = acc[mt][nt][3];
            if (EPI >= 1) {
                const float b0 = bias[col];
                const float b1 = bias[col + 1];
                v0 += b0; v1 += b1; v2 += b0; v3 += b1;
            }
            if (EPI == 2) {
                v0 = softplus_f(v0); v1 = softplus_f(v1);
                v2 = softplus_f(v2); v3 = softplus_f(v3);
            }
            if (EPI == 3) {
                const float z0 = Z[(size_t)row * ldz + col];
                const float z1 = Z[(size_t)row * ldz + col + 1];
                const float z2 = Z[(size_t)(row + 8) * ldz + col];
                const float z3 = Z[(size_t)(row + 8) * ldz + col + 1];
                v0 = silu_f(v0) * silu_f(z0);
                v1 = silu_f(v1) * silu_f(z1);
                v2 = silu_f(v2) * silu_f(z2);
                v3 = silu_f(v3) * silu_f(z3);
            }
            float2* p0 = (float2*)&Cz[(size_t)row * ldc + col];
            float2* p1 = (float2*)&Cz[(size_t)(row + 8) * ldc + col];
            *p0 = make_float2(v0, v1);
            *p1 = make_float2(v2, v3);
        }
    }
}

// reduce x_proj split-K partials; emit xdbl fp32 + padded fp16 dt-gemm input
__global__ void reduce_xdbl_kernel(const float* __restrict__ part,
                                   float* __restrict__ out,
                                   __half* __restrict__ outp)
{
    int i = blockIdx.x * 256 + threadIdx.x;
    if (i < NTOK * XDBL_W) {
        int row = i / XDBL_W, col = i % XDBL_W;
        float s = 0.0f;
#pragma unroll
        for (int z = 0; z < XPSPLIT; z++)
            s += part[(size_t)z * NTOK * XPN + (size_t)row * XPN + col];
        out[i] = s;
        if (col < DTRANK)   outp[row * DTK + col] = __float2half(s);
        else if (col < DTK) outp[row * DTK + col] = __float2half(0.0f);
    }
}

// ------------- causal depthwise conv (4 taps) + silu (fp32 + fp16) ---------
__global__ void conv_silu_kernel(const float* __restrict__ xz,
                                 const float* __restrict__ conv_w,
                                 const float* __restrict__ conv_b,
                                 float* __restrict__ xc,
                                 __half* __restrict__ xch)
{
    int idx = blockIdx.x * blockDim.x + threadIdx.x;
    if (idx >= NTOK * DINNER) return;
    int d   = idx % DINNER;
    int row = idx / DINNER;
    int l   = row & (SEQLEN - 1);
    int b   = row >> 11;

    float w0 = conv_w[d * DCONV + 0];
    float w1 = conv_w[d * DCONV + 1];
    float w2 = conv_w[d * DCONV + 2];
    float w3 = conv_w[d * DCONV + 3];

    float acc = conv_b[d];
    const size_t base = ((size_t)b * SEQLEN) * (2 * DINNER) + d;
    if (l >= 3) acc += w0 * xz[base + (size_t)(l - 3) * (2 * DINNER)];
    if (l >= 2) acc += w1 * xz[base + (size_t)(l - 2) * (2 * DINNER)];
    if (l >= 1) acc += w2 * xz[base + (size_t)(l - 1) * (2 * DINNER)];
    acc += w3 * xz[base + (size_t)l * (2 * DINNER)];

    float v = silu_f(acc);
    xc[idx]  = v;
    xch[idx] = __float2half(v);
}

// ============== chunked selective scan: 3 phases ===========================
// Warp layout: 8 channels x 4 lanes/channel x 4 states/lane.
// Block = 128 threads = 32 channels. Grid (NCHAN/32, NCH).

struct ScanASmem {
    float dt[2][SUB][32];
    float xc[2][SUB][32];
    float Bm[2][SUB][16];
};

__global__ void __launch_bounds__(128)
scanA_kernel(const float* __restrict__ dt, const float* __restrict__ xc,
             const float* __restrict__ xdbl, const float* __restrict__ A_log,
             float* __restrict__ gA, float* __restrict__ gB)
{
    __shared__ ScanASmem sm;
    const int tid  = threadIdx.x;
    const int cb   = tid >> 2;            // channel within block 0..31
    const int st4  = (tid & 3) * 4;       // first state of this thread
    const int c    = blockIdx.y;
    const int ch   = blockIdx.x * 32 + cb;
    const int b    = (blockIdx.x * 32) / DINNER;
    const int d0   = (blockIdx.x * 32) % DINNER;
    const int d    = d0 + cb;

    float4 Alg = *(const float4*)&A_log[d * DSTATE + st4];
    const float4 An = make_float4(-__expf(Alg.x), -__expf(Alg.y),
                                  -__expf(Alg.z), -__expf(Alg.w));
    const int row0 = b * SEQLEN + c * CH_T;

    // staging: dt/xc rows rA=tid>>2 cols (tid&3)*8, +4; Bm rows rA col (tid&3)*4
    const int rA = tid >> 2;
    const int cA = (tid & 3) * 8;
    const int cB = (tid & 3) * 4;

    auto stage = [&](int sc, int s) {
        const size_t r = (size_t)(row0 + sc * SUB + rA);
        cp16(&sm.dt[s][rA][cA],     &dt[r * DINNER + d0 + cA]);
        cp16(&sm.dt[s][rA][cA + 4], &dt[r * DINNER + d0 + cA + 4]);
        cp16(&sm.xc[s][rA][cA],     &xc[r * DINNER + d0 + cA]);
        cp16(&sm.xc[s][rA][cA + 4], &xc[r * DINNER + d0 + cA + 4]);
        cp16(&sm.Bm[s][rA][cB],     &xdbl[r * XDBL_W + DTRANK + cB]);
        cp_commit();
    };

    float4 Ap = make_float4(1.f, 1.f, 1.f, 1.f);
    float4 hB = make_float4(0.f, 0.f, 0.f, 0.f);

    stage(0, 0);
    for (int sc = 0; sc < CH_T / SUB; sc++) {
        const int s = sc & 1;
        if (sc + 1 < CH_T / SUB) {
            stage(sc + 1, s ^ 1);
            asm volatile("cp.async.wait_group 1;" ::: "memory");
        } else {
            asm volatile("cp.async.wait_group 0;" ::: "memory");
        }
        __syncthreads();

#pragma unroll 4
        for (int l = 0; l < SUB; l++) {
            const float dtv = sm.dt[s][l][cb];
            const float xv  = sm.xc[s][l][cb];
            const float4 Bv = *(const float4*)&sm.Bm[s][l][st4];
            const float u = dtv * xv;
            const float a0 = __expf(dtv * An.x);
            const float a1 = __expf(dtv * An.y);
            const float a2 = __expf(dtv * An.z);
            const float a3 = __expf(dtv * An.w);
            hB.x = fmaf(a0, hB.x, u * Bv.x);
            hB.y = fmaf(a1, hB.y, u * Bv.y);
            hB.z = fmaf(a2, hB.z, u * Bv.z);
            hB.w = fmaf(a3, hB.w, u * Bv.w);
            Ap.x *= a0; Ap.y *= a1; Ap.z *= a2; Ap.w *= a3;
        }
        __syncthreads();
    }

    const size_t o = ((size_t)c * NCHAN + ch) * DSTATE + st4;
    *(float4*)&gA[o] = Ap;
    *(float4*)&gB[o] = hB;
}

__global__ void scanB_kernel(const float* __restrict__ gA,
                             const float* __restrict__ gB,
                             float* __restrict__ hst)
{
    int idx = blockIdx.x * 256 + threadIdx.x;
    if (idx >= NCHAN * DSTATE) return;
    float h = 0.0f;
#pragma unroll
    for (int c = 0; c < NCH; c++) {
        const size_t o = (size_t)c * (NCHAN * DSTATE) + idx;
        hst[o] = h;
        h = fmaf(gA[o], h, gB[o]);
    }
}

struct ScanCSmem {
    float dt[2][SUB][32];
    float xc[2][SUB][32];
    float gt[2][SUB][32];
    float Bm[2][SUB][16];
    float Cm[2][SUB][16];
};

__global__ void __launch_bounds__(128)
scanC_kernel(const float* __restrict__ xdbl, const float* __restrict__ dt,
             const float* __restrict__ xc,   const float* __restrict__ gate,
             const float* __restrict__ A_log, const float* __restrict__ Dvec,
             const float* __restrict__ hst,  __half* __restrict__ yout)
{
    __shared__ ScanCSmem sm;
    const int tid  = threadIdx.x;
    const int cb   = tid >> 2;
    const int st4  = (tid & 3) * 4;
    const int c    = blockIdx.y;
    const int ch   = blockIdx.x * 32 + cb;
    const int b    = (blockIdx.x * 32) / DINNER;
    const int d0   = (blockIdx.x * 32) % DINNER;
    const int d    = d0 + cb;

    float4 Alg = *(const float4*)&A_log[d * DSTATE + st4];
    const float4 An = make_float4(-__expf(Alg.x), -__expf(Alg.y),
                                  -__expf(Alg.z), -__expf(Alg.w));
    const float Dd = Dvec[d];
    const int row0 = b * SEQLEN + c * CH_T;

    const int rA = tid >> 2;
    const int cA = (tid & 3) * 8;
    const int cB = (tid & 3) * 4;

    auto stage = [&](int sc, int s) {
        const size_t r = (size_t)(row0 + sc * SUB + rA);
        cp16(&sm.dt[s][rA][cA],     &dt  [r * DINNER + d0 + cA]);
        cp16(&sm.dt[s][rA][cA + 4], &dt  [r * DINNER + d0 + cA + 4]);
        cp16(&sm.xc[s][rA][cA],     &xc  [r * DINNER + d0 + cA]);
        cp16(&sm.xc[s][rA][cA + 4], &xc  [r * DINNER + d0 + cA + 4]);
        cp16(&sm.gt[s][rA][cA],     &gate[r * DINNER + d0 + cA]);
        cp16(&sm.gt[s][rA][cA + 4], &gate[r * DINNER + d0 + cA + 4]);
        cp16(&sm.Bm[s][rA][cB],     &xdbl[r * XDBL_W + DTRANK + cB]);
        cp16(&sm.Cm[s][rA][cB],     &xdbl[r * XDBL_W + DTRANK + DSTATE + cB]);
        cp_commit();
    };

    float4 h = *(const float4*)&hst[((size_t)c * NCHAN + ch) * DSTATE + st4];

    stage(0, 0);
    for (int sc = 0; sc < CH_T / SUB; sc++) {
        const int s = sc & 1;
        if (sc + 1 < CH_T / SUB) {
            stage(sc + 1, s ^ 1);
            asm volatile("cp.async.wait_group 1;" ::: "memory");
        } else {
            asm volatile("cp.async.wait_group 0;" ::: "memory");
        }
        __syncthreads();

#pragma unroll 4
        for (int l = 0; l < SUB; l++) {
            const float dtv = sm.dt[s][l][cb];
            const float xv  = sm.xc[s][l][cb];
            const float4 Bv = *(const float4*)&sm.Bm[s][l][st4];
            const float4 Cv = *(const float4*)&sm.Cm[s][l][st4];
            const float u = dtv * xv;
            h.x = fmaf(__expf(dtv * An.x), h.x, u * Bv.x);
            h.y = fmaf(__expf(dtv * An.y), h.y, u * Bv.y);
            h.z = fmaf(__expf(dtv * An.z), h.z, u * Bv.z);
            h.w = fmaf(__expf(dtv * An.w), h.w, u * Bv.w);

            float p = h.x * Cv.x + h.y * Cv.y + h.z * Cv.z + h.w * Cv.w;
            p += __shfl_xor_sync(0xffffffffu, p, 1);
            p += __shfl_xor_sync(0xffffffffu, p, 2);

            if ((tid & 3) == 0) {
                const float y = (p + xv * Dd) * sm.gt[s][l][cb];
                yout[(size_t)(row0 + sc * SUB + l) * DINNER + d] = __float2half(y);
            }
        }
        __syncthreads();
    }
}

// --------------------------------- host ------------------------------------
extern "C" void kernel_launch(void* const* d_in, const int* in_sizes, int n_in,
                              void* d_out, int out_size)
{
    const float* hs         = (const float*)d_in[0];
    const float* query      = (const float*)d_in[1];
    const float* in_proj_w  = (const float*)d_in[2];
    const float* conv_w     = (const float*)d_in[3];
    const float* conv_b     = (const float*)d_in[4];
    const float* x_proj_w   = (const float*)d_in[5];
    const float* dt_proj_w  = (const float*)d_in[6];
    const float* dt_proj_b  = (const float*)d_in[7];
    const float* A_log      = (const float*)d_in[8];
    const float* Dvec       = (const float*)d_in[9];
    const float* query_w    = (const float*)d_in[10];
    const float* query_b    = (const float*)d_in[11];
    const float* out_proj_w = (const float*)d_in[12];
    float* out = (float*)d_out;

    float  *p_xz, *p_gate, *p_xc, *p_xdbl, *p_xdp, *p_dt, *p_scA, *p_scB, *p_hst;
    __half *p_hsh, *p_quh, *p_w1h, *p_w2h, *p_w3h, *p_w4h;
    __half *p_xpwh, *p_xch, *p_xdinh, *p_yh;
    cudaGetSymbolAddress((void**)&p_xz,    g_xz);
    cudaGetSymbolAddress((void**)&p_gate,  g_gate);
    cudaGetSymbolAddress((void**)&p_xc,    g_xc);
    cudaGetSymbolAddress((void**)&p_xdbl,  g_xdbl);
    cudaGetSymbolAddress((void**)&p_xdp,   g_xdp);
    cudaGetSymbolAddress((void**)&p_dt,    g_dt);
    cudaGetSymbolAddress((void**)&p_scA,   g_scA);
    cudaGetSymbolAddress((void**)&p_scB,   g_scB);
    cudaGetSymbolAddress((void**)&p_hst,   g_hst);
    cudaGetSymbolAddress((void**)&p_hsh,   g_hsh);
    cudaGetSymbolAddress((void**)&p_quh,   g_quh);
    cudaGetSymbolAddress((void**)&p_w1h,   g_w1h);
    cudaGetSymbolAddress((void**)&p_w2h,   g_w2h);
    cudaGetSymbolAddress((void**)&p_w3h,   g_w3h);
    cudaGetSymbolAddress((void**)&p_w4h,   g_w4h);
    cudaGetSymbolAddress((void**)&p_xpwh,  g_xpwh);
    cudaGetSymbolAddress((void**)&p_xch,   g_xch);
    cudaGetSymbolAddress((void**)&p_xdinh, g_xdinh);
    cudaGetSymbolAddress((void**)&p_yh,    g_yh);

    cudaFuncSetAttribute(gemm_hf<0>, cudaFuncAttributeMaxDynamicSharedMemorySize, HSMEM);
    cudaFuncSetAttribute(gemm_hf<2>, cudaFuncAttributeMaxDynamicSharedMemorySize, HSMEM);
    cudaFuncSetAttribute(gemm_hf<3>, cudaFuncAttributeMaxDynamicSharedMemorySize, HSMEM);

    // 1) fused conversions: hs, query, in_proj_w
    {
        int n0 = NTOK * DMODEL / 8;
        int n1 = NTOK * DMODEL / 8;
        int n2 = 2 * DINNER * DMODEL / 8;
        int tot = n0 + n1 + n2;
        f2h3_kernel<<<(tot + 255) / 256, 256>>>(hs, p_hsh, n0,
                                                query, p_quh, n1,
                                                in_proj_w, p_w1h, n2);
    }
    // 2) fused conversions: query_w, out_proj_w
    {
        int n0 = DINNER * DMODEL / 8;
        int n1 = DMODEL * DINNER / 8;
        int tot = n0 + n1;
        f2h3_kernel<<<(tot + 255) / 256, 256>>>(query_w, p_w2h, n0,
                                                out_proj_w, p_w3h, n1,
                                                nullptr, nullptr, 0);
    }
    // 3) fused pads: dt weights + x_proj weights
    {
        int tot = DINNER * DTK + XPN * DINNER;
        padcomb_kernel<<<(tot + 255) / 256, 256>>>(dt_proj_w, p_w4h,
                                                   x_proj_w, p_xpwh);
    }

    // 4) xz = hs @ in_proj_w^T  (4096 x 3072, K=768)   [ncu captures this]
    gemm_hf<0><<<dim3(2 * DINNER / 128, NTOK / 128), 128, HSMEM>>>(
        p_hsh, p_w1h, nullptr, nullptr, p_xz, DMODEL, DMODEL, DMODEL, 0, 2 * DINNER);

    // 5) gate = silu(query @ query_w^T + b) * silu(z)  (4096 x 1536)
    gemm_hf<3><<<dim3(DINNER / 128, NTOK / 128), 128, HSMEM>>>(
        p_quh, p_w2h, query_b, p_xz + DINNER, p_gate,
        DMODEL, DMODEL, DMODEL, 2 * DINNER, DINNER);

    // 6) causal depthwise conv + silu (fp32 + fp16 outputs)
    {
        int total = NTOK * DINNER;
        conv_silu_kernel<<<(total + 255) / 256, 256>>>(
            p_xz, conv_w, conv_b, p_xc, p_xch);
    }

    // 7) x_dbl partials = xc @ x_proj_w^T (padded N=128, split-K=4)
    gemm_hf<0><<<dim3(1, NTOK / 128, XPSPLIT), 128, HSMEM>>>(
        p_xch, p_xpwh, nullptr, nullptr, p_xdp,
        DINNER / XPSPLIT, DINNER, DINNER, 0, XPN);

    // 8) reduce partials -> xdbl fp32 + padded fp16 dt input
    reduce_xdbl_kernel<<<(NTOK * XDBL_W + 255) / 256, 256>>>(p_xdp, p_xdbl, p_xdinh);

    // 9) dt = softplus(xdin @ w4^T + dt_proj_b)  (K=64 padded)
    gemm_hf<2><<<dim3(DINNER / 128, NTOK / 128), 128, HSMEM>>>(
        p_xdinh, p_w4h, dt_proj_b, nullptr, p_dt, DTK, DTK, DTK, 0, DINNER);

    // 10-12) chunked selective scan
    scanA_kernel<<<dim3(NCHAN / 32, NCH), 128>>>(
        p_dt, p_xc, p_xdbl, A_log, p_scA, p_scB);
    scanB_kernel<<<(NCHAN * DSTATE + 255) / 256, 256>>>(p_scA, p_scB, p_hst);
    scanC_kernel<<<dim3(NCHAN / 32, NCH), 128>>>(
        p_xdbl, p_dt, p_xc, p_gate, A_log, Dvec, p_hst, p_yh);

    // 13) out = y @ out_proj_w^T  (4096 x 768, K=1536)
    gemm_hf<0><<<dim3(DMODEL / 128, NTOK / 128), 128, HSMEM>>>(
        p_yh, p_w3h, nullptr, nullptr, out, DINNER, DINNER, DINNER, 0, DMODEL);
}

// round 15
// speedup vs baseline: 13.5345x; 1.2428x over previous
#include <cuda_runtime.h>
#include <cuda_fp16.h>
#include <cstdint>

// Problem constants
#define DMODEL   768
#define DSTATE   16
#define DCONV    4
#define DINNER   1536
#define DTRANK   48
#define NBATCH   2
#define SEQLEN   2048
#define NTOK     (NBATCH * SEQLEN)        // 4096
#define XDBL_W   (DTRANK + 2 * DSTATE)    // 80
#define XPN      128                       // padded N for x_proj gemm
#define XPSPLIT  4                         // split-K for x_proj gemm
#define DTK      64                        // padded K for dt gemm
#define NCHAN    (NBATCH * DINNER)         // 3072 scan channels
#define CH_T     128                       // timesteps per scan chunk
#define NCH      (SEQLEN / CH_T)           // 16 chunks
#define SUB      32                        // staging sub-chunk

// -------- scratch (static device globals; no runtime allocation) ----------
__device__ float  g_xz   [NTOK * 2 * DINNER];
__device__ float  g_gate [NTOK * DINNER];          // silu(q)*silu(z)
__device__ float  g_xc   [NTOK * DINNER];
__device__ float  g_xdbl [NTOK * XDBL_W];
__device__ float  g_xdp  [XPSPLIT * NTOK * XPN];   // x_proj split-K partials
__device__ float  g_dt   [NTOK * DINNER];
__device__ float  g_scA  [NCH * NCHAN * DSTATE];   // per-chunk prod(a)
__device__ float  g_scB  [NCH * NCHAN * DSTATE];   // per-chunk local state
__device__ float  g_hst  [NCH * NCHAN * DSTATE];   // chunk-start states
// fp16 GEMM operands
__device__ __half g_hsh  [NTOK * DMODEL];
__device__ __half g_quh  [NTOK * DMODEL];
__device__ __half g_w1h  [2 * DINNER * DMODEL];
__device__ __half g_w2h  [DINNER * DMODEL];
__device__ __half g_w3h  [DMODEL * DINNER];
__device__ __half g_w4h  [DINNER * DTK];
__device__ __half g_xpwh [XPN * DINNER];           // padded x_proj weights
__device__ __half g_xch  [NTOK * DINNER];          // fp16 conv output
__device__ __half g_xdinh[NTOK * DTK];
__device__ __half g_yh   [NTOK * DINNER];

// -------------------------- helpers ---------------------------------------
__device__ __forceinline__ float silu_f(float x) {
    return x / (1.0f + __expf(-x));
}
__device__ __forceinline__ float softplus_f(float x) {
    return (x > 20.0f) ? x : log1pf(__expf(x));
}
// .cg = bypass L1 (no L1 reuse for streamed tiles)
__device__ __forceinline__ void cp16(void* s, const void* g) {
    uint32_t sa = (uint32_t)__cvta_generic_to_shared(s);
    asm volatile("cp.async.cg.shared.global [%0], [%1], 16;" :: "r"(sa), "l"(g));
}
__device__ __forceinline__ void cp16s(uint32_t saddr, const void* g) {
    asm volatile("cp.async.cg.shared.global [%0], [%1], 16;" :: "r"(saddr), "l"(g));
}
__device__ __forceinline__ void cp_commit() {
    asm volatile("cp.async.commit_group;" ::: "memory");
}
__device__ __forceinline__ void ldsm_x4(uint32_t* r, uint32_t addr) {
    asm volatile("ldmatrix.sync.aligned.m8n8.x4.shared.b16 {%0,%1,%2,%3}, [%4];"
                 : "=r"(r[0]), "=r"(r[1]), "=r"(r[2]), "=r"(r[3]) : "r"(addr));
}
__device__ __forceinline__ void mma_f16(float* d, const uint32_t* a, const uint32_t* b) {
    asm volatile(
        "mma.sync.aligned.m16n8k16.row.col.f32.f16.f16.f32 "
        "{%0,%1,%2,%3}, {%4,%5,%6,%7}, {%8,%9}, {%0,%1,%2,%3};\n"
        : "+f"(d[0]), "+f"(d[1]), "+f"(d[2]), "+f"(d[3])
        : "r"(a[0]), "r"(a[1]), "r"(a[2]), "r"(a[3]), "r"(b[0]), "r"(b[1]));
}

// ---------------- fused fp32 -> fp16 conversion (up to 3 arrays) -----------
__device__ __forceinline__ void f2h8(const float* in, __half* out, int j) {
    float4 v0 = ((const float4*)in)[2 * j];
    float4 v1 = ((const float4*)in)[2 * j + 1];
    __half2 hp[4];
    hp[0] = __floats2half2_rn(v0.x, v0.y);
    hp[1] = __floats2half2_rn(v0.z, v0.w);
    hp[2] = __floats2half2_rn(v1.x, v1.y);
    hp[3] = __floats2half2_rn(v1.z, v1.w);
    ((uint4*)out)[j] = *(const uint4*)hp;
}

__global__ void f2h3_kernel(const float* i0, __half* o0, int n0,
                            const float* i1, __half* o1, int n1,
                            const float* i2, __half* o2, int n2)
{
    int i = blockIdx.x * blockDim.x + threadIdx.x;
    if (i < n0)                 f2h8(i0, o0, i);
    else if (i < n0 + n1)       f2h8(i1, o1, i - n0);
    else if (i < n0 + n1 + n2)  f2h8(i2, o2, i - n0 - n1);
}

// fused pads: dt weights [1536,48]->[1536,64], x_proj weights [80,1536]->[128,1536]
__global__ void padcomb_kernel(const float* w4, __half* ow4,
                               const float* xw, __half* oxw)
{
    int i = blockIdx.x * blockDim.x + threadIdx.x;
    if (i < DINNER * DTK) {
        int row = i >> 6, col = i & 63;
        ow4[i] = (col < DTRANK) ? __float2half(w4[row * DTRANK + col])
                                : __float2half(0.0f);
    } else {
        int k = i - DINNER * DTK;
        if (k < XPN * DINNER) {
            int row = k / DINNER;
            oxw[k] = (row < XDBL_W) ? __float2half(xw[k]) : __float2half(0.0f);
        }
    }
}

// ================= fp16 tensor-core GEMM: C = A * W^T + epi ================
// A: [M,K_total] half (lda), W: [N,K_total] half (ldw), C fp32 (ldc)
// CTA 128x128, BK=32, 8 warps (2Mx4N of 64x32), 4-stage cp.async, 1 sync/iter.
// EPI: 0 none; 1 +bias; 2 +bias,softplus; 3 silu(v+bias)*silu(Z[row][col])
#define HBK   32
#define HSTR  40
#define HAST  (128 * HSTR * 2)
#define HSTG  (2 * HAST)
#define HNST  4
#define HSMEM (HNST * HSTG)

template<int EPI>
__global__ void __launch_bounds__(256, 2)
gemm_hf(const __half* __restrict__ A, const __half* __restrict__ W,
        const float* __restrict__ bias, const float* __restrict__ Z,
        float* __restrict__ C,
        int K, int lda, int ldw, int ldz, int ldc)
{
    extern __shared__ char dynsmem[];
    const uint32_t sb = (uint32_t)__cvta_generic_to_shared(dynsmem);

    const int tid  = threadIdx.x;
    const int m0   = blockIdx.y * 128;
    const int n0   = blockIdx.x * 128;
    const int koff = blockIdx.z * K;
    const int warp = tid >> 5;
    const int lane = tid & 31;
    const int g    = lane >> 2;
    const int t    = lane & 3;
    const int wm   = (warp & 1) * 64;
    const int wn   = (warp >> 1) * 32;

    const int u   = lane & 7;
    const int grp = lane >> 3;

    uint32_t aA[4];
#pragma unroll
    for (int mt = 0; mt < 4; mt++) {
        int row  = wm + mt * 16 + (grp & 1) * 8 + u;
        int kofh = (grp >> 1) * 8;
        aA[mt] = (uint32_t)(row * HSTR + kofh) * 2u;
    }
    uint32_t aB[2];
#pragma unroll
    for (int p = 0; p < 2; p++) {
        int row  = wn + (2 * p + (grp >> 1)) * 8 + u;
        int kofh = (grp & 1) * 8;
        aB[p] = (uint32_t)HAST + (uint32_t)(row * HSTR + kofh) * 2u;
    }

    // loader: 64 rows/pass x 4 chunks of 8 halfs (16B) per 32-col row
    const int lr = tid >> 2;
    const int lc = (tid & 3) * 8;
    const int niter = K / HBK;

    const __half* Abase = A + (size_t)(m0 + lr) * lda + koff + lc;
    const __half* Wbase = W + (size_t)(n0 + lr) * ldw + koff + lc;
    const uint32_t dA0 = sb + (uint32_t)(lr * HSTR + lc) * 2u;
    const uint32_t dA1 = sb + (uint32_t)((lr + 64) * HSTR + lc) * 2u;
    const uint32_t dW0 = dA0 + HAST;
    const uint32_t dW1 = dA1 + HAST;

    auto stage_load = [&](int s, int kb) {
        const uint32_t so = (uint32_t)s * HSTG;
        const int k0 = kb * HBK;
        cp16s(dA0 + so, Abase + k0);
        cp16s(dA1 + so, Abase + k0 + (size_t)64 * lda);
        cp16s(dW0 + so, Wbase + k0);
        cp16s(dW1 + so, Wbase + k0 + (size_t)64 * ldw);
    };

    float acc[4][4][4];
#pragma unroll
    for (int mt = 0; mt < 4; mt++)
#pragma unroll
        for (int nt = 0; nt < 4; nt++)
#pragma unroll
            for (int i = 0; i < 4; i++) acc[mt][nt][i] = 0.0f;

#pragma unroll
    for (int s = 0; s < HNST - 1; s++) {
        if (s < niter) stage_load(s, s);
        cp_commit();
    }

    for (int it = 0; it < niter; it++) {
        asm volatile("cp.async.wait_group %0;" :: "n"(HNST - 2) : "memory");
        __syncthreads();

        const int pf = it + HNST - 1;
        if (pf < niter) stage_load(pf % HNST, pf);
        cp_commit();

        const uint32_t sOff = sb + (uint32_t)(it % HNST) * HSTG;
#pragma unroll
        for (int kk = 0; kk < 2; kk++) {
            const uint32_t kOff = sOff + (uint32_t)kk * 32u;
            uint32_t afr[4][4];
            uint32_t bfr[4][2];
#pragma unroll
            for (int mt = 0; mt < 4; mt++)
                ldsm_x4(afr[mt], aA[mt] + kOff);
            {
                uint32_t r[4];
                ldsm_x4(r, aB[0] + kOff);
                bfr[0][0] = r[0]; bfr[0][1] = r[1];
                bfr[1][0] = r[2]; bfr[1][1] = r[3];
                ldsm_x4(r, aB[1] + kOff);
                bfr[2][0] = r[0]; bfr[2][1] = r[1];
                bfr[3][0] = r[2]; bfr[3][1] = r[3];
            }
#pragma unroll
            for (int mt = 0; mt < 4; mt++)
#pragma unroll
                for (int nt = 0; nt < 4; nt++)
                    mma_f16(acc[mt][nt], afr[mt], bfr[nt]);
        }
    }

    float* Cz = C + (size_t)blockIdx.z * NTOK * ldc;
#pragma unroll
    for (int mt = 0; mt < 4; mt++) {
#pragma unroll
        for (int nt = 0; nt < 4; nt++) {
            const int row = m0 + wm + mt * 16 + g;
            const int col = n0 + wn + nt * 8 + 2 * t;
            float v0 = acc[mt][nt][0];
            float v1 = acc[mt][nt][1];
            float v2 = acc[mt][nt][2];
            float v3 = acc[mt][nt][3];
            if (EPI >= 1) {
                const float b0 = bias[col];
                const float b1 = bias[col + 1];
                v0 += b0; v1 += b1; v2 += b0; v3 += b1;
            }
            if (EPI == 2) {
                v0 = softplus_f(v0); v1 = softplus_f(v1);
                v2 = softplus_f(v2); v3 = softplus_f(v3);
            }
            if (EPI == 3) {
                const float z0 = Z[(size_t)row * ldz + col];
                const float z1 = Z[(size_t)row * ldz + col + 1];
                const float z2 = Z[(size_t)(row + 8) * ldz + col];
                const float z3 = Z[(size_t)(row + 8) * ldz + col + 1];
                v0 = silu_f(v0) * silu_f(z0);
                v1 = silu_f(v1) * silu_f(z1);
                v2 = silu_f(v2) * silu_f(z2);
                v3 = silu_f(v3) * silu_f(z3);
            }
            float2* p0 = (float2*)&Cz[(size_t)row * ldc + col];
            float2* p1 = (float2*)&Cz[(size_t)(row + 8) * ldc + col];
            *p0 = make_float2(v0, v1);
            *p1 = make_float2(v2, v3);
        }
    }
}

// reduce x_proj split-K partials; emit xdbl fp32 + padded fp16 dt-gemm input
__global__ void reduce_xdbl_kernel(const float* __restrict__ part,
                                   float* __restrict__ out,
                                   __half* __restrict__ outp)
{
    int i = blockIdx.x * 256 + threadIdx.x;
    if (i < NTOK * XDBL_W) {
        int row = i / XDBL_W, col = i % XDBL_W;
        float s = 0.0f;
#pragma unroll
        for (int z = 0; z < XPSPLIT; z++)
            s += part[(size_t)z * NTOK * XPN + (size_t)row * XPN + col];
        out[i] = s;
        if (col < DTRANK)   outp[row * DTK + col] = __float2half(s);
        else if (col < DTK) outp[row * DTK + col] = __float2half(0.0f);
    }
}

// ------------- causal depthwise conv (4 taps) + silu (fp32 + fp16) ---------
__global__ void conv_silu_kernel(const float* __restrict__ xz,
                                 const float* __restrict__ conv_w,
                                 const float* __restrict__ conv_b,
                                 float* __restrict__ xc,
                                 __half* __restrict__ xch)
{
    int idx = blockIdx.x * blockDim.x + threadIdx.x;
    if (idx >= NTOK * DINNER) return;
    int d   = idx % DINNER;
    int row = idx / DINNER;
    int l   = row & (SEQLEN - 1);
    int b   = row >> 11;

    float w0 = conv_w[d * DCONV + 0];
    float w1 = conv_w[d * DCONV + 1];
    float w2 = conv_w[d * DCONV + 2];
    float w3 = conv_w[d * DCONV + 3];

    float acc = conv_b[d];
    const size_t base = ((size_t)b * SEQLEN) * (2 * DINNER) + d;
    if (l >= 3) acc += w0 * xz[base + (size_t)(l - 3) * (2 * DINNER)];
    if (l >= 2) acc += w1 * xz[base + (size_t)(l - 2) * (2 * DINNER)];
    if (l >= 1) acc += w2 * xz[base + (size_t)(l - 1) * (2 * DINNER)];
    acc += w3 * xz[base + (size_t)l * (2 * DINNER)];

    float v = silu_f(acc);
    xc[idx]  = v;
    xch[idx] = __float2half(v);
}

// ============== chunked selective scan: 3 phases ===========================
// Warp layout: 8 channels x 4 lanes/channel x 4 states/lane.
// Block = 128 threads = 32 channels. Grid (NCHAN/32, NCH).

struct ScanASmem {
    float dt[2][SUB][32];
    float xc[2][SUB][32];
    float Bm[2][SUB][16];
};

__global__ void __launch_bounds__(128)
scanA_kernel(const float* __restrict__ dt, const float* __restrict__ xc,
             const float* __restrict__ xdbl, const float* __restrict__ A_log,
             float* __restrict__ gA, float* __restrict__ gB)
{
    __shared__ ScanASmem sm;
    const int tid  = threadIdx.x;
    const int cb   = tid >> 2;            // channel within block 0..31
    const int st4  = (tid & 3) * 4;       // first state of this thread
    const int c    = blockIdx.y;
    const int ch   = blockIdx.x * 32 + cb;
    const int b    = (blockIdx.x * 32) / DINNER;
    const int d0   = (blockIdx.x * 32) % DINNER;
    const int d    = d0 + cb;

    float4 Alg = *(const float4*)&A_log[d * DSTATE + st4];
    const float4 An = make_float4(-__expf(Alg.x), -__expf(Alg.y),
                                  -__expf(Alg.z), -__expf(Alg.w));
    const int row0 = b * SEQLEN + c * CH_T;

    const int rA = tid >> 2;
    const int cA = (tid & 3) * 8;
    const int cB = (tid & 3) * 4;

    auto stage = [&](int sc, int s) {
        const size_t r = (size_t)(row0 + sc * SUB + rA);
        cp16(&sm.dt[s][rA][cA],     &dt[r * DINNER + d0 + cA]);
        cp16(&sm.dt[s][rA][cA + 4], &dt[r * DINNER + d0 + cA + 4]);
        cp16(&sm.xc[s][rA][cA],     &xc[r * DINNER + d0 + cA]);
        cp16(&sm.xc[s][rA][cA + 4], &xc[r * DINNER + d0 + cA + 4]);
        cp16(&sm.Bm[s][rA][cB],     &xdbl[r * XDBL_W + DTRANK + cB]);
        cp_commit();
    };

    float4 Ap = make_float4(1.f, 1.f, 1.f, 1.f);
    float4 hB = make_float4(0.f, 0.f, 0.f, 0.f);

    stage(0, 0);
    for (int sc = 0; sc < CH_T / SUB; sc++) {
        const int s = sc & 1;
        if (sc + 1 < CH_T / SUB) {
            stage(sc + 1, s ^ 1);
            asm volatile("cp.async.wait_group 1;" ::: "memory");
        } else {
            asm volatile("cp.async.wait_group 0;" ::: "memory");
        }
        __syncthreads();

#pragma unroll 4
        for (int l = 0; l < SUB; l++) {
            const float dtv = sm.dt[s][l][cb];
            const float xv  = sm.xc[s][l][cb];
            const float4 Bv = *(const float4*)&sm.Bm[s][l][st4];
            const float u = dtv * xv;
            const float a0 = __expf(dtv * An.x);
            const float a1 = __expf(dtv * An.y);
            const float a2 = __expf(dtv * An.z);
            const float a3 = __expf(dtv * An.w);
            hB.x = fmaf(a0, hB.x, u * Bv.x);
            hB.y = fmaf(a1, hB.y, u * Bv.y);
            hB.z = fmaf(a2, hB.z, u * Bv.z);
            hB.w = fmaf(a3, hB.w, u * Bv.w);
            Ap.x *= a0; Ap.y *= a1; Ap.z *= a2; Ap.w *= a3;
        }
        __syncthreads();
    }

    const size_t o = ((size_t)c * NCHAN + ch) * DSTATE + st4;
    *(float4*)&gA[o] = Ap;
    *(float4*)&gB[o] = hB;
}

__global__ void scanB_kernel(const float* __restrict__ gA,
                             const float* __restrict__ gB,
                             float* __restrict__ hst)
{
    int idx = blockIdx.x * 256 + threadIdx.x;
    if (idx >= NCHAN * DSTATE) return;
    float h = 0.0f;
#pragma unroll
    for (int c = 0; c < NCH; c++) {
        const size_t o = (size_t)c * (NCHAN * DSTATE) + idx;
        hst[o] = h;
        h = fmaf(gA[o], h, gB[o]);
    }
}

struct ScanCSmem {
    float dt[2][SUB][32];
    float xc[2][SUB][32];
    float gt[2][SUB][32];
    float Bm[2][SUB][16];
    float Cm[2][SUB][16];
};

__global__ void __launch_bounds__(128)
scanC_kernel(const float* __restrict__ xdbl, const float* __restrict__ dt,
             const float* __restrict__ xc,   const float* __restrict__ gate,
             const float* __restrict__ A_log, const float* __restrict__ Dvec,
             const float* __restrict__ hst,  __half* __restrict__ yout)
{
    __shared__ ScanCSmem sm;
    const int tid  = threadIdx.x;
    const int cb   = tid >> 2;
    const int st4  = (tid & 3) * 4;
    const int c    = blockIdx.y;
    const int ch   = blockIdx.x * 32 + cb;
    const int b    = (blockIdx.x * 32) / DINNER;
    const int d0   = (blockIdx.x * 32) % DINNER;
    const int d    = d0 + cb;

    float4 Alg = *(const float4*)&A_log[d * DSTATE + st4];
    const float4 An = make_float4(-__expf(Alg.x), -__expf(Alg.y),
                                  -__expf(Alg.z), -__expf(Alg.w));
    const float Dd = Dvec[d];
    const int row0 = b * SEQLEN + c * CH_T;

    const int rA = tid >> 2;
    const int cA = (tid & 3) * 8;
    const int cB = (tid & 3) * 4;

    auto stage = [&](int sc, int s) {
        const size_t r = (size_t)(row0 + sc * SUB + rA);
        cp16(&sm.dt[s][rA][cA],     &dt  [r * DINNER + d0 + cA]);
        cp16(&sm.dt[s][rA][cA + 4], &dt  [r * DINNER + d0 + cA + 4]);
        cp16(&sm.xc[s][rA][cA],     &xc  [r * DINNER + d0 + cA]);
        cp16(&sm.xc[s][rA][cA + 4], &xc  [r * DINNER + d0 + cA + 4]);
        cp16(&sm.gt[s][rA][cA],     &gate[r * DINNER + d0 + cA]);
        cp16(&sm.gt[s][rA][cA + 4], &gate[r * DINNER + d0 + cA + 4]);
        cp16(&sm.Bm[s][rA][cB],     &xdbl[r * XDBL_W + DTRANK + cB]);
        cp16(&sm.Cm[s][rA][cB],     &xdbl[r * XDBL_W + DTRANK + DSTATE + cB]);
        cp_commit();
    };

    float4 h = *(const float4*)&hst[((size_t)c * NCHAN + ch) * DSTATE + st4];

    stage(0, 0);
    for (int sc = 0; sc < CH_T / SUB; sc++) {
        const int s = sc & 1;
        if (sc + 1 < CH_T / SUB) {
            stage(sc + 1, s ^ 1);
            asm volatile("cp.async.wait_group 1;" ::: "memory");
        } else {
            asm volatile("cp.async.wait_group 0;" ::: "memory");
        }
        __syncthreads();

#pragma unroll 4
        for (int l = 0; l < SUB; l++) {
            const float dtv = sm.dt[s][l][cb];
            const float xv  = sm.xc[s][l][cb];
            const float4 Bv = *(const float4*)&sm.Bm[s][l][st4];
            const float4 Cv = *(const float4*)&sm.Cm[s][l][st4];
            const float u = dtv * xv;
            h.x = fmaf(__expf(dtv * An.x), h.x, u * Bv.x);
            h.y = fmaf(__expf(dtv * An.y), h.y, u * Bv.y);
            h.z = fmaf(__expf(dtv * An.z), h.z, u * Bv.z);
            h.w = fmaf(__expf(dtv * An.w), h.w, u * Bv.w);

            float p = h.x * Cv.x + h.y * Cv.y + h.z * Cv.z + h.w * Cv.w;
            p += __shfl_xor_sync(0xffffffffu, p, 1);
            p += __shfl_xor_sync(0xffffffffu, p, 2);

            if ((tid & 3) == 0) {
                const float y = (p + xv * Dd) * sm.gt[s][l][cb];
                yout[(size_t)(row0 + sc * SUB + l) * DINNER + d] = __float2half(y);
            }
        }
        __syncthreads();
    }
}

// --------------------------------- host ------------------------------------
extern "C" void kernel_launch(void* const* d_in, const int* in_sizes, int n_in,
                              void* d_out, int out_size)
{
    const float* hs         = (const float*)d_in[0];
    const float* query      = (const float*)d_in[1];
    const float* in_proj_w  = (const float*)d_in[2];
    const float* conv_w     = (const float*)d_in[3];
    const float* conv_b     = (const float*)d_in[4];
    const float* x_proj_w   = (const float*)d_in[5];
    const float* dt_proj_w  = (const float*)d_in[6];
    const float* dt_proj_b  = (const float*)d_in[7];
    const float* A_log      = (const float*)d_in[8];
    const float* Dvec       = (const float*)d_in[9];
    const float* query_w    = (const float*)d_in[10];
    const float* query_b    = (const float*)d_in[11];
    const float* out_proj_w = (const float*)d_in[12];
    float* out = (float*)d_out;

    float  *p_xz, *p_gate, *p_xc, *p_xdbl, *p_xdp, *p_dt, *p_scA, *p_scB, *p_hst;
    __half *p_hsh, *p_quh, *p_w1h, *p_w2h, *p_w3h, *p_w4h;
    __half *p_xpwh, *p_xch, *p_xdinh, *p_yh;
    cudaGetSymbolAddress((void**)&p_xz,    g_xz);
    cudaGetSymbolAddress((void**)&p_gate,  g_gate);
    cudaGetSymbolAddress((void**)&p_xc,    g_xc);
    cudaGetSymbolAddress((void**)&p_xdbl,  g_xdbl);
    cudaGetSymbolAddress((void**)&p_xdp,   g_xdp);
    cudaGetSymbolAddress((void**)&p_dt,    g_dt);
    cudaGetSymbolAddress((void**)&p_scA,   g_scA);
    cudaGetSymbolAddress((void**)&p_scB,   g_scB);
    cudaGetSymbolAddress((void**)&p_hst,   g_hst);
    cudaGetSymbolAddress((void**)&p_hsh,   g_hsh);
    cudaGetSymbolAddress((void**)&p_quh,   g_quh);
    cudaGetSymbolAddress((void**)&p_w1h,   g_w1h);
    cudaGetSymbolAddress((void**)&p_w2h,   g_w2h);
    cudaGetSymbolAddress((void**)&p_w3h,   g_w3h);
    cudaGetSymbolAddress((void**)&p_w4h,   g_w4h);
    cudaGetSymbolAddress((void**)&p_xpwh,  g_xpwh);
    cudaGetSymbolAddress((void**)&p_xch,   g_xch);
    cudaGetSymbolAddress((void**)&p_xdinh, g_xdinh);
    cudaGetSymbolAddress((void**)&p_yh,    g_yh);

    cudaFuncSetAttribute(gemm_hf<0>, cudaFuncAttributeMaxDynamicSharedMemorySize, HSMEM);
    cudaFuncSetAttribute(gemm_hf<2>, cudaFuncAttributeMaxDynamicSharedMemorySize, HSMEM);
    cudaFuncSetAttribute(gemm_hf<3>, cudaFuncAttributeMaxDynamicSharedMemorySize, HSMEM);

    // 1) fused conversions: hs, query, in_proj_w
    {
        int n0 = NTOK * DMODEL / 8;
        int n1 = NTOK * DMODEL / 8;
        int n2 = 2 * DINNER * DMODEL / 8;
        int tot = n0 + n1 + n2;
        f2h3_kernel<<<(tot + 255) / 256, 256>>>(hs, p_hsh, n0,
                                                query, p_quh, n1,
                                                in_proj_w, p_w1h, n2);
    }
    // 2) fused conversions: query_w, out_proj_w
    {
        int n0 = DINNER * DMODEL / 8;
        int n1 = DMODEL * DINNER / 8;
        int tot = n0 + n1;
        f2h3_kernel<<<(tot + 255) / 256, 256>>>(query_w, p_w2h, n0,
                                                out_proj_w, p_w3h, n1,
                                                nullptr, nullptr, 0);
    }
    // 3) fused pads: dt weights + x_proj weights
    {
        int tot = DINNER * DTK + XPN * DINNER;
        padcomb_kernel<<<(tot + 255) / 256, 256>>>(dt_proj_w, p_w4h,
                                                   x_proj_w, p_xpwh);
    }

    // 4) xz = hs @ in_proj_w^T  (4096 x 3072, K=768)   [ncu captures this]
    gemm_hf<0><<<dim3(2 * DINNER / 128, NTOK / 128), 256, HSMEM>>>(
        p_hsh, p_w1h, nullptr, nullptr, p_xz, DMODEL, DMODEL, DMODEL, 0, 2 * DINNER);

    // 5) gate = silu(query @ query_w^T + b) * silu(z)  (4096 x 1536)
    gemm_hf<3><<<dim3(DINNER / 128, NTOK / 128), 256, HSMEM>>>(
        p_quh, p_w2h, query_b, p_xz + DINNER, p_gate,
        DMODEL, DMODEL, DMODEL, 2 * DINNER, DINNER);

    // 6) causal depthwise conv + silu (fp32 + fp16 outputs)
    {
        int total = NTOK * DINNER;
        conv_silu_kernel<<<(total + 255) / 256, 256>>>(
            p_xz, conv_w, conv_b, p_xc, p_xch);
    }

    // 7) x_dbl partials = xc @ x_proj_w^T (padded N=128, split-K=4)
    gemm_hf<0><<<dim3(1, NTOK / 128, XPSPLIT), 256, HSMEM>>>(
        p_xch, p_xpwh, nullptr, nullptr, p_xdp,
        DINNER / XPSPLIT, DINNER, DINNER, 0, XPN);

    // 8) reduce partials -> xdbl fp32 + padded fp16 dt input
    reduce_xdbl_kernel<<<(NTOK * XDBL_W + 255) / 256, 256>>>(p_xdp, p_xdbl, p_xdinh);

    // 9) dt = softplus(xdin @ w4^T + dt_proj_b)  (K=64 padded)
    gemm_hf<2><<<dim3(DINNER / 128, NTOK / 128), 256, HSMEM>>>(
        p_xdinh, p_w4h, dt_proj_b, nullptr, p_dt, DTK, DTK, DTK, 0, DINNER);

    // 10-12) chunked selective scan
    scanA_kernel<<<dim3(NCHAN / 32, NCH), 128>>>(
        p_dt, p_xc, p_xdbl, A_log, p_scA, p_scB);
    scanB_kernel<<<(NCHAN * DSTATE + 255) / 256, 256>>>(p_scA, p_scB, p_hst);
    scanC_kernel<<<dim3(NCHAN / 32, NCH), 128>>>(
        p_xdbl, p_dt, p_xc, p_gate, A_log, Dvec, p_hst, p_yh);

    // 13) out = y @ out_proj_w^T  (4096 x 768, K=1536)
    gemm_hf<0><<<dim3(DMODEL / 128, NTOK / 128), 256, HSMEM>>>(
        p_yh, p_w3h, nullptr, nullptr, out, DINNER, DINNER, DINNER, 0, DMODEL);
}

// round 16
// speedup vs baseline: 13.7957x; 1.0193x over previous
#include <cuda_runtime.h>
#include <cuda_fp16.h>
#include <cstdint>

// Problem constants
#define DMODEL   768
#define DSTATE   16
#define DCONV    4
#define DINNER   1536
#define DTRANK   48
#define NBATCH   2
#define SEQLEN   2048
#define NTOK     (NBATCH * SEQLEN)        // 4096
#define XDBL_W   (DTRANK + 2 * DSTATE)    // 80
#define XPN      128                       // padded N for x_proj gemm
#define XPSPLIT  4                         // split-K for x_proj gemm
#define DTK      64                        // padded K for dt gemm
#define NCHAN    (NBATCH * DINNER)         // 3072 scan channels
#define CH_T     128                       // timesteps per scan chunk
#define NCH      (SEQLEN / CH_T)           // 16 chunks
#define SUB      32                        // staging sub-chunk

// -------- scratch (static device globals; no runtime allocation) ----------
__device__ float  g_xz   [NTOK * 2 * DINNER];
__device__ float  g_gate [NTOK * DINNER];          // silu(q)*silu(z)
__device__ float  g_xc   [NTOK * DINNER];
__device__ float  g_xdbl [NTOK * XDBL_W];
__device__ float  g_xdp  [XPSPLIT * NTOK * XPN];   // x_proj split-K partials
__device__ float  g_dt   [NTOK * DINNER];
__device__ float  g_scA  [NCH * NCHAN * DSTATE];   // per-chunk prod(a)
__device__ float  g_scB  [NCH * NCHAN * DSTATE];   // per-chunk local state
__device__ float  g_hst  [NCH * NCHAN * DSTATE];   // chunk-start states
// fp16 GEMM operands
__device__ __half g_hsh  [NTOK * DMODEL];
__device__ __half g_quh  [NTOK * DMODEL];
__device__ __half g_w1h  [2 * DINNER * DMODEL];
__device__ __half g_w2h  [DINNER * DMODEL];
__device__ __half g_w3h  [DMODEL * DINNER];
__device__ __half g_w4h  [DINNER * DTK];
__device__ __half g_xpwh [XPN * DINNER];           // padded x_proj weights
__device__ __half g_xch  [NTOK * DINNER];          // fp16 conv output
__device__ __half g_xdinh[NTOK * DTK];
__device__ __half g_yh   [NTOK * DINNER];

// -------------------------- helpers ---------------------------------------
__device__ __forceinline__ float silu_f(float x) {
    return x / (1.0f + __expf(-x));
}
__device__ __forceinline__ float softplus_f(float x) {
    return (x > 20.0f) ? x : log1pf(__expf(x));
}
// .cg = bypass L1 (no L1 reuse for streamed tiles)
__device__ __forceinline__ void cp16(void* s, const void* g) {
    uint32_t sa = (uint32_t)__cvta_generic_to_shared(s);
    asm volatile("cp.async.cg.shared.global [%0], [%1], 16;" :: "r"(sa), "l"(g));
}
__device__ __forceinline__ void cp16s(uint32_t saddr, const void* g) {
    asm volatile("cp.async.cg.shared.global [%0], [%1], 16;" :: "r"(saddr), "l"(g));
}
__device__ __forceinline__ void cp_commit() {
    asm volatile("cp.async.commit_group;" ::: "memory");
}
__device__ __forceinline__ void ldsm_x4(uint32_t* r, uint32_t addr) {
    asm volatile("ldmatrix.sync.aligned.m8n8.x4.shared.b16 {%0,%1,%2,%3}, [%4];"
                 : "=r"(r[0]), "=r"(r[1]), "=r"(r[2]), "=r"(r[3]) : "r"(addr));
}
__device__ __forceinline__ void mma_f16(float* d, const uint32_t* a, const uint32_t* b) {
    asm volatile(
        "mma.sync.aligned.m16n8k16.row.col.f32.f16.f16.f32 "
        "{%0,%1,%2,%3}, {%4,%5,%6,%7}, {%8,%9}, {%0,%1,%2,%3};\n"
        : "+f"(d[0]), "+f"(d[1]), "+f"(d[2]), "+f"(d[3])
        : "r"(a[0]), "r"(a[1]), "r"(a[2]), "r"(a[3]), "r"(b[0]), "r"(b[1]));
}

// ---------------- fused prep: 5 conversions + 2 padded conversions ---------
__device__ __forceinline__ void f2h8(const float* in, __half* out, int j) {
    float4 v0 = ((const float4*)in)[2 * j];
    float4 v1 = ((const float4*)in)[2 * j + 1];
    __half2 hp[4];
    hp[0] = __floats2half2_rn(v0.x, v0.y);
    hp[1] = __floats2half2_rn(v0.z, v0.w);
    hp[2] = __floats2half2_rn(v1.x, v1.y);
    hp[3] = __floats2half2_rn(v1.z, v1.w);
    ((uint4*)out)[j] = *(const uint4*)hp;
}

#define PREP_N0 (NTOK * DMODEL / 8)            // hs
#define PREP_N1 (NTOK * DMODEL / 8)            // query
#define PREP_N2 (2 * DINNER * DMODEL / 8)      // in_proj_w
#define PREP_N3 (DINNER * DMODEL / 8)          // query_w
#define PREP_N4 (DMODEL * DINNER / 8)          // out_proj_w
#define PREP_F2H (PREP_N0 + PREP_N1 + PREP_N2 + PREP_N3 + PREP_N4)
#define PREP_P4  (DINNER * DTK)                // dt-weight pad (per element)
#define PREP_PX  (XPN * DINNER)                // x_proj-weight pad (per element)
#define PREP_TOT (PREP_F2H + PREP_P4 + PREP_PX)

__global__ void prep_kernel(const float* hs, __half* hsh,
                            const float* qu, __half* quh,
                            const float* w1, __half* w1h,
                            const float* w2, __half* w2h,
                            const float* w3, __half* w3h,
                            const float* w4, __half* w4h,
                            const float* xw, __half* xwh)
{
    int i = blockIdx.x * blockDim.x + threadIdx.x;
    if (i < PREP_N0) { f2h8(hs, hsh, i); return; }
    i -= PREP_N0;
    if (i < PREP_N1) { f2h8(qu, quh, i); return; }
    i -= PREP_N1;
    if (i < PREP_N2) { f2h8(w1, w1h, i); return; }
    i -= PREP_N2;
    if (i < PREP_N3) { f2h8(w2, w2h, i); return; }
    i -= PREP_N3;
    if (i < PREP_N4) { f2h8(w3, w3h, i); return; }
    i -= PREP_N4;
    if (i < PREP_P4) {
        int row = i >> 6, col = i & 63;
        w4h[i] = (col < DTRANK) ? __float2half(w4[row * DTRANK + col])
                                : __float2half(0.0f);
        return;
    }
    i -= PREP_P4;
    if (i < PREP_PX) {
        int row = i / DINNER;
        xwh[i] = (row < XDBL_W) ? __float2half(xw[i]) : __float2half(0.0f);
    }
}

// ================= fp16 tensor-core GEMM: C = A * W^T + epi ================
// A: [M,K_total] half (lda), W: [N,K_total] half (ldw), C fp32 (ldc)
// CTA 128x128, BK=32, 8 warps (2Mx4N of 64x32), 4-stage cp.async, 1 sync/iter.
// Mainloop fragments software-pipelined: 10 of 12 LDSM issue before first MMA.
// EPI: 0 none; 1 +bias; 2 +bias,softplus; 3 silu(v+bias)*silu(Z[row][col])
#define HBK   32
#define HSTR  40
#define HAST  (128 * HSTR * 2)
#define HSTG  (2 * HAST)
#define HNST  4
#define HSMEM (HNST * HSTG)

template<int EPI>
__global__ void __launch_bounds__(256, 2)
gemm_hf(const __half* __restrict__ A, const __half* __restrict__ W,
        const float* __restrict__ bias, const float* __restrict__ Z,
        float* __restrict__ C,
        int K, int lda, int ldw, int ldz, int ldc)
{
    extern __shared__ char dynsmem[];
    const uint32_t sb = (uint32_t)__cvta_generic_to_shared(dynsmem);

    const int tid  = threadIdx.x;
    const int m0   = blockIdx.y * 128;
    const int n0   = blockIdx.x * 128;
    const int koff = blockIdx.z * K;
    const int warp = tid >> 5;
    const int lane = tid & 31;
    const int g    = lane >> 2;
    const int t    = lane & 3;
    const int wm   = (warp & 1) * 64;
    const int wn   = (warp >> 1) * 32;

    const int u   = lane & 7;
    const int grp = lane >> 3;

    uint32_t aA[4];
#pragma unroll
    for (int mt = 0; mt < 4; mt++) {
        int row  = wm + mt * 16 + (grp & 1) * 8 + u;
        int kofh = (grp >> 1) * 8;
        aA[mt] = (uint32_t)(row * HSTR + kofh) * 2u;
    }
    uint32_t aB[2];
#pragma unroll
    for (int p = 0; p < 2; p++) {
        int row  = wn + (2 * p + (grp >> 1)) * 8 + u;
        int kofh = (grp & 1) * 8;
        aB[p] = (uint32_t)HAST + (uint32_t)(row * HSTR + kofh) * 2u;
    }

    // loader: 64 rows/pass x 4 chunks of 8 halfs (16B) per 32-col row
    const int lr = tid >> 2;
    const int lc = (tid & 3) * 8;
    const int niter = K / HBK;

    const __half* Abase = A + (size_t)(m0 + lr) * lda + koff + lc;
    const __half* Wbase = W + (size_t)(n0 + lr) * ldw + koff + lc;
    const uint32_t dA0 = sb + (uint32_t)(lr * HSTR + lc) * 2u;
    const uint32_t dA1 = sb + (uint32_t)((lr + 64) * HSTR + lc) * 2u;
    const uint32_t dW0 = dA0 + HAST;
    const uint32_t dW1 = dA1 + HAST;

    auto stage_load = [&](int s, int kb) {
        const uint32_t so = (uint32_t)s * HSTG;
        const int k0 = kb * HBK;
        cp16s(dA0 + so, Abase + k0);
        cp16s(dA1 + so, Abase + k0 + (size_t)64 * lda);
        cp16s(dW0 + so, Wbase + k0);
        cp16s(dW1 + so, Wbase + k0 + (size_t)64 * ldw);
    };

    float acc[4][4][4];
#pragma unroll
    for (int mt = 0; mt < 4; mt++)
#pragma unroll
        for (int nt = 0; nt < 4; nt++)
#pragma unroll
            for (int i = 0; i < 4; i++) acc[mt][nt][i] = 0.0f;

#pragma unroll
    for (int s = 0; s < HNST - 1; s++) {
        if (s < niter) stage_load(s, s);
        cp_commit();
    }

    for (int it = 0; it < niter; it++) {
        asm volatile("cp.async.wait_group %0;" :: "n"(HNST - 2) : "memory");
        __syncthreads();

        const int pf = it + HNST - 1;
        if (pf < niter) stage_load(pf % HNST, pf);
        cp_commit();

        const uint32_t sOff = sb + (uint32_t)(it % HNST) * HSTG;
        const uint32_t k1   = sOff + 32u;     // kk=1 offset (16 halfs)

        uint32_t afr0[4][4], afr1[4][4];
        uint32_t bfr0[4][2], bfr1[4][2];

        // kk0 fragments (A + B)
#pragma unroll
        for (int mt = 0; mt < 4; mt++)
            ldsm_x4(afr0[mt], aA[mt] + sOff);
        {
            uint32_t r[4];
            ldsm_x4(r, aB[0] + sOff);
            bfr0[0][0] = r[0]; bfr0[0][1] = r[1];
            bfr0[1][0] = r[2]; bfr0[1][1] = r[3];
            ldsm_x4(r, aB[1] + sOff);
            bfr0[2][0] = r[0]; bfr0[2][1] = r[1];
            bfr0[3][0] = r[2]; bfr0[3][1] = r[3];
        }
        // kk1 A fragments early (hidden behind kk0 MMAs)
#pragma unroll
        for (int mt = 0; mt < 4; mt++)
            ldsm_x4(afr1[mt], aA[mt] + k1);

        // kk0 MMAs
#pragma unroll
        for (int mt = 0; mt < 4; mt++)
#pragma unroll
            for (int nt = 0; nt < 4; nt++)
                mma_f16(acc[mt][nt], afr0[mt], bfr0[nt]);

        // kk1 B fragments
        {
            uint32_t r[4];
            ldsm_x4(r, aB[0] + k1);
            bfr1[0][0] = r[0]; bfr1[0][1] = r[1];
            bfr1[1][0] = r[2]; bfr1[1][1] = r[3];
            ldsm_x4(r, aB[1] + k1);
            bfr1[2][0] = r[0]; bfr1[2][1] = r[1];
            bfr1[3][0] = r[2]; bfr1[3][1] = r[3];
        }

        // kk1 MMAs
#pragma unroll
        for (int mt = 0; mt < 4; mt++)
#pragma unroll
            for (int nt = 0; nt < 4; nt++)
                mma_f16(acc[mt][nt], afr1[mt], bfr1[nt]);
    }

    float* Cz = C + (size_t)blockIdx.z * NTOK * ldc;
#pragma unroll
    for (int mt = 0; mt < 4; mt++) {
#pragma unroll
        for (int nt = 0; nt < 4; nt++) {
            const int row = m0 + wm + mt * 16 + g;
            const int col = n0 + wn + nt * 8 + 2 * t;
            float v0 = acc[mt][nt][0];
            float v1 = acc[mt][nt][1];
            float v2 = acc[mt][nt][2];
            float v3 = acc[mt][nt][3];
            if (EPI >= 1) {
                const float b0 = bias[col];
                const float b1 = bias[col + 1];
                v0 += b0; v1 += b1; v2 += b0; v3 += b1;
            }
            if (EPI == 2) {
                v0 = softplus_f(v0); v1 = softplus_f(v1);
                v2 = softplus_f(v2); v3 = softplus_f(v3);
            }
            if (EPI == 3) {
                const float z0 = Z[(size_t)row * ldz + col];
                const float z1 = Z[(size_t)row * ldz + col + 1];
                const float z2 = Z[(size_t)(row + 8) * ldz + col];
                const float z3 = Z[(size_t)(row + 8) * ldz + col + 1];
                v0 = silu_f(v0) * silu_f(z0);
                v1 = silu_f(v1) * silu_f(z1);
                v2 = silu_f(v2) * silu_f(z2);
                v3 = silu_f(v3) * silu_f(z3);
            }
            float2* p0 = (float2*)&Cz[(size_t)row * ldc + col];
            float2* p1 = (float2*)&Cz[(size_t)(row + 8) * ldc + col];
            *p0 = make_float2(v0, v1);
            *p1 = make_float2(v2, v3);
        }
    }
}

// reduce x_proj split-K partials; emit xdbl fp32 + padded fp16 dt-gemm input
__global__ void reduce_xdbl_kernel(const float* __restrict__ part,
                                   float* __restrict__ out,
                                   __half* __restrict__ outp)
{
    int i = blockIdx.x * 256 + threadIdx.x;
    if (i < NTOK * XDBL_W) {
        int row = i / XDBL_W, col = i % XDBL_W;
        float s = 0.0f;
#pragma unroll
        for (int z = 0; z < XPSPLIT; z++)
            s += part[(size_t)z * NTOK * XPN + (size_t)row * XPN + col];
        out[i] = s;
        if (col < DTRANK)   outp[row * DTK + col] = __float2half(s);
        else if (col < DTK) outp[row * DTK + col] = __float2half(0.0f);
    }
}

// ------------- causal depthwise conv (4 taps) + silu (fp32 + fp16) ---------
__global__ void conv_silu_kernel(const float* __restrict__ xz,
                                 const float* __restrict__ conv_w,
                                 const float* __restrict__ conv_b,
                                 float* __restrict__ xc,
                                 __half* __restrict__ xch)
{
    int idx = blockIdx.x * blockDim.x + threadIdx.x;
    if (idx >= NTOK * DINNER) return;
    int d   = idx % DINNER;
    int row = idx / DINNER;
    int l   = row & (SEQLEN - 1);
    int b   = row >> 11;

    float w0 = conv_w[d * DCONV + 0];
    float w1 = conv_w[d * DCONV + 1];
    float w2 = conv_w[d * DCONV + 2];
    float w3 = conv_w[d * DCONV + 3];

    float acc = conv_b[d];
    const size_t base = ((size_t)b * SEQLEN) * (2 * DINNER) + d;
    if (l >= 3) acc += w0 * xz[base + (size_t)(l - 3) * (2 * DINNER)];
    if (l >= 2) acc += w1 * xz[base + (size_t)(l - 2) * (2 * DINNER)];
    if (l >= 1) acc += w2 * xz[base + (size_t)(l - 1) * (2 * DINNER)];
    acc += w3 * xz[base + (size_t)l * (2 * DINNER)];

    float v = silu_f(acc);
    xc[idx]  = v;
    xch[idx] = __float2half(v);
}

// ============== chunked selective scan: 3 phases ===========================
// Warp layout: 8 channels x 4 lanes/channel x 4 states/lane.
// Block = 128 threads = 32 channels. Grid (NCHAN/32, NCH).

struct ScanASmem {
    float dt[2][SUB][32];
    float xc[2][SUB][32];
    float Bm[2][SUB][16];
};

__global__ void __launch_bounds__(128)
scanA_kernel(const float* __restrict__ dt, const float* __restrict__ xc,
             const float* __restrict__ xdbl, const float* __restrict__ A_log,
             float* __restrict__ gA, float* __restrict__ gB)
{
    __shared__ ScanASmem sm;
    const int tid  = threadIdx.x;
    const int cb   = tid >> 2;            // channel within block 0..31
    const int st4  = (tid & 3) * 4;       // first state of this thread
    const int c    = blockIdx.y;
    const int ch   = blockIdx.x * 32 + cb;
    const int b    = (blockIdx.x * 32) / DINNER;
    const int d0   = (blockIdx.x * 32) % DINNER;
    const int d    = d0 + cb;

    float4 Alg = *(const float4*)&A_log[d * DSTATE + st4];
    const float4 An = make_float4(-__expf(Alg.x), -__expf(Alg.y),
                                  -__expf(Alg.z), -__expf(Alg.w));
    const int row0 = b * SEQLEN + c * CH_T;

    const int rA = tid >> 2;
    const int cA = (tid & 3) * 8;
    const int cB = (tid & 3) * 4;

    auto stage = [&](int sc, int s) {
        const size_t r = (size_t)(row0 + sc * SUB + rA);
        cp16(&sm.dt[s][rA][cA],     &dt[r * DINNER + d0 + cA]);
        cp16(&sm.dt[s][rA][cA + 4], &dt[r * DINNER + d0 + cA + 4]);
        cp16(&sm.xc[s][rA][cA],     &xc[r * DINNER + d0 + cA]);
        cp16(&sm.xc[s][rA][cA + 4], &xc[r * DINNER + d0 + cA + 4]);
        cp16(&sm.Bm[s][rA][cB],     &xdbl[r * XDBL_W + DTRANK + cB]);
        cp_commit();
    };

    float4 Ap = make_float4(1.f, 1.f, 1.f, 1.f);
    float4 hB = make_float4(0.f, 0.f, 0.f, 0.f);

    stage(0, 0);
    for (int sc = 0; sc < CH_T / SUB; sc++) {
        const int s = sc & 1;
        if (sc + 1 < CH_T / SUB) {
            stage(sc + 1, s ^ 1);
            asm volatile("cp.async.wait_group 1;" ::: "memory");
        } else {
            asm volatile("cp.async.wait_group 0;" ::: "memory");
        }
        __syncthreads();

#pragma unroll 4
        for (int l = 0; l < SUB; l++) {
            const float dtv = sm.dt[s][l][cb];
            const float xv  = sm.xc[s][l][cb];
            const float4 Bv = *(const float4*)&sm.Bm[s][l][st4];
            const float u = dtv * xv;
            const float a0 = __expf(dtv * An.x);
            const float a1 = __expf(dtv * An.y);
            const float a2 = __expf(dtv * An.z);
            const float a3 = __expf(dtv * An.w);
            hB.x = fmaf(a0, hB.x, u * Bv.x);
            hB.y = fmaf(a1, hB.y, u * Bv.y);
            hB.z = fmaf(a2, hB.z, u * Bv.z);
            hB.w = fmaf(a3, hB.w, u * Bv.w);
            Ap.x *= a0; Ap.y *= a1; Ap.z *= a2; Ap.w *= a3;
        }
        __syncthreads();
    }

    const size_t o = ((size_t)c * NCHAN + ch) * DSTATE + st4;
    *(float4*)&gA[o] = Ap;
    *(float4*)&gB[o] = hB;
}

__global__ void scanB_kernel(const float* __restrict__ gA,
                             const float* __restrict__ gB,
                             float* __restrict__ hst)
{
    int idx = blockIdx.x * 256 + threadIdx.x;
    if (idx >= NCHAN * DSTATE) return;
    float h = 0.0f;
#pragma unroll
    for (int c = 0; c < NCH; c++) {
        const size_t o = (size_t)c * (NCHAN * DSTATE) + idx;
        hst[o] = h;
        h = fmaf(gA[o], h, gB[o]);
    }
}

struct ScanCSmem {
    float dt[2][SUB][32];
    float xc[2][SUB][32];
    float gt[2][SUB][32];
    float Bm[2][SUB][16];
    float Cm[2][SUB][16];
};

__global__ void __launch_bounds__(128)
scanC_kernel(const float* __restrict__ xdbl, const float* __restrict__ dt,
             const float* __restrict__ xc,   const float* __restrict__ gate,
             const float* __restrict__ A_log, const float* __restrict__ Dvec,
             const float* __restrict__ hst,  __half* __restrict__ yout)
{
    __shared__ ScanCSmem sm;
    const int tid  = threadIdx.x;
    const int cb   = tid >> 2;
    const int st4  = (tid & 3) * 4;
    const int c    = blockIdx.y;
    const int ch   = blockIdx.x * 32 + cb;
    const int b    = (blockIdx.x * 32) / DINNER;
    const int d0   = (blockIdx.x * 32) % DINNER;
    const int d    = d0 + cb;

    float4 Alg = *(const float4*)&A_log[d * DSTATE + st4];
    const float4 An = make_float4(-__expf(Alg.x), -__expf(Alg.y),
                                  -__expf(Alg.z), -__expf(Alg.w));
    const float Dd = Dvec[d];
    const int row0 = b * SEQLEN + c * CH_T;

    const int rA = tid >> 2;
    const int cA = (tid & 3) * 8;
    const int cB = (tid & 3) * 4;

    auto stage = [&](int sc, int s) {
        const size_t r = (size_t)(row0 + sc * SUB + rA);
        cp16(&sm.dt[s][rA][cA],     &dt  [r * DINNER + d0 + cA]);
        cp16(&sm.dt[s][rA][cA + 4], &dt  [r * DINNER + d0 + cA + 4]);
        cp16(&sm.xc[s][rA][cA],     &xc  [r * DINNER + d0 + cA]);
        cp16(&sm.xc[s][rA][cA + 4], &xc  [r * DINNER + d0 + cA + 4]);
        cp16(&sm.gt[s][rA][cA],     &gate[r * DINNER + d0 + cA]);
        cp16(&sm.gt[s][rA][cA + 4], &gate[r * DINNER + d0 + cA + 4]);
        cp16(&sm.Bm[s][rA][cB],     &xdbl[r * XDBL_W + DTRANK + cB]);
        cp16(&sm.Cm[s][rA][cB],     &xdbl[r * XDBL_W + DTRANK + DSTATE + cB]);
        cp_commit();
    };

    float4 h = *(const float4*)&hst[((size_t)c * NCHAN + ch) * DSTATE + st4];

    stage(0, 0);
    for (int sc = 0; sc < CH_T / SUB; sc++) {
        const int s = sc & 1;
        if (sc + 1 < CH_T / SUB) {
            stage(sc + 1, s ^ 1);
            asm volatile("cp.async.wait_group 1;" ::: "memory");
        } else {
            asm volatile("cp.async.wait_group 0;" ::: "memory");
        }
        __syncthreads();

#pragma unroll 4
        for (int l = 0; l < SUB; l++) {
            const float dtv = sm.dt[s][l][cb];
            const float xv  = sm.xc[s][l][cb];
            const float4 Bv = *(const float4*)&sm.Bm[s][l][st4];
            const float4 Cv = *(const float4*)&sm.Cm[s][l][st4];
            const float u = dtv * xv;
            h.x = fmaf(__expf(dtv * An.x), h.x, u * Bv.x);
            h.y = fmaf(__expf(dtv * An.y), h.y, u * Bv.y);
            h.z = fmaf(__expf(dtv * An.z), h.z, u * Bv.z);
            h.w = fmaf(__expf(dtv * An.w), h.w, u * Bv.w);

            float p = h.x * Cv.x + h.y * Cv.y + h.z * Cv.z + h.w * Cv.w;
            p += __shfl_xor_sync(0xffffffffu, p, 1);
            p += __shfl_xor_sync(0xffffffffu, p, 2);

            if ((tid & 3) == 0) {
                const float y = (p + xv * Dd) * sm.gt[s][l][cb];
                yout[(size_t)(row0 + sc * SUB + l) * DINNER + d] = __float2half(y);
            }
        }
        __syncthreads();
    }
}

// --------------------------------- host ------------------------------------
extern "C" void kernel_launch(void* const* d_in, const int* in_sizes, int n_in,
                              void* d_out, int out_size)
{
    const float* hs         = (const float*)d_in[0];
    const float* query      = (const float*)d_in[1];
    const float* in_proj_w  = (const float*)d_in[2];
    const float* conv_w     = (const float*)d_in[3];
    const float* conv_b     = (const float*)d_in[4];
    const float* x_proj_w   = (const float*)d_in[5];
    const float* dt_proj_w  = (const float*)d_in[6];
    const float* dt_proj_b  = (const float*)d_in[7];
    const float* A_log      = (const float*)d_in[8];
    const float* Dvec       = (const float*)d_in[9];
    const float* query_w    = (const float*)d_in[10];
    const float* query_b    = (const float*)d_in[11];
    const float* out_proj_w = (const float*)d_in[12];
    float* out = (float*)d_out;

    float  *p_xz, *p_gate, *p_xc, *p_xdbl, *p_xdp, *p_dt, *p_scA, *p_scB, *p_hst;
    __half *p_hsh, *p_quh, *p_w1h, *p_w2h, *p_w3h, *p_w4h;
    __half *p_xpwh, *p_xch, *p_xdinh, *p_yh;
    cudaGetSymbolAddress((void**)&p_xz,    g_xz);
    cudaGetSymbolAddress((void**)&p_gate,  g_gate);
    cudaGetSymbolAddress((void**)&p_xc,    g_xc);
    cudaGetSymbolAddress((void**)&p_xdbl,  g_xdbl);
    cudaGetSymbolAddress((void**)&p_xdp,   g_xdp);
    cudaGetSymbolAddress((void**)&p_dt,    g_dt);
    cudaGetSymbolAddress((void**)&p_scA,   g_scA);
    cudaGetSymbolAddress((void**)&p_scB,   g_scB);
    cudaGetSymbolAddress((void**)&p_hst,   g_hst);
    cudaGetSymbolAddress((void**)&p_hsh,   g_hsh);
    cudaGetSymbolAddress((void**)&p_quh,   g_quh);
    cudaGetSymbolAddress((void**)&p_w1h,   g_w1h);
    cudaGetSymbolAddress((void**)&p_w2h,   g_w2h);
    cudaGetSymbolAddress((void**)&p_w3h,   g_w3h);
    cudaGetSymbolAddress((void**)&p_w4h,   g_w4h);
    cudaGetSymbolAddress((void**)&p_xpwh,  g_xpwh);
    cudaGetSymbolAddress((void**)&p_xch,   g_xch);
    cudaGetSymbolAddress((void**)&p_xdinh, g_xdinh);
    cudaGetSymbolAddress((void**)&p_yh,    g_yh);

    cudaFuncSetAttribute(gemm_hf<0>, cudaFuncAttributeMaxDynamicSharedMemorySize, HSMEM);
    cudaFuncSetAttribute(gemm_hf<2>, cudaFuncAttributeMaxDynamicSharedMemorySize, HSMEM);
    cudaFuncSetAttribute(gemm_hf<3>, cudaFuncAttributeMaxDynamicSharedMemorySize, HSMEM);

    // 1) fused prep: all 5 fp32->fp16 conversions + 2 padded conversions
    prep_kernel<<<(PREP_TOT + 255) / 256, 256>>>(
        hs, p_hsh, query, p_quh, in_proj_w, p_w1h,
        query_w, p_w2h, out_proj_w, p_w3h,
        dt_proj_w, p_w4h, x_proj_w, p_xpwh);

    // 2) xz = hs @ in_proj_w^T  (4096 x 3072, K=768)
    gemm_hf<0><<<dim3(2 * DINNER / 128, NTOK / 128), 256, HSMEM>>>(
        p_hsh, p_w1h, nullptr, nullptr, p_xz, DMODEL, DMODEL, DMODEL, 0, 2 * DINNER);

    // 3) gate = silu(query @ query_w^T + b) * silu(z)  (4096 x 1536)
    gemm_hf<3><<<dim3(DINNER / 128, NTOK / 128), 256, HSMEM>>>(
        p_quh, p_w2h, query_b, p_xz + DINNER, p_gate,
        DMODEL, DMODEL, DMODEL, 2 * DINNER, DINNER);

    // 4) causal depthwise conv + silu (fp32 + fp16 outputs)  [ncu captures #4]
    {
        int total = NTOK * DINNER;
        conv_silu_kernel<<<(total + 255) / 256, 256>>>(
            p_xz, conv_w, conv_b, p_xc, p_xch);
    }

    // 5) x_dbl partials = xc @ x_proj_w^T (padded N=128, split-K=4)
    gemm_hf<0><<<dim3(1, NTOK / 128, XPSPLIT), 256, HSMEM>>>(
        p_xch, p_xpwh, nullptr, nullptr, p_xdp,
        DINNER / XPSPLIT, DINNER, DINNER, 0, XPN);

    // 6) reduce partials -> xdbl fp32 + padded fp16 dt input
    reduce_xdbl_kernel<<<(NTOK * XDBL_W + 255) / 256, 256>>>(p_xdp, p_xdbl, p_xdinh);

    // 7) dt = softplus(xdin @ w4^T + dt_proj_b)  (K=64 padded)
    gemm_hf<2><<<dim3(DINNER / 128, NTOK / 128), 256, HSMEM>>>(
        p_xdinh, p_w4h, dt_proj_b, nullptr, p_dt, DTK, DTK, DTK, 0, DINNER);

    // 8-10) chunked selective scan
    scanA_kernel<<<dim3(NCHAN / 32, NCH), 128>>>(
        p_dt, p_xc, p_xdbl, A_log, p_scA, p_scB);
    scanB_kernel<<<(NCHAN * DSTATE + 255) / 256, 256>>>(p_scA, p_scB, p_hst);
    scanC_kernel<<<dim3(NCHAN / 32, NCH), 128>>>(
        p_xdbl, p_dt, p_xc, p_gate, A_log, Dvec, p_hst, p_yh);

    // 11) out = y @ out_proj_w^T  (4096 x 768, K=1536)
    gemm_hf<0><<<dim3(DMODEL / 128, NTOK / 128), 256, HSMEM>>>(
        p_yh, p_w3h, nullptr, nullptr, out, DINNER, DINNER, DINNER, 0, DMODEL);
}

// round 17
// speedup vs baseline: 14.4288x; 1.0459x over previous
#include <cuda_runtime.h>
#include <cuda_fp16.h>
#include <cstdint>

// Problem constants
#define DMODEL   768
#define DSTATE   16
#define DCONV    4
#define DINNER   1536
#define DTRANK   48
#define NBATCH   2
#define SEQLEN   2048
#define NTOK     (NBATCH * SEQLEN)        // 4096
#define XDBL_W   (DTRANK + 2 * DSTATE)    // 80
#define XPN      128                       // padded N for x_proj gemm
#define XPSPLIT  4                         // split-K for x_proj gemm
#define DTK      64                        // padded K for dt gemm
#define NCHAN    (NBATCH * DINNER)         // 3072 scan channels
#define CH_T     128                       // timesteps per scan chunk
#define NCH      (SEQLEN / CH_T)           // 16 chunks
#define SUB      32                        // staging sub-chunk

// -------- scratch (static device globals; no runtime allocation) ----------
__device__ float  g_xz   [NTOK * 2 * DINNER];
__device__ float  g_gate [NTOK * DINNER];          // silu(q)*silu(z)
__device__ float  g_xc   [NTOK * DINNER];
__device__ float  g_xdbl [NTOK * XDBL_W];
__device__ float  g_xdp  [XPSPLIT * NTOK * XPN];   // x_proj split-K partials
__device__ float  g_dt   [NTOK * DINNER];
__device__ float  g_scA  [NCH * NCHAN * DSTATE];   // per-chunk prod(a)
__device__ float  g_scB  [NCH * NCHAN * DSTATE];   // per-chunk local state
__device__ float  g_hst  [NCH * NCHAN * DSTATE];   // chunk-start states
// fp16 GEMM operands
__device__ __half g_hsh  [NTOK * DMODEL];
__device__ __half g_quh  [NTOK * DMODEL];
__device__ __half g_w1h  [2 * DINNER * DMODEL];
__device__ __half g_w2h  [DINNER * DMODEL];
__device__ __half g_w3h  [DMODEL * DINNER];
__device__ __half g_w4h  [DINNER * DTK];
__device__ __half g_xpwh [XPN * DINNER];           // padded x_proj weights
__device__ __half g_xch  [NTOK * DINNER];          // fp16 conv output
__device__ __half g_xdinh[NTOK * DTK];
__device__ __half g_yh   [NTOK * DINNER];

// -------------------------- helpers ---------------------------------------
__device__ __forceinline__ float silu_f(float x) {
    return x / (1.0f + __expf(-x));
}
__device__ __forceinline__ float softplus_f(float x) {
    return (x > 20.0f) ? x : log1pf(__expf(x));
}
// .cg = bypass L1 (no L1 reuse for streamed tiles)
__device__ __forceinline__ void cp16(void* s, const void* g) {
    uint32_t sa = (uint32_t)__cvta_generic_to_shared(s);
    asm volatile("cp.async.cg.shared.global [%0], [%1], 16;" :: "r"(sa), "l"(g));
}
__device__ __forceinline__ void cp16s(uint32_t saddr, const void* g) {
    asm volatile("cp.async.cg.shared.global [%0], [%1], 16;" :: "r"(saddr), "l"(g));
}
__device__ __forceinline__ void cp_commit() {
    asm volatile("cp.async.commit_group;" ::: "memory");
}
__device__ __forceinline__ void ldsm_x4(uint32_t* r, uint32_t addr) {
    asm volatile("ldmatrix.sync.aligned.m8n8.x4.shared.b16 {%0,%1,%2,%3}, [%4];"
                 : "=r"(r[0]), "=r"(r[1]), "=r"(r[2]), "=r"(r[3]) : "r"(addr));
}
__device__ __forceinline__ void mma_f16(float* d, const uint32_t* a, const uint32_t* b) {
    asm volatile(
        "mma.sync.aligned.m16n8k16.row.col.f32.f16.f16.f32 "
        "{%0,%1,%2,%3}, {%4,%5,%6,%7}, {%8,%9}, {%0,%1,%2,%3};\n"
        : "+f"(d[0]), "+f"(d[1]), "+f"(d[2]), "+f"(d[3])
        : "r"(a[0]), "r"(a[1]), "r"(a[2]), "r"(a[3]), "r"(b[0]), "r"(b[1]));
}

// ---------------- fused prep: 5 conversions + 2 padded conversions ---------
__device__ __forceinline__ void f2h8(const float* in, __half* out, int j) {
    float4 v0 = ((const float4*)in)[2 * j];
    float4 v1 = ((const float4*)in)[2 * j + 1];
    __half2 hp[4];
    hp[0] = __floats2half2_rn(v0.x, v0.y);
    hp[1] = __floats2half2_rn(v0.z, v0.w);
    hp[2] = __floats2half2_rn(v1.x, v1.y);
    hp[3] = __floats2half2_rn(v1.z, v1.w);
    ((uint4*)out)[j] = *(const uint4*)hp;
}

#define PREP_N0 (NTOK * DMODEL / 8)            // hs
#define PREP_N1 (NTOK * DMODEL / 8)            // query
#define PREP_N2 (2 * DINNER * DMODEL / 8)      // in_proj_w
#define PREP_N3 (DINNER * DMODEL / 8)          // query_w
#define PREP_N4 (DMODEL * DINNER / 8)          // out_proj_w
#define PREP_F2H (PREP_N0 + PREP_N1 + PREP_N2 + PREP_N3 + PREP_N4)
#define PREP_P4  (DINNER * DTK)                // dt-weight pad (per element)
#define PREP_PX  (XPN * DINNER)                // x_proj-weight pad (per element)
#define PREP_TOT (PREP_F2H + PREP_P4 + PREP_PX)

__global__ void prep_kernel(const float* hs, __half* hsh,
                            const float* qu, __half* quh,
                            const float* w1, __half* w1h,
                            const float* w2, __half* w2h,
                            const float* w3, __half* w3h,
                            const float* w4, __half* w4h,
                            const float* xw, __half* xwh)
{
    int i = blockIdx.x * blockDim.x + threadIdx.x;
    if (i < PREP_N0) { f2h8(hs, hsh, i); return; }
    i -= PREP_N0;
    if (i < PREP_N1) { f2h8(qu, quh, i); return; }
    i -= PREP_N1;
    if (i < PREP_N2) { f2h8(w1, w1h, i); return; }
    i -= PREP_N2;
    if (i < PREP_N3) { f2h8(w2, w2h, i); return; }
    i -= PREP_N3;
    if (i < PREP_N4) { f2h8(w3, w3h, i); return; }
    i -= PREP_N4;
    if (i < PREP_P4) {
        int row = i >> 6, col = i & 63;
        w4h[i] = (col < DTRANK) ? __float2half(w4[row * DTRANK + col])
                                : __float2half(0.0f);
        return;
    }
    i -= PREP_P4;
    if (i < PREP_PX) {
        int row = i / DINNER;
        xwh[i] = (row < XDBL_W) ? __float2half(xw[i]) : __float2half(0.0f);
    }
}

// ================= fp16 tensor-core GEMM: C = A * W^T + epi ================
// A: [M,K_total] half (lda), W: [N,K_total] half (ldw), C fp32 (ldc)
// CTA 128x128, BK=32, 8 warps (2Mx4N of 64x32), 4-stage cp.async, 1 sync/iter.
// Mainloop fragments software-pipelined: 10 of 12 LDSM issue before first MMA.
// EPI: 0 none; 1 +bias; 2 +bias,softplus; 3 silu(v+bias)*silu(Z[row][col])
#define HBK   32
#define HSTR  40
#define HAST  (128 * HSTR * 2)
#define HSTG  (2 * HAST)
#define HNST  4
#define HSMEM (HNST * HSTG)

template<int EPI>
__global__ void __launch_bounds__(256, 2)
gemm_hf(const __half* __restrict__ A, const __half* __restrict__ W,
        const float* __restrict__ bias, const float* __restrict__ Z,
        float* __restrict__ C,
        int K, int lda, int ldw, int ldz, int ldc)
{
    extern __shared__ char dynsmem[];
    const uint32_t sb = (uint32_t)__cvta_generic_to_shared(dynsmem);

    const int tid  = threadIdx.x;
    const int m0   = blockIdx.y * 128;
    const int n0   = blockIdx.x * 128;
    const int koff = blockIdx.z * K;
    const int warp = tid >> 5;
    const int lane = tid & 31;
    const int g    = lane >> 2;
    const int t    = lane & 3;
    const int wm   = (warp & 1) * 64;
    const int wn   = (warp >> 1) * 32;

    const int u   = lane & 7;
    const int grp = lane >> 3;

    uint32_t aA[4];
#pragma unroll
    for (int mt = 0; mt < 4; mt++) {
        int row  = wm + mt * 16 + (grp & 1) * 8 + u;
        int kofh = (grp >> 1) * 8;
        aA[mt] = (uint32_t)(row * HSTR + kofh) * 2u;
    }
    uint32_t aB[2];
#pragma unroll
    for (int p = 0; p < 2; p++) {
        int row  = wn + (2 * p + (grp >> 1)) * 8 + u;
        int kofh = (grp & 1) * 8;
        aB[p] = (uint32_t)HAST + (uint32_t)(row * HSTR + kofh) * 2u;
    }

    // loader: 64 rows/pass x 4 chunks of 8 halfs (16B) per 32-col row
    const int lr = tid >> 2;
    const int lc = (tid & 3) * 8;
    const int niter = K / HBK;

    const __half* Abase = A + (size_t)(m0 + lr) * lda + koff + lc;
    const __half* Wbase = W + (size_t)(n0 + lr) * ldw + koff + lc;
    const uint32_t dA0 = sb + (uint32_t)(lr * HSTR + lc) * 2u;
    const uint32_t dA1 = sb + (uint32_t)((lr + 64) * HSTR + lc) * 2u;
    const uint32_t dW0 = dA0 + HAST;
    const uint32_t dW1 = dA1 + HAST;

    auto stage_load = [&](int s, int kb) {
        const uint32_t so = (uint32_t)s * HSTG;
        const int k0 = kb * HBK;
        cp16s(dA0 + so, Abase + k0);
        cp16s(dA1 + so, Abase + k0 + (size_t)64 * lda);
        cp16s(dW0 + so, Wbase + k0);
        cp16s(dW1 + so, Wbase + k0 + (size_t)64 * ldw);
    };

    float acc[4][4][4];
#pragma unroll
    for (int mt = 0; mt < 4; mt++)
#pragma unroll
        for (int nt = 0; nt < 4; nt++)
#pragma unroll
            for (int i = 0; i < 4; i++) acc[mt][nt][i] = 0.0f;

#pragma unroll
    for (int s = 0; s < HNST - 1; s++) {
        if (s < niter) stage_load(s, s);
        cp_commit();
    }

    for (int it = 0; it < niter; it++) {
        asm volatile("cp.async.wait_group %0;" :: "n"(HNST - 2) : "memory");
        __syncthreads();

        const int pf = it + HNST - 1;
        if (pf < niter) stage_load(pf % HNST, pf);
        cp_commit();

        const uint32_t sOff = sb + (uint32_t)(it % HNST) * HSTG;
        const uint32_t k1   = sOff + 32u;     // kk=1 offset (16 halfs)

        uint32_t afr0[4][4], afr1[4][4];
        uint32_t bfr0[4][2], bfr1[4][2];

        // kk0 fragments (A + B)
#pragma unroll
        for (int mt = 0; mt < 4; mt++)
            ldsm_x4(afr0[mt], aA[mt] + sOff);
        {
            uint32_t r[4];
            ldsm_x4(r, aB[0] + sOff);
            bfr0[0][0] = r[0]; bfr0[0][1] = r[1];
            bfr0[1][0] = r[2]; bfr0[1][1] = r[3];
            ldsm_x4(r, aB[1] + sOff);
            bfr0[2][0] = r[0]; bfr0[2][1] = r[1];
            bfr0[3][0] = r[2]; bfr0[3][1] = r[3];
        }
        // kk1 A fragments early (hidden behind kk0 MMAs)
#pragma unroll
        for (int mt = 0; mt < 4; mt++)
            ldsm_x4(afr1[mt], aA[mt] + k1);

        // kk0 MMAs
#pragma unroll
        for (int mt = 0; mt < 4; mt++)
#pragma unroll
            for (int nt = 0; nt < 4; nt++)
                mma_f16(acc[mt][nt], afr0[mt], bfr0[nt]);

        // kk1 B fragments
        {
            uint32_t r[4];
            ldsm_x4(r, aB[0] + k1);
            bfr1[0][0] = r[0]; bfr1[0][1] = r[1];
            bfr1[1][0] = r[2]; bfr1[1][1] = r[3];
            ldsm_x4(r, aB[1] + k1);
            bfr1[2][0] = r[0]; bfr1[2][1] = r[1];
            bfr1[3][0] = r[2]; bfr1[3][1] = r[3];
        }

        // kk1 MMAs
#pragma unroll
        for (int mt = 0; mt < 4; mt++)
#pragma unroll
            for (int nt = 0; nt < 4; nt++)
                mma_f16(acc[mt][nt], afr1[mt], bfr1[nt]);
    }

    float* Cz = C + (size_t)blockIdx.z * NTOK * ldc;
#pragma unroll
    for (int mt = 0; mt < 4; mt++) {
#pragma unroll
        for (int nt = 0; nt < 4; nt++) {
            const int row = m0 + wm + mt * 16 + g;
            const int col = n0 + wn + nt * 8 + 2 * t;
            float v0 = acc[mt][nt][0];
            float v1 = acc[mt][nt][1];
            float v2 = acc[mt][nt][2];
            float v3 = acc[mt][nt][3];
            if (EPI >= 1) {
                const float b0 = bias[col];
                const float b1 = bias[col + 1];
                v0 += b0; v1 += b1; v2 += b0; v3 += b1;
            }
            if (EPI == 2) {
                v0 = softplus_f(v0); v1 = softplus_f(v1);
                v2 = softplus_f(v2); v3 = softplus_f(v3);
            }
            if (EPI == 3) {
                const float z0 = Z[(size_t)row * ldz + col];
                const float z1 = Z[(size_t)row * ldz + col + 1];
                const float z2 = Z[(size_t)(row + 8) * ldz + col];
                const float z3 = Z[(size_t)(row + 8) * ldz + col + 1];
                v0 = silu_f(v0) * silu_f(z0);
                v1 = silu_f(v1) * silu_f(z1);
                v2 = silu_f(v2) * silu_f(z2);
                v3 = silu_f(v3) * silu_f(z3);
            }
            float2* p0 = (float2*)&Cz[(size_t)row * ldc + col];
            float2* p1 = (float2*)&Cz[(size_t)(row + 8) * ldc + col];
            *p0 = make_float2(v0, v1);
            *p1 = make_float2(v2, v3);
        }
    }
}

// reduce x_proj split-K partials; emit xdbl fp32 + padded fp16 dt-gemm input
__global__ void reduce_xdbl_kernel(const float* __restrict__ part,
                                   float* __restrict__ out,
                                   __half* __restrict__ outp)
{
    int i = blockIdx.x * 256 + threadIdx.x;
    if (i < NTOK * XDBL_W) {
        int row = i / XDBL_W, col = i % XDBL_W;
        float s = 0.0f;
#pragma unroll
        for (int z = 0; z < XPSPLIT; z++)
            s += part[(size_t)z * NTOK * XPN + (size_t)row * XPN + col];
        out[i] = s;
        if (col < DTRANK)   outp[row * DTK + col] = __float2half(s);
        else if (col < DTK) outp[row * DTK + col] = __float2half(0.0f);
    }
}

// ------ causal depthwise conv + silu: 1 block/token, float4 channels -------
#define CONV_T (DINNER / 4)   // 384 threads
__global__ void __launch_bounds__(CONV_T)
conv_silu_kernel(const float* __restrict__ xz,
                 const float* __restrict__ conv_w,
                 const float* __restrict__ conv_b,
                 float* __restrict__ xc,
                 __half* __restrict__ xch)
{
    const int row = blockIdx.x;              // global token 0..NTOK-1
    const int d   = threadIdx.x * 4;         // first channel of this thread
    const int l   = row & (SEQLEN - 1);

    const size_t base = (size_t)row * (2 * DINNER) + d;
    const float4* cw = (const float4*)conv_w;   // [DINNER] of 4-tap float4

    const float4 w0 = cw[d + 0];
    const float4 w1 = cw[d + 1];
    const float4 w2 = cw[d + 2];
    const float4 w3 = cw[d + 3];

    float4 acc = *(const float4*)&conv_b[d];

    if (l >= 3) {
        float4 x = *(const float4*)&xz[base - (size_t)3 * 2 * DINNER];
        acc.x += w0.x * x.x; acc.y += w1.x * x.y;
        acc.z += w2.x * x.z; acc.w += w3.x * x.w;
    }
    if (l >= 2) {
        float4 x = *(const float4*)&xz[base - (size_t)2 * 2 * DINNER];
        acc.x += w0.y * x.x; acc.y += w1.y * x.y;
        acc.z += w2.y * x.z; acc.w += w3.y * x.w;
    }
    if (l >= 1) {
        float4 x = *(const float4*)&xz[base - (size_t)2 * DINNER];
        acc.x += w0.z * x.x; acc.y += w1.z * x.y;
        acc.z += w2.z * x.z; acc.w += w3.z * x.w;
    }
    {
        float4 x = *(const float4*)&xz[base];
        acc.x += w0.w * x.x; acc.y += w1.w * x.y;
        acc.z += w2.w * x.z; acc.w += w3.w * x.w;
    }

    float4 v;
    v.x = silu_f(acc.x); v.y = silu_f(acc.y);
    v.z = silu_f(acc.z); v.w = silu_f(acc.w);

    const size_t o = (size_t)row * DINNER + d;
    *(float4*)&xc[o] = v;
    __half2 h01 = __floats2half2_rn(v.x, v.y);
    __half2 h23 = __floats2half2_rn(v.z, v.w);
    __half2 hp[2] = {h01, h23};
    *(uint2*)&xch[o] = *(const uint2*)hp;
}

// ============== chunked selective scan: 3 phases ===========================
// Warp layout: 8 channels x 4 lanes/channel x 4 states/lane.
// Block = 128 threads = 32 channels. Grid (NCHAN/32, NCH).

struct ScanASmem {
    float dt[2][SUB][32];
    float xc[2][SUB][32];
    float Bm[2][SUB][16];
};

__global__ void __launch_bounds__(128)
scanA_kernel(const float* __restrict__ dt, const float* __restrict__ xc,
             const float* __restrict__ xdbl, const float* __restrict__ A_log,
             float* __restrict__ gA, float* __restrict__ gB)
{
    __shared__ ScanASmem sm;
    const int tid  = threadIdx.x;
    const int cb   = tid >> 2;            // channel within block 0..31
    const int st4  = (tid & 3) * 4;       // first state of this thread
    const int c    = blockIdx.y;
    const int ch   = blockIdx.x * 32 + cb;
    const int b    = (blockIdx.x * 32) / DINNER;
    const int d0   = (blockIdx.x * 32) % DINNER;
    const int d    = d0 + cb;

    float4 Alg = *(const float4*)&A_log[d * DSTATE + st4];
    const float4 An = make_float4(-__expf(Alg.x), -__expf(Alg.y),
                                  -__expf(Alg.z), -__expf(Alg.w));
    const int row0 = b * SEQLEN + c * CH_T;

    const int rA = tid >> 2;
    const int cA = (tid & 3) * 8;
    const int cB = (tid & 3) * 4;

    auto stage = [&](int sc, int s) {
        const size_t r = (size_t)(row0 + sc * SUB + rA);
        cp16(&sm.dt[s][rA][cA],     &dt[r * DINNER + d0 + cA]);
        cp16(&sm.dt[s][rA][cA + 4], &dt[r * DINNER + d0 + cA + 4]);
        cp16(&sm.xc[s][rA][cA],     &xc[r * DINNER + d0 + cA]);
        cp16(&sm.xc[s][rA][cA + 4], &xc[r * DINNER + d0 + cA + 4]);
        cp16(&sm.Bm[s][rA][cB],     &xdbl[r * XDBL_W + DTRANK + cB]);
        cp_commit();
    };

    float4 Ap = make_float4(1.f, 1.f, 1.f, 1.f);
    float4 hB = make_float4(0.f, 0.f, 0.f, 0.f);

    stage(0, 0);
    for (int sc = 0; sc < CH_T / SUB; sc++) {
        const int s = sc & 1;
        if (sc + 1 < CH_T / SUB) {
            stage(sc + 1, s ^ 1);
            asm volatile("cp.async.wait_group 1;" ::: "memory");
        } else {
            asm volatile("cp.async.wait_group 0;" ::: "memory");
        }
        __syncthreads();

#pragma unroll 4
        for (int l = 0; l < SUB; l++) {
            const float dtv = sm.dt[s][l][cb];
            const float xv  = sm.xc[s][l][cb];
            const float4 Bv = *(const float4*)&sm.Bm[s][l][st4];
            const float u = dtv * xv;
            const float a0 = __expf(dtv * An.x);
            const float a1 = __expf(dtv * An.y);
            const float a2 = __expf(dtv * An.z);
            const float a3 = __expf(dtv * An.w);
            hB.x = fmaf(a0, hB.x, u * Bv.x);
            hB.y = fmaf(a1, hB.y, u * Bv.y);
            hB.z = fmaf(a2, hB.z, u * Bv.z);
            hB.w = fmaf(a3, hB.w, u * Bv.w);
            Ap.x *= a0; Ap.y *= a1; Ap.z *= a2; Ap.w *= a3;
        }
        __syncthreads();
    }

    const size_t o = ((size_t)c * NCHAN + ch) * DSTATE + st4;
    *(float4*)&gA[o] = Ap;
    *(float4*)&gB[o] = hB;
}

__global__ void scanB_kernel(const float* __restrict__ gA,
                             const float* __restrict__ gB,
                             float* __restrict__ hst)
{
    int idx = blockIdx.x * 256 + threadIdx.x;
    if (idx >= NCHAN * DSTATE) return;
    float h = 0.0f;
#pragma unroll
    for (int c = 0; c < NCH; c++) {
        const size_t o = (size_t)c * (NCHAN * DSTATE) + idx;
        hst[o] = h;
        h = fmaf(gA[o], h, gB[o]);
    }
}

struct ScanCSmem {
    float dt[2][SUB][32];
    float xc[2][SUB][32];
    float gt[2][SUB][32];
    float Bm[2][SUB][16];
    float Cm[2][SUB][16];
};

__global__ void __launch_bounds__(128)
scanC_kernel(const float* __restrict__ xdbl, const float* __restrict__ dt,
             const float* __restrict__ xc,   const float* __restrict__ gate,
             const float* __restrict__ A_log, const float* __restrict__ Dvec,
             const float* __restrict__ hst,  __half* __restrict__ yout)
{
    __shared__ ScanCSmem sm;
    const int tid  = threadIdx.x;
    const int cb   = tid >> 2;
    const int st4  = (tid & 3) * 4;
    const int c    = blockIdx.y;
    const int ch   = blockIdx.x * 32 + cb;
    const int b    = (blockIdx.x * 32) / DINNER;
    const int d0   = (blockIdx.x * 32) % DINNER;
    const int d    = d0 + cb;

    float4 Alg = *(const float4*)&A_log[d * DSTATE + st4];
    const float4 An = make_float4(-__expf(Alg.x), -__expf(Alg.y),
                                  -__expf(Alg.z), -__expf(Alg.w));
    const float Dd = Dvec[d];
    const int row0 = b * SEQLEN + c * CH_T;

    const int rA = tid >> 2;
    const int cA = (tid & 3) * 8;
    const int cB = (tid & 3) * 4;

    auto stage = [&](int sc, int s) {
        const size_t r = (size_t)(row0 + sc * SUB + rA);
        cp16(&sm.dt[s][rA][cA],     &dt  [r * DINNER + d0 + cA]);
        cp16(&sm.dt[s][rA][cA + 4], &dt  [r * DINNER + d0 + cA + 4]);
        cp16(&sm.xc[s][rA][cA],     &xc  [r * DINNER + d0 + cA]);
        cp16(&sm.xc[s][rA][cA + 4], &xc  [r * DINNER + d0 + cA + 4]);
        cp16(&sm.gt[s][rA][cA],     &gate[r * DINNER + d0 + cA]);
        cp16(&sm.gt[s][rA][cA + 4], &gate[r * DINNER + d0 + cA + 4]);
        cp16(&sm.Bm[s][rA][cB],     &xdbl[r * XDBL_W + DTRANK + cB]);
        cp16(&sm.Cm[s][rA][cB],     &xdbl[r * XDBL_W + DTRANK + DSTATE + cB]);
        cp_commit();
    };

    float4 h = *(const float4*)&hst[((size_t)c * NCHAN + ch) * DSTATE + st4];

    stage(0, 0);
    for (int sc = 0; sc < CH_T / SUB; sc++) {
        const int s = sc & 1;
        if (sc + 1 < CH_T / SUB) {
            stage(sc + 1, s ^ 1);
            asm volatile("cp.async.wait_group 1;" ::: "memory");
        } else {
            asm volatile("cp.async.wait_group 0;" ::: "memory");
        }
        __syncthreads();

#pragma unroll 4
        for (int l = 0; l < SUB; l++) {
            const float dtv = sm.dt[s][l][cb];
            const float xv  = sm.xc[s][l][cb];
            const float4 Bv = *(const float4*)&sm.Bm[s][l][st4];
            const float4 Cv = *(const float4*)&sm.Cm[s][l][st4];
            const float u = dtv * xv;
            h.x = fmaf(__expf(dtv * An.x), h.x, u * Bv.x);
            h.y = fmaf(__expf(dtv * An.y), h.y, u * Bv.y);
            h.z = fmaf(__expf(dtv * An.z), h.z, u * Bv.z);
            h.w = fmaf(__expf(dtv * An.w), h.w, u * Bv.w);

            float p = h.x * Cv.x + h.y * Cv.y + h.z * Cv.z + h.w * Cv.w;
            p += __shfl_xor_sync(0xffffffffu, p, 1);
            p += __shfl_xor_sync(0xffffffffu, p, 2);

            if ((tid & 3) == 0) {
                const float y = (p + xv * Dd) * sm.gt[s][l][cb];
                yout[(size_t)(row0 + sc * SUB + l) * DINNER + d] = __float2half(y);
            }
        }
        __syncthreads();
    }
}

// --------------------------------- host ------------------------------------
extern "C" void kernel_launch(void* const* d_in, const int* in_sizes, int n_in,
                              void* d_out, int out_size)
{
    const float* hs         = (const float*)d_in[0];
    const float* query      = (const float*)d_in[1];
    const float* in_proj_w  = (const float*)d_in[2];
    const float* conv_w     = (const float*)d_in[3];
    const float* conv_b     = (const float*)d_in[4];
    const float* x_proj_w   = (const float*)d_in[5];
    const float* dt_proj_w  = (const float*)d_in[6];
    const float* dt_proj_b  = (const float*)d_in[7];
    const float* A_log      = (const float*)d_in[8];
    const float* Dvec       = (const float*)d_in[9];
    const float* query_w    = (const float*)d_in[10];
    const float* query_b    = (const float*)d_in[11];
    const float* out_proj_w = (const float*)d_in[12];
    float* out = (float*)d_out;

    float  *p_xz, *p_gate, *p_xc, *p_xdbl, *p_xdp, *p_dt, *p_scA, *p_scB, *p_hst;
    __half *p_hsh, *p_quh, *p_w1h, *p_w2h, *p_w3h, *p_w4h;
    __half *p_xpwh, *p_xch, *p_xdinh, *p_yh;
    cudaGetSymbolAddress((void**)&p_xz,    g_xz);
    cudaGetSymbolAddress((void**)&p_gate,  g_gate);
    cudaGetSymbolAddress((void**)&p_xc,    g_xc);
    cudaGetSymbolAddress((void**)&p_xdbl,  g_xdbl);
    cudaGetSymbolAddress((void**)&p_xdp,   g_xdp);
    cudaGetSymbolAddress((void**)&p_dt,    g_dt);
    cudaGetSymbolAddress((void**)&p_scA,   g_scA);
    cudaGetSymbolAddress((void**)&p_scB,   g_scB);
    cudaGetSymbolAddress((void**)&p_hst,   g_hst);
    cudaGetSymbolAddress((void**)&p_hsh,   g_hsh);
    cudaGetSymbolAddress((void**)&p_quh,   g_quh);
    cudaGetSymbolAddress((void**)&p_w1h,   g_w1h);
    cudaGetSymbolAddress((void**)&p_w2h,   g_w2h);
    cudaGetSymbolAddress((void**)&p_w3h,   g_w3h);
    cudaGetSymbolAddress((void**)&p_w4h,   g_w4h);
    cudaGetSymbolAddress((void**)&p_xpwh,  g_xpwh);
    cudaGetSymbolAddress((void**)&p_xch,   g_xch);
    cudaGetSymbolAddress((void**)&p_xdinh, g_xdinh);
    cudaGetSymbolAddress((void**)&p_yh,    g_yh);

    cudaFuncSetAttribute(gemm_hf<0>, cudaFuncAttributeMaxDynamicSharedMemorySize, HSMEM);
    cudaFuncSetAttribute(gemm_hf<2>, cudaFuncAttributeMaxDynamicSharedMemorySize, HSMEM);
    cudaFuncSetAttribute(gemm_hf<3>, cudaFuncAttributeMaxDynamicSharedMemorySize, HSMEM);

    // second stream for overlapping the gate GEMM with the conv->scan chain
    cudaStream_t s2;
    cudaStreamCreateWithFlags(&s2, cudaStreamNonBlocking);
    cudaEvent_t e1, e2;
    cudaEventCreateWithFlags(&e1, cudaEventDisableTiming);
    cudaEventCreateWithFlags(&e2, cudaEventDisableTiming);

    // 1) fused prep: all 5 fp32->fp16 conversions + 2 padded conversions
    prep_kernel<<<(PREP_TOT + 255) / 256, 256>>>(
        hs, p_hsh, query, p_quh, in_proj_w, p_w1h,
        query_w, p_w2h, out_proj_w, p_w3h,
        dt_proj_w, p_w4h, x_proj_w, p_xpwh);

    // 2) xz = hs @ in_proj_w^T  (4096 x 3072, K=768)
    gemm_hf<0><<<dim3(2 * DINNER / 128, NTOK / 128), 256, HSMEM>>>(
        p_hsh, p_w1h, nullptr, nullptr, p_xz, DMODEL, DMODEL, DMODEL, 0, 2 * DINNER);

    // fork: gate GEMM on s2 (needed only by scanC)
    cudaEventRecord(e1, 0);
    cudaStreamWaitEvent(s2, e1, 0);

    // 3) gate = silu(query @ query_w^T + b) * silu(z)  (4096 x 1536)  [s2]
    gemm_hf<3><<<dim3(DINNER / 128, NTOK / 128), 256, HSMEM, s2>>>(
        p_quh, p_w2h, query_b, p_xz + DINNER, p_gate,
        DMODEL, DMODEL, DMODEL, 2 * DINNER, DINNER);
    cudaEventRecord(e2, s2);

    // 4) causal depthwise conv + silu (float4-vectorized, 1 block/token)
    conv_silu_kernel<<<NTOK, CONV_T>>>(p_xz, conv_w, conv_b, p_xc, p_xch);

    // 5) x_dbl partials = xc @ x_proj_w^T (padded N=128, split-K=4)
    gemm_hf<0><<<dim3(1, NTOK / 128, XPSPLIT), 256, HSMEM>>>(
        p_xch, p_xpwh, nullptr, nullptr, p_xdp,
        DINNER / XPSPLIT, DINNER, DINNER, 0, XPN);

    // 6) reduce partials -> xdbl fp32 + padded fp16 dt input
    reduce_xdbl_kernel<<<(NTOK * XDBL_W + 255) / 256, 256>>>(p_xdp, p_xdbl, p_xdinh);

    // 7) dt = softplus(xdin @ w4^T + dt_proj_b)  (K=64 padded)
    gemm_hf<2><<<dim3(DINNER / 128, NTOK / 128), 256, HSMEM>>>(
        p_xdinh, p_w4h, dt_proj_b, nullptr, p_dt, DTK, DTK, DTK, 0, DINNER);

    // 8-9) chunked selective scan phases A, B
    scanA_kernel<<<dim3(NCHAN / 32, NCH), 128>>>(
        p_dt, p_xc, p_xdbl, A_log, p_scA, p_scB);
    scanB_kernel<<<(NCHAN * DSTATE + 255) / 256, 256>>>(p_scA, p_scB, p_hst);

    // join: scanC needs the gate
    cudaStreamWaitEvent(0, e2, 0);

    // 10) scan phase C (gated output)
    scanC_kernel<<<dim3(NCHAN / 32, NCH), 128>>>(
        p_xdbl, p_dt, p_xc, p_gate, A_log, Dvec, p_hst, p_yh);

    // 11) out = y @ out_proj_w^T  (4096 x 768, K=1536)
    gemm_hf<0><<<dim3(DMODEL / 128, NTOK / 128), 256, HSMEM>>>(
        p_yh, p_w3h, nullptr, nullptr, out, DINNER, DINNER, DINNER, 0, DMODEL);
}